// round 6
// baseline (speedup 1.0000x reference)
#include <cuda_runtime.h>

#define TD 2048
#define CD 512
#define DD 64
#define BH 32
#define RWS 8192
#define NRW 65536

typedef unsigned long long u64;
typedef unsigned int u32;

// ---------------- scratch ----------------
__device__ float g_W[CD * CD];
__device__ float g_w[RWS * CD];
__device__ float g_q[RWS * CD];   // tf32-rounded, scaled by inv*0.125*log2e
__device__ float g_k[RWS * CD];   // tf32-rounded
__device__ float g_v[RWS * CD];   // tf32-rounded
__device__ float g_att[(size_t)BH * TD * TD];   // exp(att), tf32-rounded fp32
__device__ float g_pv[(size_t)BH * TD * DD];    // tf32(pc_k * v), [bh*TD+k][64]
__device__ float g_srow[BH * TD];
__device__ float g_scol[BH * TD];
__device__ float g_prow[BH * TD];
__device__ float g_pcol[BH * TD];
__device__ float g_y[RWS * CD];

// ---------------- helpers ----------------
__device__ __forceinline__ void fma2(u64& d, u64 a, u64 b) {
    asm("fma.rn.f32x2 %0, %1, %2, %0;" : "+l"(d) : "l"(a), "l"(b));
}
__device__ __forceinline__ float2 unpk(u64 v) {
    float2 f; asm("mov.b64 {%0, %1}, %2;" : "=f"(f.x), "=f"(f.y) : "l"(v)); return f;
}
__device__ __forceinline__ u32 tf32c(float f) {
    u32 r; asm("cvt.rna.tf32.f32 %0, %1;" : "=r"(r) : "f"(f)); return r;
}
__device__ __forceinline__ float tf32f(float f) { return __uint_as_float(tf32c(f)); }
__device__ __forceinline__ float ex2(float x) {
    float y; asm("ex2.approx.f32 %0, %1;" : "=f"(y) : "f"(x)); return y;
}
__device__ __forceinline__ void mma8(float* d, const u32* a, const u32* b) {
    asm("mma.sync.aligned.m16n8k8.row.col.f32.tf32.tf32.f32 "
        "{%0,%1,%2,%3},{%4,%5,%6,%7},{%8,%9},{%0,%1,%2,%3};"
        : "+f"(d[0]), "+f"(d[1]), "+f"(d[2]), "+f"(d[3])
        : "r"(a[0]), "r"(a[1]), "r"(a[2]), "r"(a[3]), "r"(b[0]), "r"(b[1]));
}

// ---------------------------------------------------------------- W = dw + qw
__global__ void k_addw(const float* __restrict__ dw, const float* __restrict__ qw) {
    int i = blockIdx.x * 256 + threadIdx.x;
    g_W[i] = dw[i] + qw[i];
}

// ================================================================ g_w = x @ W^T (FFMA2, exact)
__global__ __launch_bounds__(256, 2) void k_wgemm(const float* __restrict__ x) {
    __shared__ __align__(16) float sm[16 * 264 + 16 * 132];
    const int BO = 16 * 264;
    const int tid = threadIdx.x;
    const int tx = tid & 15, ty = tid >> 4;
    const int i0 = blockIdx.y * 128, j0 = blockIdx.x * 128;
    const float* Ab = x + (size_t)i0 * CD;
    const float* Bb = g_W + (size_t)j0 * CD;
    u64 acc[8][4] = {};
    #pragma unroll 1
    for (int s = 0; s < 32; s++) {
        int k0 = s * 16;
        #pragma unroll
        for (int l = 0; l < 2; l++) {
            int idx = tid + l * 256;
            int rr = idx >> 2, c4 = (idx & 3) * 4;
            float4 va = *(const float4*)(Ab + (size_t)rr * CD + k0 + c4);
            sm[(c4 + 0) * 264 + 2 * rr] = va.x; sm[(c4 + 0) * 264 + 2 * rr + 1] = va.x;
            sm[(c4 + 1) * 264 + 2 * rr] = va.y; sm[(c4 + 1) * 264 + 2 * rr + 1] = va.y;
            sm[(c4 + 2) * 264 + 2 * rr] = va.z; sm[(c4 + 2) * 264 + 2 * rr + 1] = va.z;
            sm[(c4 + 3) * 264 + 2 * rr] = va.w; sm[(c4 + 3) * 264 + 2 * rr + 1] = va.w;
            float4 vb = *(const float4*)(Bb + (size_t)rr * CD + k0 + c4);
            sm[BO + (c4 + 0) * 132 + rr] = vb.x;
            sm[BO + (c4 + 1) * 132 + rr] = vb.y;
            sm[BO + (c4 + 2) * 132 + rr] = vb.z;
            sm[BO + (c4 + 3) * 132 + rr] = vb.w;
        }
        __syncthreads();
        #pragma unroll
        for (int kk = 0; kk < 16; kk++) {
            u64 a[8], b[4]; ulonglong2 t;
            t = *(const ulonglong2*)&sm[kk * 264 + ty * 8];       a[0] = t.x; a[1] = t.y;
            t = *(const ulonglong2*)&sm[kk * 264 + ty * 8 + 4];   a[2] = t.x; a[3] = t.y;
            t = *(const ulonglong2*)&sm[kk * 264 + 128 + ty * 8]; a[4] = t.x; a[5] = t.y;
            t = *(const ulonglong2*)&sm[kk * 264 + 132 + ty * 8]; a[6] = t.x; a[7] = t.y;
            t = *(const ulonglong2*)&sm[BO + kk * 132 + tx * 4];      b[0] = t.x; b[1] = t.y;
            t = *(const ulonglong2*)&sm[BO + kk * 132 + 64 + tx * 4]; b[2] = t.x; b[3] = t.y;
            #pragma unroll
            for (int i = 0; i < 8; i++)
                #pragma unroll
                for (int j = 0; j < 4; j++)
                    fma2(acc[i][j], a[i], b[j]);
        }
        __syncthreads();
    }
    float* Cb = g_w + (size_t)i0 * CD + j0;
    #pragma unroll
    for (int i = 0; i < 8; i++) {
        int row = (i < 4) ? ty * 4 + i : 64 + ty * 4 + (i - 4);
        float2 p0 = unpk(acc[i][0]), p1 = unpk(acc[i][1]), p2 = unpk(acc[i][2]), p3 = unpk(acc[i][3]);
        *(float4*)(Cb + (size_t)row * CD + tx * 4)      = make_float4(p0.x, p0.y, p1.x, p1.y);
        *(float4*)(Cb + (size_t)row * CD + 64 + tx * 4) = make_float4(p2.x, p2.y, p3.x, p3.y);
    }
}

// ------------------------------------------- rmsnorm -> q (scaled, tf32), k (tf32), v (tf32)
__global__ void k_norm(const float* __restrict__ g1, const float* __restrict__ g2,
                       const float* __restrict__ g3) {
    int warp = (blockIdx.x * blockDim.x + threadIdx.x) >> 5;
    int lane = threadIdx.x & 31;
    size_t off = (size_t)(warp >> 3) * CD + (warp & 7) * DD;
    float x0 = g_w[off + lane], x1 = g_w[off + lane + 32];
    float ss = x0 * x0 + x1 * x1;
    #pragma unroll
    for (int s = 16; s; s >>= 1) ss += __shfl_xor_sync(0xffffffffu, ss, s);
    float inv = rsqrtf(ss * (1.0f / 64.0f) + 1.1920929e-07f);
    float qs = inv * 0.125f * 1.44269504f;   // fold 1/sqrt(D) and log2(e)
    g_q[off + lane]      = tf32f(x0 * qs  * g1[lane]);
    g_q[off + lane + 32] = tf32f(x1 * qs  * g1[lane + 32]);
    g_k[off + lane]      = tf32f(x0 * inv * g2[lane]);
    g_k[off + lane + 32] = tf32f(x1 * inv * g2[lane + 32]);
    g_v[off + lane]      = tf32f(x0 * inv * g3[lane]);
    g_v[off + lane + 32] = tf32f(x1 * inv * g3[lane + 32]);
}

// ================================================================ E = 2^(q@k^T), store + fused sums
// 128x64 tile, 8 warps (4m x 2n), 32 accs/thread, occ 2.
__global__ __launch_bounds__(256, 2) void k_att() {
    __shared__ __align__(16) float sq[128 * 40];
    __shared__ __align__(16) float sk[64 * 40];
    const int tid = threadIdx.x;
    const int lane = tid & 31, warp = tid >> 5;
    const int wm = warp >> 1, wn = warp & 1;
    const int g = lane >> 2, t = lane & 3;
    const int bh = blockIdx.z;
    const int i0 = blockIdx.y * 128, j0 = blockIdx.x * 64;
    const size_t base = (size_t)(bh >> 3) * TD * CD + (bh & 7) * DD;
    const float* qb = g_q + base + (size_t)i0 * CD;
    const float* kb = g_k + base + (size_t)j0 * CD;
    float d[2][4][4] = {};
    #pragma unroll
    for (int stage = 0; stage < 2; stage++) {
        int k0 = stage * 32;
        #pragma unroll
        for (int l = 0; l < 4; l++) {
            int idx = tid + l * 256;
            int rr = idx >> 3, c4 = (idx & 7) * 4;
            int pbase = (c4 & 24) + ((c4 & 4) ? 1 : 0);
            float4 v = *(const float4*)(qb + (size_t)rr * CD + k0 + c4);
            sq[rr * 40 + pbase] = v.x; sq[rr * 40 + pbase + 2] = v.y;
            sq[rr * 40 + pbase + 4] = v.z; sq[rr * 40 + pbase + 6] = v.w;
        }
        #pragma unroll
        for (int l = 0; l < 2; l++) {
            int idx = tid + l * 256;
            int rr = idx >> 3, c4 = (idx & 7) * 4;
            int pbase = (c4 & 24) + ((c4 & 4) ? 1 : 0);
            float4 w = *(const float4*)(kb + (size_t)rr * CD + k0 + c4);
            sk[rr * 40 + pbase] = w.x; sk[rr * 40 + pbase + 2] = w.y;
            sk[rr * 40 + pbase + 4] = w.z; sk[rr * 40 + pbase + 6] = w.w;
        }
        __syncthreads();
        #pragma unroll
        for (int ks = 0; ks < 4; ks++) {
            u32 a[2][4], b[4][2];
            #pragma unroll
            for (int mt = 0; mt < 2; mt++) {
                float2 lo = *(const float2*)&sq[(wm * 32 + mt * 16 + g) * 40 + ks * 8 + 2 * t];
                float2 hi = *(const float2*)&sq[(wm * 32 + mt * 16 + g + 8) * 40 + ks * 8 + 2 * t];
                a[mt][0] = __float_as_uint(lo.x); a[mt][2] = __float_as_uint(lo.y);
                a[mt][1] = __float_as_uint(hi.x); a[mt][3] = __float_as_uint(hi.y);
            }
            #pragma unroll
            for (int nt = 0; nt < 4; nt++) {
                float2 bb = *(const float2*)&sk[(wn * 32 + nt * 8 + g) * 40 + ks * 8 + 2 * t];
                b[nt][0] = __float_as_uint(bb.x); b[nt][1] = __float_as_uint(bb.y);
            }
            #pragma unroll
            for (int mt = 0; mt < 2; mt++)
                #pragma unroll
                for (int nt = 0; nt < 4; nt++)
                    mma8(d[mt][nt], a[mt], b[nt]);
        }
        __syncthreads();
    }
    // epilogue: exp2, tf32-round, store, fused sums of the SAME rounded values
    float* ob = g_att + (size_t)bh * TD * TD + (size_t)i0 * TD + j0;
    float rsum[2][2] = {};
    float cs0[4] = {}, cs1[4] = {};
    #pragma unroll
    for (int mt = 0; mt < 2; mt++) {
        int r0 = wm * 32 + mt * 16 + g;
        #pragma unroll
        for (int nt = 0; nt < 4; nt++) {
            int col = wn * 32 + nt * 8 + 2 * t;
            float e0 = tf32f(ex2(d[mt][nt][0])), e1 = tf32f(ex2(d[mt][nt][1]));
            float e2 = tf32f(ex2(d[mt][nt][2])), e3 = tf32f(ex2(d[mt][nt][3]));
            *(float2*)(ob + (size_t)r0 * TD + col)       = make_float2(e0, e1);
            *(float2*)(ob + (size_t)(r0 + 8) * TD + col) = make_float2(e2, e3);
            rsum[mt][0] += e0 + e1; rsum[mt][1] += e2 + e3;
            cs0[nt] += e0 + e2;     cs1[nt] += e1 + e3;
        }
    }
    #pragma unroll
    for (int mt = 0; mt < 2; mt++)
        #pragma unroll
        for (int h = 0; h < 2; h++) {
            rsum[mt][h] += __shfl_xor_sync(0xffffffffu, rsum[mt][h], 1);
            rsum[mt][h] += __shfl_xor_sync(0xffffffffu, rsum[mt][h], 2);
        }
    #pragma unroll
    for (int nt = 0; nt < 4; nt++) {
        cs0[nt] += __shfl_xor_sync(0xffffffffu, cs0[nt], 4);
        cs0[nt] += __shfl_xor_sync(0xffffffffu, cs0[nt], 8);
        cs0[nt] += __shfl_xor_sync(0xffffffffu, cs0[nt], 16);
        cs1[nt] += __shfl_xor_sync(0xffffffffu, cs1[nt], 4);
        cs1[nt] += __shfl_xor_sync(0xffffffffu, cs1[nt], 8);
        cs1[nt] += __shfl_xor_sync(0xffffffffu, cs1[nt], 16);
    }
    __syncthreads();                    // all MMA reads of sq/sk done before reuse
    float* srowp = sq;                  // [2][128]  (partial over wn)
    float* scolp = sk;                  // [4][64]   (partial over wm)
    if (t == 0) {
        #pragma unroll
        for (int mt = 0; mt < 2; mt++) {
            srowp[wn * 128 + wm * 32 + mt * 16 + g]     = rsum[mt][0];
            srowp[wn * 128 + wm * 32 + mt * 16 + g + 8] = rsum[mt][1];
        }
    }
    if (g == 0) {
        #pragma unroll
        for (int nt = 0; nt < 4; nt++) {
            scolp[wm * 64 + wn * 32 + nt * 8 + 2 * t]     = cs0[nt];
            scolp[wm * 64 + wn * 32 + nt * 8 + 2 * t + 1] = cs1[nt];
        }
    }
    __syncthreads();
    if (tid < 128) {
        atomicAdd(&g_srow[bh * TD + i0 + tid], srowp[tid] + srowp[128 + tid]);
    } else if (tid < 192) {
        int c = tid - 128;
        atomicAdd(&g_scol[bh * TD + j0 + c],
                  scolp[c] + scolp[64 + c] + scolp[128 + c] + scolp[192 + c]);
    }
}

// ------------------------------------------- reciprocals of sums
__global__ void k_recip() {
    int i = blockIdx.x * 256 + threadIdx.x;
    g_prow[i] = 1.0f / g_srow[i];
    g_pcol[i] = 1.0f / g_scol[i];
}

// ------------------------------------------- pv = tf32(pc_k * v_k), [bh*TD+k][64]
__global__ void k_pv() {
    int n = blockIdx.x * 256 + threadIdx.x;   // float4 units over BH*TD*16
    int kg = n >> 4;                          // bh*TD + k
    int d4 = (n & 15) * 4;
    int bh = kg >> 11, k = kg & 2047;
    size_t base = (size_t)(bh >> 3) * TD * CD + (bh & 7) * DD;
    float4 v = *(const float4*)(g_v + base + (size_t)k * CD + d4);
    float pc = g_pcol[kg];
    *(float4*)(g_pv + (size_t)kg * 64 + d4) =
        make_float4(tf32f(v.x * pc), tf32f(v.y * pc), tf32f(v.z * pc), tf32f(v.w * pc));
}

// ================================================================ y = pr ⊙ (E@v) + E@(pc⊙v)
// 128x64 tile, 8 warps (4m x 2n). A-fragments (E, already tf32 bit patterns) come straight
// from gmem as float2 at cols (2t, 2t+1); B fragments use the MATCHING k-relabeling:
// rows (2t, 2t+1) of v/pv. Smem stride 68 keeps those rows conflict-free.
__global__ __launch_bounds__(256, 2) void k_y() {
    __shared__ __align__(16) float sv[64 * 68];
    __shared__ __align__(16) float sp[64 * 68];
    const int tid = threadIdx.x;
    const int lane = tid & 31, warp = tid >> 5;
    const int wm = warp >> 1, wn = warp & 1;
    const int g = lane >> 2, t = lane & 3;
    const int bh = blockIdx.y;
    const int i0 = blockIdx.x * 128;
    const size_t base = (size_t)(bh >> 3) * TD * CD + (bh & 7) * DD;
    const float* eb = g_att + (size_t)bh * TD * TD;
    const float* vb = g_v + base;
    const float* pvb = g_pv + (size_t)bh * TD * 64;
    float prv[2][2];
    #pragma unroll
    for (int mt = 0; mt < 2; mt++) {
        prv[mt][0] = g_prow[bh * TD + i0 + wm * 32 + mt * 16 + g];
        prv[mt][1] = g_prow[bh * TD + i0 + wm * 32 + mt * 16 + g + 8];
    }
    const float* erow[2][2];
    #pragma unroll
    for (int mt = 0; mt < 2; mt++) {
        erow[mt][0] = eb + (size_t)(i0 + wm * 32 + mt * 16 + g) * TD + 2 * t;
        erow[mt][1] = erow[mt][0] + 8 * TD;
    }
    float d1[2][4][4] = {}, d2[2][4][4] = {};
    #pragma unroll 1
    for (int kc = 0; kc < 32; kc++) {
        int k0 = kc * 64;
        __syncthreads();
        #pragma unroll
        for (int l = 0; l < 4; l++) {
            int idx = tid + l * 256;
            int rr = idx >> 4, c4 = (idx & 15) * 4;
            *(float4*)&sv[rr * 68 + c4] = *(const float4*)(vb + (size_t)(k0 + rr) * CD + c4);
            *(float4*)&sp[rr * 68 + c4] = *(const float4*)(pvb + (size_t)(k0 + rr) * 64 + c4);
        }
        __syncthreads();
        #pragma unroll
        for (int ks = 0; ks < 8; ks++) {
            u32 a[2][4], bv[4][2], bp[4][2];
            #pragma unroll
            for (int mt = 0; mt < 2; mt++) {
                float2 lo = *(const float2*)(erow[mt][0] + k0 + ks * 8);
                float2 hi = *(const float2*)(erow[mt][1] + k0 + ks * 8);
                a[mt][0] = __float_as_uint(lo.x); a[mt][2] = __float_as_uint(lo.y);
                a[mt][1] = __float_as_uint(hi.x); a[mt][3] = __float_as_uint(hi.y);
            }
            #pragma unroll
            for (int nt = 0; nt < 4; nt++) {
                int n = wn * 32 + nt * 8 + g;
                bv[nt][0] = __float_as_uint(sv[(ks * 8 + 2 * t) * 68 + n]);
                bv[nt][1] = __float_as_uint(sv[(ks * 8 + 2 * t + 1) * 68 + n]);
                bp[nt][0] = __float_as_uint(sp[(ks * 8 + 2 * t) * 68 + n]);
                bp[nt][1] = __float_as_uint(sp[(ks * 8 + 2 * t + 1) * 68 + n]);
            }
            #pragma unroll
            for (int mt = 0; mt < 2; mt++)
                #pragma unroll
                for (int nt = 0; nt < 4; nt++) {
                    mma8(d1[mt][nt], a[mt], bv[nt]);
                    mma8(d2[mt][nt], a[mt], bp[nt]);
                }
        }
    }
    float* yb = g_y + base + (size_t)i0 * CD;
    #pragma unroll
    for (int mt = 0; mt < 2; mt++) {
        int r0 = wm * 32 + mt * 16 + g;
        #pragma unroll
        for (int nt = 0; nt < 4; nt++) {
            int col = wn * 32 + nt * 8 + 2 * t;
            *(float2*)(yb + (size_t)r0 * CD + col) =
                make_float2(prv[mt][0] * d1[mt][nt][0] + d2[mt][nt][0],
                            prv[mt][0] * d1[mt][nt][1] + d2[mt][nt][1]);
            *(float2*)(yb + (size_t)(r0 + 8) * CD + col) =
                make_float2(prv[mt][1] * d1[mt][nt][2] + d2[mt][nt][2],
                            prv[mt][1] * d1[mt][nt][3] + d2[mt][nt][3]);
        }
    }
}

// ================================================================ out = y @ W (NN, FFMA2, exact)
__global__ __launch_bounds__(256, 2) void k_outgemm(float* __restrict__ out) {
    __shared__ __align__(16) float sm[16 * 264 + 16 * 132];
    const int BO = 16 * 264;
    const int tid = threadIdx.x;
    const int tx = tid & 15, ty = tid >> 4;
    const int i0 = blockIdx.y * 128, j0 = blockIdx.x * 128;
    const float* Ab = g_y + (size_t)i0 * CD;
    u64 acc[8][4] = {};
    #pragma unroll 1
    for (int s = 0; s < 32; s++) {
        int k0 = s * 16;
        #pragma unroll
        for (int l = 0; l < 2; l++) {
            int idx = tid + l * 256;
            int rr = idx >> 2, c4 = (idx & 3) * 4;
            float4 va = *(const float4*)(Ab + (size_t)rr * CD + k0 + c4);
            sm[(c4 + 0) * 264 + 2 * rr] = va.x; sm[(c4 + 0) * 264 + 2 * rr + 1] = va.x;
            sm[(c4 + 1) * 264 + 2 * rr] = va.y; sm[(c4 + 1) * 264 + 2 * rr + 1] = va.y;
            sm[(c4 + 2) * 264 + 2 * rr] = va.z; sm[(c4 + 2) * 264 + 2 * rr + 1] = va.z;
            sm[(c4 + 3) * 264 + 2 * rr] = va.w; sm[(c4 + 3) * 264 + 2 * rr + 1] = va.w;
            int kk = idx >> 5, j4 = (idx & 31) * 4;
            *(float4*)&sm[BO + kk * 132 + j4] =
                *(const float4*)(g_W + (size_t)(k0 + kk) * CD + j0 + j4);
        }
        __syncthreads();
        #pragma unroll
        for (int kk = 0; kk < 16; kk++) {
            u64 a[8], b[4]; ulonglong2 t;
            t = *(const ulonglong2*)&sm[kk * 264 + ty * 8];       a[0] = t.x; a[1] = t.y;
            t = *(const ulonglong2*)&sm[kk * 264 + ty * 8 + 4];   a[2] = t.x; a[3] = t.y;
            t = *(const ulonglong2*)&sm[kk * 264 + 128 + ty * 8]; a[4] = t.x; a[5] = t.y;
            t = *(const ulonglong2*)&sm[kk * 264 + 132 + ty * 8]; a[6] = t.x; a[7] = t.y;
            t = *(const ulonglong2*)&sm[BO + kk * 132 + tx * 4];      b[0] = t.x; b[1] = t.y;
            t = *(const ulonglong2*)&sm[BO + kk * 132 + 64 + tx * 4]; b[2] = t.x; b[3] = t.y;
            #pragma unroll
            for (int i = 0; i < 8; i++)
                #pragma unroll
                for (int j = 0; j < 4; j++)
                    fma2(acc[i][j], a[i], b[j]);
        }
        __syncthreads();
    }
    float* Cb = out + (size_t)i0 * CD + j0;
    #pragma unroll
    for (int i = 0; i < 8; i++) {
        int row = (i < 4) ? ty * 4 + i : 64 + ty * 4 + (i - 4);
        float2 p0 = unpk(acc[i][0]), p1 = unpk(acc[i][1]), p2 = unpk(acc[i][2]), p3 = unpk(acc[i][3]);
        *(float4*)(Cb + (size_t)row * CD + tx * 4)      = make_float4(p0.x, p0.y, p1.x, p1.y);
        *(float4*)(Cb + (size_t)row * CD + 64 + tx * 4) = make_float4(p2.x, p2.y, p3.x, p3.y);
    }
}

extern "C" void kernel_launch(void* const* d_in, const int* in_sizes, int n_in,
                              void* d_out, int out_size) {
    (void)in_sizes; (void)n_in; (void)out_size;
    const float* x  = (const float*)d_in[0];
    const float* dw = (const float*)d_in[1];
    const float* qw = (const float*)d_in[2];
    const float* g1 = (const float*)d_in[3];
    const float* g2 = (const float*)d_in[4];
    const float* g3 = (const float*)d_in[5];
    float* out = (float*)d_out;

    float *ps, *pc;
    cudaGetSymbolAddress((void**)&ps, g_srow);
    cudaGetSymbolAddress((void**)&pc, g_scol);
    cudaMemsetAsync(ps, 0, BH * TD * sizeof(float));
    cudaMemsetAsync(pc, 0, BH * TD * sizeof(float));

    k_addw<<<(CD * CD) / 256, 256>>>(dw, qw);
    k_wgemm<<<dim3(CD / 128, RWS / 128), 256>>>(x);
    k_norm<<<NRW / 8, 256>>>(g1, g2, g3);
    k_att<<<dim3(TD / 64, TD / 128, BH), 256>>>();
    k_recip<<<(BH * TD) / 256, 256>>>();
    k_pv<<<(BH * TD * 16) / 256, 256>>>();
    k_y<<<dim3(TD / 128, BH), 256>>>();
    k_outgemm<<<dim3(CD / 128, RWS / 128), 256>>>(out);
}

// round 7
// speedup vs baseline: 1.2780x; 1.2780x over previous
#include <cuda_runtime.h>

#define TD 2048
#define CD 512
#define DD 64
#define BH 32
#define RWS 8192
#define NRW 65536

typedef unsigned long long u64;
typedef unsigned int u32;

// ---------------- scratch ----------------
__device__ float g_W[CD * CD];
__device__ float g_w[RWS * CD];
__device__ float g_q[RWS * CD];   // tf32-rounded, scaled by inv*0.125*log2e
__device__ float g_k[RWS * CD];   // tf32-rounded
__device__ float g_v[RWS * CD];   // tf32-rounded
__device__ float g_att[(size_t)BH * TD * TD];   // exp(att)
__device__ float g_srow[BH * TD];
__device__ float g_scol[BH * TD];
__device__ float g_prow[BH * TD];
__device__ float g_pcol[BH * TD];
__device__ float g_y[RWS * CD];

// ---------------- helpers ----------------
__device__ __forceinline__ u32 tf32c(float f) {
    u32 r; asm("cvt.rna.tf32.f32 %0, %1;" : "=r"(r) : "f"(f)); return r;
}
__device__ __forceinline__ float tf32f(float f) { return __uint_as_float(tf32c(f)); }
__device__ __forceinline__ float ex2(float x) {
    float y; asm("ex2.approx.f32 %0, %1;" : "=f"(y) : "f"(x)); return y;
}
__device__ __forceinline__ void mma8(float* d, const u32* a, const u32* b) {
    asm("mma.sync.aligned.m16n8k8.row.col.f32.tf32.tf32.f32 "
        "{%0,%1,%2,%3},{%4,%5,%6,%7},{%8,%9},{%0,%1,%2,%3};"
        : "+f"(d[0]), "+f"(d[1]), "+f"(d[2]), "+f"(d[3])
        : "r"(a[0]), "r"(a[1]), "r"(a[2]), "r"(a[3]), "r"(b[0]), "r"(b[1]));
}

// ---------------------------------------------------------------- W = dw + qw
__global__ void k_addw(const float* __restrict__ dw, const float* __restrict__ qw) {
    int i = blockIdx.x * 256 + threadIdx.x;
    g_W[i] = dw[i] + qw[i];
}

// ================================================================ g_w = x @ W^T  (tf32 MMA)
// 128x64 tile, 8 warps (4m x 2n), K-chunks of 32.
__global__ __launch_bounds__(256, 2) void k_wgemm32(const float* __restrict__ x) {
    __shared__ __align__(16) float sA[128 * 40];
    __shared__ __align__(16) float sB[64 * 40];
    const int tid = threadIdx.x;
    const int lane = tid & 31, warp = tid >> 5;
    const int wm = warp >> 1, wn = warp & 1;
    const int g = lane >> 2, t = lane & 3;
    const int i0 = blockIdx.y * 128, j0 = blockIdx.x * 64;
    const float* Ab = x + (size_t)i0 * CD;
    const float* Bb = g_W + (size_t)j0 * CD;
    float d[2][4][4] = {};
    #pragma unroll 1
    for (int kc = 0; kc < 16; kc++) {
        int k0 = kc * 32;
        #pragma unroll
        for (int l = 0; l < 4; l++) {
            int idx = tid + l * 256;
            int rr = idx >> 3, c4 = (idx & 7) * 4;
            int pbase = (c4 & 24) + ((c4 & 4) ? 1 : 0);
            float4 v = *(const float4*)(Ab + (size_t)rr * CD + k0 + c4);
            sA[rr * 40 + pbase] = tf32f(v.x); sA[rr * 40 + pbase + 2] = tf32f(v.y);
            sA[rr * 40 + pbase + 4] = tf32f(v.z); sA[rr * 40 + pbase + 6] = tf32f(v.w);
        }
        #pragma unroll
        for (int l = 0; l < 2; l++) {
            int idx = tid + l * 256;
            int rr = idx >> 3, c4 = (idx & 7) * 4;
            int pbase = (c4 & 24) + ((c4 & 4) ? 1 : 0);
            float4 w = *(const float4*)(Bb + (size_t)rr * CD + k0 + c4);
            sB[rr * 40 + pbase] = tf32f(w.x); sB[rr * 40 + pbase + 2] = tf32f(w.y);
            sB[rr * 40 + pbase + 4] = tf32f(w.z); sB[rr * 40 + pbase + 6] = tf32f(w.w);
        }
        __syncthreads();
        #pragma unroll
        for (int ks = 0; ks < 4; ks++) {
            u32 a[2][4], b[4][2];
            #pragma unroll
            for (int mt = 0; mt < 2; mt++) {
                float2 lo = *(const float2*)&sA[(wm * 32 + mt * 16 + g) * 40 + ks * 8 + 2 * t];
                float2 hi = *(const float2*)&sA[(wm * 32 + mt * 16 + g + 8) * 40 + ks * 8 + 2 * t];
                a[mt][0] = __float_as_uint(lo.x); a[mt][2] = __float_as_uint(lo.y);
                a[mt][1] = __float_as_uint(hi.x); a[mt][3] = __float_as_uint(hi.y);
            }
            #pragma unroll
            for (int nt = 0; nt < 4; nt++) {
                float2 bb = *(const float2*)&sB[(wn * 32 + nt * 8 + g) * 40 + ks * 8 + 2 * t];
                b[nt][0] = __float_as_uint(bb.x); b[nt][1] = __float_as_uint(bb.y);
            }
            #pragma unroll
            for (int mt = 0; mt < 2; mt++)
                #pragma unroll
                for (int nt = 0; nt < 4; nt++)
                    mma8(d[mt][nt], a[mt], b[nt]);
        }
        __syncthreads();
    }
    float* Cb = g_w + (size_t)i0 * CD + j0;
    #pragma unroll
    for (int mt = 0; mt < 2; mt++) {
        int r0 = wm * 32 + mt * 16 + g;
        #pragma unroll
        for (int nt = 0; nt < 4; nt++) {
            int col = wn * 32 + nt * 8 + 2 * t;
            *(float2*)(Cb + (size_t)r0 * CD + col)       = make_float2(d[mt][nt][0], d[mt][nt][1]);
            *(float2*)(Cb + (size_t)(r0 + 8) * CD + col) = make_float2(d[mt][nt][2], d[mt][nt][3]);
        }
    }
}

// ------------------------------------------- rmsnorm -> q (scaled, tf32), k (tf32), v (tf32)
__global__ void k_norm(const float* __restrict__ g1, const float* __restrict__ g2,
                       const float* __restrict__ g3) {
    int warp = (blockIdx.x * blockDim.x + threadIdx.x) >> 5;
    int lane = threadIdx.x & 31;
    size_t off = (size_t)(warp >> 3) * CD + (warp & 7) * DD;
    float x0 = g_w[off + lane], x1 = g_w[off + lane + 32];
    float ss = x0 * x0 + x1 * x1;
    #pragma unroll
    for (int s = 16; s; s >>= 1) ss += __shfl_xor_sync(0xffffffffu, ss, s);
    float inv = rsqrtf(ss * (1.0f / 64.0f) + 1.1920929e-07f);
    float qs = inv * 0.125f * 1.44269504f;   // fold 1/sqrt(D) and log2(e)
    g_q[off + lane]      = tf32f(x0 * qs  * g1[lane]);
    g_q[off + lane + 32] = tf32f(x1 * qs  * g1[lane + 32]);
    g_k[off + lane]      = tf32f(x0 * inv * g2[lane]);
    g_k[off + lane + 32] = tf32f(x1 * inv * g2[lane + 32]);
    g_v[off + lane]      = tf32f(x0 * inv * g3[lane]);
    g_v[off + lane + 32] = tf32f(x1 * inv * g3[lane + 32]);
}

// ================================================================ E = 2^(q@k^T), store + fused sums
// 128x64 tile, 8 warps (4m x 2n), occ 2.  (proven R6 kernel; raw-exp store)
__global__ __launch_bounds__(256, 2) void k_att() {
    __shared__ __align__(16) float sq[128 * 40];
    __shared__ __align__(16) float sk[64 * 40];
    const int tid = threadIdx.x;
    const int lane = tid & 31, warp = tid >> 5;
    const int wm = warp >> 1, wn = warp & 1;
    const int g = lane >> 2, t = lane & 3;
    const int bh = blockIdx.z;
    const int i0 = blockIdx.y * 128, j0 = blockIdx.x * 64;
    const size_t base = (size_t)(bh >> 3) * TD * CD + (bh & 7) * DD;
    const float* qb = g_q + base + (size_t)i0 * CD;
    const float* kb = g_k + base + (size_t)j0 * CD;
    float d[2][4][4] = {};
    #pragma unroll
    for (int stage = 0; stage < 2; stage++) {
        int k0 = stage * 32;
        #pragma unroll
        for (int l = 0; l < 4; l++) {
            int idx = tid + l * 256;
            int rr = idx >> 3, c4 = (idx & 7) * 4;
            int pbase = (c4 & 24) + ((c4 & 4) ? 1 : 0);
            float4 v = *(const float4*)(qb + (size_t)rr * CD + k0 + c4);
            sq[rr * 40 + pbase] = v.x; sq[rr * 40 + pbase + 2] = v.y;
            sq[rr * 40 + pbase + 4] = v.z; sq[rr * 40 + pbase + 6] = v.w;
        }
        #pragma unroll
        for (int l = 0; l < 2; l++) {
            int idx = tid + l * 256;
            int rr = idx >> 3, c4 = (idx & 7) * 4;
            int pbase = (c4 & 24) + ((c4 & 4) ? 1 : 0);
            float4 w = *(const float4*)(kb + (size_t)rr * CD + k0 + c4);
            sk[rr * 40 + pbase] = w.x; sk[rr * 40 + pbase + 2] = w.y;
            sk[rr * 40 + pbase + 4] = w.z; sk[rr * 40 + pbase + 6] = w.w;
        }
        __syncthreads();
        #pragma unroll
        for (int ks = 0; ks < 4; ks++) {
            u32 a[2][4], b[4][2];
            #pragma unroll
            for (int mt = 0; mt < 2; mt++) {
                float2 lo = *(const float2*)&sq[(wm * 32 + mt * 16 + g) * 40 + ks * 8 + 2 * t];
                float2 hi = *(const float2*)&sq[(wm * 32 + mt * 16 + g + 8) * 40 + ks * 8 + 2 * t];
                a[mt][0] = __float_as_uint(lo.x); a[mt][2] = __float_as_uint(lo.y);
                a[mt][1] = __float_as_uint(hi.x); a[mt][3] = __float_as_uint(hi.y);
            }
            #pragma unroll
            for (int nt = 0; nt < 4; nt++) {
                float2 bb = *(const float2*)&sk[(wn * 32 + nt * 8 + g) * 40 + ks * 8 + 2 * t];
                b[nt][0] = __float_as_uint(bb.x); b[nt][1] = __float_as_uint(bb.y);
            }
            #pragma unroll
            for (int mt = 0; mt < 2; mt++)
                #pragma unroll
                for (int nt = 0; nt < 4; nt++)
                    mma8(d[mt][nt], a[mt], b[nt]);
        }
        __syncthreads();
    }
    // epilogue: exp2, store raw, fused sums of the same values
    float* ob = g_att + (size_t)bh * TD * TD + (size_t)i0 * TD + j0;
    float rsum[2][2] = {};
    float cs0[4] = {}, cs1[4] = {};
    #pragma unroll
    for (int mt = 0; mt < 2; mt++) {
        int r0 = wm * 32 + mt * 16 + g;
        #pragma unroll
        for (int nt = 0; nt < 4; nt++) {
            int col = wn * 32 + nt * 8 + 2 * t;
            float e0 = ex2(d[mt][nt][0]), e1 = ex2(d[mt][nt][1]);
            float e2 = ex2(d[mt][nt][2]), e3 = ex2(d[mt][nt][3]);
            *(float2*)(ob + (size_t)r0 * TD + col)       = make_float2(e0, e1);
            *(float2*)(ob + (size_t)(r0 + 8) * TD + col) = make_float2(e2, e3);
            rsum[mt][0] += e0 + e1; rsum[mt][1] += e2 + e3;
            cs0[nt] += e0 + e2;     cs1[nt] += e1 + e3;
        }
    }
    #pragma unroll
    for (int mt = 0; mt < 2; mt++)
        #pragma unroll
        for (int h = 0; h < 2; h++) {
            rsum[mt][h] += __shfl_xor_sync(0xffffffffu, rsum[mt][h], 1);
            rsum[mt][h] += __shfl_xor_sync(0xffffffffu, rsum[mt][h], 2);
        }
    #pragma unroll
    for (int nt = 0; nt < 4; nt++) {
        cs0[nt] += __shfl_xor_sync(0xffffffffu, cs0[nt], 4);
        cs0[nt] += __shfl_xor_sync(0xffffffffu, cs0[nt], 8);
        cs0[nt] += __shfl_xor_sync(0xffffffffu, cs0[nt], 16);
        cs1[nt] += __shfl_xor_sync(0xffffffffu, cs1[nt], 4);
        cs1[nt] += __shfl_xor_sync(0xffffffffu, cs1[nt], 8);
        cs1[nt] += __shfl_xor_sync(0xffffffffu, cs1[nt], 16);
    }
    __syncthreads();
    float* srowp = sq;                  // [2][128]
    float* scolp = sk;                  // [4][64]
    if (t == 0) {
        #pragma unroll
        for (int mt = 0; mt < 2; mt++) {
            srowp[wn * 128 + wm * 32 + mt * 16 + g]     = rsum[mt][0];
            srowp[wn * 128 + wm * 32 + mt * 16 + g + 8] = rsum[mt][1];
        }
    }
    if (g == 0) {
        #pragma unroll
        for (int nt = 0; nt < 4; nt++) {
            scolp[wm * 64 + wn * 32 + nt * 8 + 2 * t]     = cs0[nt];
            scolp[wm * 64 + wn * 32 + nt * 8 + 2 * t + 1] = cs1[nt];
        }
    }
    __syncthreads();
    if (tid < 128) {
        atomicAdd(&g_srow[bh * TD + i0 + tid], srowp[tid] + srowp[128 + tid]);
    } else if (tid < 192) {
        int c = tid - 128;
        atomicAdd(&g_scol[bh * TD + j0 + c],
                  scolp[c] + scolp[64 + c] + scolp[128 + c] + scolp[192 + c]);
    }
}

// ------------------------------------------- reciprocals of sums
__global__ void k_recip() {
    int i = blockIdx.x * 256 + threadIdx.x;
    g_prow[i] = 1.0f / g_srow[i];
    g_pcol[i] = 1.0f / g_scol[i];
}

// ================================================================ y = (E*(pr+pc)) @ v  (proven R3 kernel)
// 128x64 tile, 8 warps (4m x 2n), K-chunks of 32, E staged via smem.
__global__ __launch_bounds__(256, 2) void k_y() {
    __shared__ __align__(16) float sS[128 * 40];
    __shared__ __align__(16) float sV[32 * 72];
    __shared__ float spr[128];
    const int tid = threadIdx.x;
    const int lane = tid & 31, warp = tid >> 5;
    const int wm = warp >> 1, wn = warp & 1;
    const int g = lane >> 2, t = lane & 3;
    const int bh = blockIdx.y;
    const int i0 = blockIdx.x * 128;
    const float* eb  = g_att + (size_t)bh * TD * TD + (size_t)i0 * TD;
    const float* pcb = g_pcol + bh * TD;
    const size_t base = (size_t)(bh >> 3) * TD * CD + (bh & 7) * DD;
    const float* vb = g_v + base;
    if (tid < 128) spr[tid] = g_prow[bh * TD + i0 + tid];
    __syncthreads();
    float d[2][4][4] = {};
    #pragma unroll 1
    for (int kc = 0; kc < 64; kc++) {
        int k0 = kc * 32;
        #pragma unroll
        for (int l = 0; l < 4; l++) {
            int idx = tid + l * 256;
            int rr = idx >> 3, c4 = (idx & 7) * 4;
            int pbase = (c4 & 24) + ((c4 & 4) ? 1 : 0);
            float4 ev = *(const float4*)(eb + (size_t)rr * TD + k0 + c4);
            float4 pv = *(const float4*)(pcb + k0 + c4);
            float p = spr[rr];
            u32* ds = (u32*)&sS[rr * 40 + pbase];
            ds[0] = tf32c(ev.x * (p + pv.x)); ds[2] = tf32c(ev.y * (p + pv.y));
            ds[4] = tf32c(ev.z * (p + pv.z)); ds[6] = tf32c(ev.w * (p + pv.w));
        }
        #pragma unroll
        for (int l = 0; l < 2; l++) {
            int idx = tid + l * 256;
            int rk = idx >> 4, n4 = (idx & 15) * 4;
            *(float4*)&sV[rk * 72 + n4] = *(const float4*)(vb + (size_t)(k0 + rk) * CD + n4);
        }
        __syncthreads();
        #pragma unroll
        for (int ks = 0; ks < 4; ks++) {
            u32 a[2][4], b[4][2];
            #pragma unroll
            for (int mt = 0; mt < 2; mt++) {
                float2 lo = *(const float2*)&sS[(wm * 32 + mt * 16 + g) * 40 + ks * 8 + 2 * t];
                float2 hi = *(const float2*)&sS[(wm * 32 + mt * 16 + g + 8) * 40 + ks * 8 + 2 * t];
                a[mt][0] = __float_as_uint(lo.x); a[mt][2] = __float_as_uint(lo.y);
                a[mt][1] = __float_as_uint(hi.x); a[mt][3] = __float_as_uint(hi.y);
            }
            #pragma unroll
            for (int nt = 0; nt < 4; nt++) {
                int n = wn * 32 + nt * 8 + g;
                b[nt][0] = __float_as_uint(sV[(ks * 8 + t) * 72 + n]);
                b[nt][1] = __float_as_uint(sV[(ks * 8 + t + 4) * 72 + n]);
            }
            #pragma unroll
            for (int mt = 0; mt < 2; mt++)
                #pragma unroll
                for (int nt = 0; nt < 4; nt++)
                    mma8(d[mt][nt], a[mt], b[nt]);
        }
        __syncthreads();
    }
    float* yb = g_y + base + (size_t)i0 * CD;
    #pragma unroll
    for (int mt = 0; mt < 2; mt++) {
        int r0 = wm * 32 + mt * 16 + g;
        #pragma unroll
        for (int nt = 0; nt < 4; nt++) {
            int col = wn * 32 + nt * 8 + 2 * t;
            *(float2*)(yb + (size_t)r0 * CD + col)       = make_float2(d[mt][nt][0], d[mt][nt][1]);
            *(float2*)(yb + (size_t)(r0 + 8) * CD + col) = make_float2(d[mt][nt][2], d[mt][nt][3]);
        }
    }
}

// ================================================================ out = y @ W (NN, tf32 MMA)
// 128x64 tile; B = W^T staged via perm scatter.
__global__ __launch_bounds__(256, 2) void k_outgemm32(float* __restrict__ out) {
    __shared__ __align__(16) float sA[128 * 40];
    __shared__ __align__(16) float sB[64 * 40];
    const int tid = threadIdx.x;
    const int lane = tid & 31, warp = tid >> 5;
    const int wm = warp >> 1, wn = warp & 1;
    const int g = lane >> 2, t = lane & 3;
    const int i0 = blockIdx.y * 128, j0 = blockIdx.x * 64;
    const float* Ab = g_y + (size_t)i0 * CD;
    float d[2][4][4] = {};
    #pragma unroll 1
    for (int kc = 0; kc < 16; kc++) {
        int k0 = kc * 32;
        #pragma unroll
        for (int l = 0; l < 4; l++) {
            int idx = tid + l * 256;
            int rr = idx >> 3, c4 = (idx & 7) * 4;
            int pbase = (c4 & 24) + ((c4 & 4) ? 1 : 0);
            float4 v = *(const float4*)(Ab + (size_t)rr * CD + k0 + c4);
            sA[rr * 40 + pbase] = tf32f(v.x); sA[rr * 40 + pbase + 2] = tf32f(v.y);
            sA[rr * 40 + pbase + 4] = tf32f(v.z); sA[rr * 40 + pbase + 6] = tf32f(v.w);
        }
        // B = W^T: sB[n][k] layout from W[k][j0+n], perm over k
        #pragma unroll
        for (int l = 0; l < 2; l++) {
            int idx = tid + l * 256;
            int kk = idx >> 4, j4 = (idx & 15) * 4;
            float4 wv = *(const float4*)(g_W + (size_t)(k0 + kk) * CD + j0 + j4);
            int pk = (kk & 24) + 2 * (kk & 3) + ((kk >> 2) & 1);
            sB[(j4 + 0) * 40 + pk] = tf32f(wv.x);
            sB[(j4 + 1) * 40 + pk] = tf32f(wv.y);
            sB[(j4 + 2) * 40 + pk] = tf32f(wv.z);
            sB[(j4 + 3) * 40 + pk] = tf32f(wv.w);
        }
        __syncthreads();
        #pragma unroll
        for (int ks = 0; ks < 4; ks++) {
            u32 a[2][4], b[4][2];
            #pragma unroll
            for (int mt = 0; mt < 2; mt++) {
                float2 lo = *(const float2*)&sA[(wm * 32 + mt * 16 + g) * 40 + ks * 8 + 2 * t];
                float2 hi = *(const float2*)&sA[(wm * 32 + mt * 16 + g + 8) * 40 + ks * 8 + 2 * t];
                a[mt][0] = __float_as_uint(lo.x); a[mt][2] = __float_as_uint(lo.y);
                a[mt][1] = __float_as_uint(hi.x); a[mt][3] = __float_as_uint(hi.y);
            }
            #pragma unroll
            for (int nt = 0; nt < 4; nt++) {
                float2 bb = *(const float2*)&sB[(wn * 32 + nt * 8 + g) * 40 + ks * 8 + 2 * t];
                b[nt][0] = __float_as_uint(bb.x); b[nt][1] = __float_as_uint(bb.y);
            }
            #pragma unroll
            for (int mt = 0; mt < 2; mt++)
                #pragma unroll
                for (int nt = 0; nt < 4; nt++)
                    mma8(d[mt][nt], a[mt], b[nt]);
        }
        __syncthreads();
    }
    float* Cb = out + (size_t)i0 * CD + j0;
    #pragma unroll
    for (int mt = 0; mt < 2; mt++) {
        int r0 = wm * 32 + mt * 16 + g;
        #pragma unroll
        for (int nt = 0; nt < 4; nt++) {
            int col = wn * 32 + nt * 8 + 2 * t;
            *(float2*)(Cb + (size_t)r0 * CD + col)       = make_float2(d[mt][nt][0], d[mt][nt][1]);
            *(float2*)(Cb + (size_t)(r0 + 8) * CD + col) = make_float2(d[mt][nt][2], d[mt][nt][3]);
        }
    }
}

extern "C" void kernel_launch(void* const* d_in, const int* in_sizes, int n_in,
                              void* d_out, int out_size) {
    (void)in_sizes; (void)n_in; (void)out_size;
    const float* x  = (const float*)d_in[0];
    const float* dw = (const float*)d_in[1];
    const float* qw = (const float*)d_in[2];
    const float* g1 = (const float*)d_in[3];
    const float* g2 = (const float*)d_in[4];
    const float* g3 = (const float*)d_in[5];
    float* out = (float*)d_out;

    float *ps, *pc;
    cudaGetSymbolAddress((void**)&ps, g_srow);
    cudaGetSymbolAddress((void**)&pc, g_scol);
    cudaMemsetAsync(ps, 0, BH * TD * sizeof(float));
    cudaMemsetAsync(pc, 0, BH * TD * sizeof(float));

    k_addw<<<(CD * CD) / 256, 256>>>(dw, qw);
    k_wgemm32<<<dim3(CD / 64, RWS / 128), 256>>>(x);
    k_norm<<<NRW / 8, 256>>>(g1, g2, g3);
    k_att<<<dim3(TD / 64, TD / 128, BH), 256>>>();
    k_recip<<<(BH * TD) / 256, 256>>>();
    k_y<<<dim3(TD / 128, BH), 256>>>();
    k_outgemm32<<<dim3(CD / 64, RWS / 128), 256>>>(out);
}

// round 8
// speedup vs baseline: 1.4284x; 1.1177x over previous
#include <cuda_runtime.h>

#define TD 2048
#define CD 512
#define DD 64
#define BH 32
#define RWS 8192

typedef unsigned long long u64;
typedef unsigned int u32;

// ---------------- scratch ----------------
__device__ float g_W[CD * CD];
__device__ float g_q[RWS * CD];   // tf32-rounded, scaled by inv*0.125*log2e
__device__ float g_k[RWS * CD];   // tf32-rounded
__device__ float g_v[RWS * CD];   // tf32-rounded
__device__ float g_att[(size_t)BH * TD * TD];   // exp(att)
__device__ float g_srow[BH * TD];
__device__ float g_scol[BH * TD];
__device__ float g_prow[BH * TD];
__device__ float g_pcol[BH * TD];
__device__ float g_y[RWS * CD];

// ---------------- helpers ----------------
__device__ __forceinline__ u32 tf32c(float f) {
    u32 r; asm("cvt.rna.tf32.f32 %0, %1;" : "=r"(r) : "f"(f)); return r;
}
__device__ __forceinline__ float tf32f(float f) { return __uint_as_float(tf32c(f)); }
__device__ __forceinline__ float ex2(float x) {
    float y; asm("ex2.approx.f32 %0, %1;" : "=f"(y) : "f"(x)); return y;
}
__device__ __forceinline__ void mma8(float* d, const u32* a, const u32* b) {
    asm("mma.sync.aligned.m16n8k8.row.col.f32.tf32.tf32.f32 "
        "{%0,%1,%2,%3},{%4,%5,%6,%7},{%8,%9},{%0,%1,%2,%3};"
        : "+f"(d[0]), "+f"(d[1]), "+f"(d[2]), "+f"(d[3])
        : "r"(a[0]), "r"(a[1]), "r"(a[2]), "r"(a[3]), "r"(b[0]), "r"(b[1]));
}

// ---------------------------------------------------------------- W = dw + qw
__global__ void k_addw(const float* __restrict__ dw, const float* __restrict__ qw) {
    int i = blockIdx.x * 256 + threadIdx.x;
    g_W[i] = dw[i] + qw[i];
}

// ================================================================ fused: w = x@W^T tile (one head)
// + RMSNorm -> write q (scaled, tf32), k (tf32), v (tf32) directly. 128x64 tile.
__global__ __launch_bounds__(256, 2) void k_wnorm(const float* __restrict__ x,
                                                  const float* __restrict__ gg1,
                                                  const float* __restrict__ gg2,
                                                  const float* __restrict__ gg3) {
    __shared__ __align__(16) float sA[128 * 40];
    __shared__ __align__(16) float sB[64 * 40];
    __shared__ float sG[192];
    const int tid = threadIdx.x;
    const int lane = tid & 31, warp = tid >> 5;
    const int wm = warp >> 1, wn = warp & 1;
    const int g = lane >> 2, t = lane & 3;
    const int i0 = blockIdx.y * 128, j0 = blockIdx.x * 64;
    if (tid < 64) sG[tid] = gg1[tid];
    else if (tid < 128) sG[tid] = gg2[tid - 64];
    else if (tid < 192) sG[tid] = gg3[tid - 128];
    const float* Ab = x + (size_t)i0 * CD;
    const float* Bb = g_W + (size_t)j0 * CD;
    float d[2][4][4] = {};
    #pragma unroll 1
    for (int kc = 0; kc < 16; kc++) {
        int k0 = kc * 32;
        #pragma unroll
        for (int l = 0; l < 4; l++) {
            int idx = tid + l * 256;
            int rr = idx >> 3, c4 = (idx & 7) * 4;
            int pbase = (c4 & 24) + ((c4 & 4) ? 1 : 0);
            float4 v = *(const float4*)(Ab + (size_t)rr * CD + k0 + c4);
            sA[rr * 40 + pbase] = tf32f(v.x); sA[rr * 40 + pbase + 2] = tf32f(v.y);
            sA[rr * 40 + pbase + 4] = tf32f(v.z); sA[rr * 40 + pbase + 6] = tf32f(v.w);
        }
        #pragma unroll
        for (int l = 0; l < 2; l++) {
            int idx = tid + l * 256;
            int rr = idx >> 3, c4 = (idx & 7) * 4;
            int pbase = (c4 & 24) + ((c4 & 4) ? 1 : 0);
            float4 w = *(const float4*)(Bb + (size_t)rr * CD + k0 + c4);
            sB[rr * 40 + pbase] = tf32f(w.x); sB[rr * 40 + pbase + 2] = tf32f(w.y);
            sB[rr * 40 + pbase + 4] = tf32f(w.z); sB[rr * 40 + pbase + 6] = tf32f(w.w);
        }
        __syncthreads();
        #pragma unroll
        for (int ks = 0; ks < 4; ks++) {
            u32 a[2][4], b[4][2];
            #pragma unroll
            for (int mt = 0; mt < 2; mt++) {
                float2 lo = *(const float2*)&sA[(wm * 32 + mt * 16 + g) * 40 + ks * 8 + 2 * t];
                float2 hi = *(const float2*)&sA[(wm * 32 + mt * 16 + g + 8) * 40 + ks * 8 + 2 * t];
                a[mt][0] = __float_as_uint(lo.x); a[mt][2] = __float_as_uint(lo.y);
                a[mt][1] = __float_as_uint(hi.x); a[mt][3] = __float_as_uint(hi.y);
            }
            #pragma unroll
            for (int nt = 0; nt < 4; nt++) {
                float2 bb = *(const float2*)&sB[(wn * 32 + nt * 8 + g) * 40 + ks * 8 + 2 * t];
                b[nt][0] = __float_as_uint(bb.x); b[nt][1] = __float_as_uint(bb.y);
            }
            #pragma unroll
            for (int mt = 0; mt < 2; mt++)
                #pragma unroll
                for (int nt = 0; nt < 4; nt++)
                    mma8(d[mt][nt], a[mt], b[nt]);
        }
        __syncthreads();
    }
    // ---- fused RMSNorm epilogue ----
    // per-row sum of squares over this thread's cols (32-col half per wn)
    float ss0[2], ss1[2];
    #pragma unroll
    for (int mt = 0; mt < 2; mt++) {
        ss0[mt] = 0.f; ss1[mt] = 0.f;
        #pragma unroll
        for (int nt = 0; nt < 4; nt++) {
            ss0[mt] += d[mt][nt][0] * d[mt][nt][0] + d[mt][nt][1] * d[mt][nt][1];
            ss1[mt] += d[mt][nt][2] * d[mt][nt][2] + d[mt][nt][3] * d[mt][nt][3];
        }
        ss0[mt] += __shfl_xor_sync(0xffffffffu, ss0[mt], 1);
        ss0[mt] += __shfl_xor_sync(0xffffffffu, ss0[mt], 2);
        ss1[mt] += __shfl_xor_sync(0xffffffffu, ss1[mt], 1);
        ss1[mt] += __shfl_xor_sync(0xffffffffu, ss1[mt], 2);
    }
    float* ssb = sB;   // reuse: [2][128]
    if (t == 0) {
        #pragma unroll
        for (int mt = 0; mt < 2; mt++) {
            ssb[wn * 128 + wm * 32 + mt * 16 + g]     = ss0[mt];
            ssb[wn * 128 + wm * 32 + mt * 16 + g + 8] = ss1[mt];
        }
    }
    __syncthreads();
    #pragma unroll
    for (int mt = 0; mt < 2; mt++) {
        int r0 = wm * 32 + mt * 16 + g, r1 = r0 + 8;
        float inv0 = rsqrtf((ssb[r0] + ssb[128 + r0]) * (1.0f / 64.0f) + 1.1920929e-07f);
        float inv1 = rsqrtf((ssb[r1] + ssb[128 + r1]) * (1.0f / 64.0f) + 1.1920929e-07f);
        float q0 = inv0 * 0.125f * 1.44269504f;
        float q1 = inv1 * 0.125f * 1.44269504f;
        size_t a0 = (size_t)(i0 + r0) * CD + j0;
        size_t a1 = (size_t)(i0 + r1) * CD + j0;
        #pragma unroll
        for (int nt = 0; nt < 4; nt++) {
            int c = wn * 32 + nt * 8 + 2 * t;
            float G1a = sG[c], G1b = sG[c + 1];
            float G2a = sG[64 + c], G2b = sG[64 + c + 1];
            float G3a = sG[128 + c], G3b = sG[128 + c + 1];
            float v0 = d[mt][nt][0], v1 = d[mt][nt][1];
            float v2 = d[mt][nt][2], v3 = d[mt][nt][3];
            *(float2*)(g_q + a0 + c) = make_float2(tf32f(v0 * q0 * G1a), tf32f(v1 * q0 * G1b));
            *(float2*)(g_k + a0 + c) = make_float2(tf32f(v0 * inv0 * G2a), tf32f(v1 * inv0 * G2b));
            *(float2*)(g_v + a0 + c) = make_float2(tf32f(v0 * inv0 * G3a), tf32f(v1 * inv0 * G3b));
            *(float2*)(g_q + a1 + c) = make_float2(tf32f(v2 * q1 * G1a), tf32f(v3 * q1 * G1b));
            *(float2*)(g_k + a1 + c) = make_float2(tf32f(v2 * inv1 * G2a), tf32f(v3 * inv1 * G2b));
            *(float2*)(g_v + a1 + c) = make_float2(tf32f(v2 * inv1 * G3a), tf32f(v3 * inv1 * G3b));
        }
    }
}

// ================================================================ E = 2^(q@k^T), store + fused sums
// q tile (128x64) resident in smem across 2 j-subtiles of 64; stride 72, chunk offset 36.
#define ATT_SMEM ((128 * 72 + 64 * 72) * 4)
__global__ __launch_bounds__(256, 2) void k_att() {
    extern __shared__ __align__(16) float smd[];
    float* sq = smd;
    float* sk = smd + 128 * 72;
    const int tid = threadIdx.x;
    const int lane = tid & 31, warp = tid >> 5;
    const int wm = warp >> 1, wn = warp & 1;
    const int g = lane >> 2, t = lane & 3;
    const int bh = blockIdx.z;
    const int i0 = blockIdx.y * 128;
    const size_t base = (size_t)(bh >> 3) * TD * CD + (bh & 7) * DD;
    const float* qb = g_q + base + (size_t)i0 * CD;
    // fill full q tile 128x64 (2 chunks of 32 cols, perm layout)
    #pragma unroll
    for (int l = 0; l < 8; l++) {
        int idx = tid + l * 256;
        int rr = idx >> 4, cg = (idx & 15) * 4;
        int ch = cg >> 5, c4 = cg & 31;
        int pb = ch * 36 + (c4 & 24) + ((c4 & 4) ? 1 : 0);
        float4 v = *(const float4*)(qb + (size_t)rr * CD + cg);
        sq[rr * 72 + pb] = v.x; sq[rr * 72 + pb + 2] = v.y;
        sq[rr * 72 + pb + 4] = v.z; sq[rr * 72 + pb + 6] = v.w;
    }
    #pragma unroll 1
    for (int jj = 0; jj < 2; jj++) {
        int j0 = blockIdx.x * 128 + jj * 64;
        const float* kb = g_k + base + (size_t)j0 * CD;
        __syncthreads();   // sq visible; sk safe to refill (prev epilogue staging done)
        #pragma unroll
        for (int l = 0; l < 4; l++) {
            int idx = tid + l * 256;
            int rr = idx >> 4, cg = (idx & 15) * 4;
            int ch = cg >> 5, c4 = cg & 31;
            int pb = ch * 36 + (c4 & 24) + ((c4 & 4) ? 1 : 0);
            float4 w = *(const float4*)(kb + (size_t)rr * CD + cg);
            sk[rr * 72 + pb] = w.x; sk[rr * 72 + pb + 2] = w.y;
            sk[rr * 72 + pb + 4] = w.z; sk[rr * 72 + pb + 6] = w.w;
        }
        __syncthreads();
        float d[2][4][4] = {};
        #pragma unroll
        for (int ch = 0; ch < 2; ch++) {
            #pragma unroll
            for (int ks = 0; ks < 4; ks++) {
                int off = ch * 36 + ks * 8 + 2 * t;
                u32 a[2][4], b[4][2];
                #pragma unroll
                for (int mt = 0; mt < 2; mt++) {
                    float2 lo = *(const float2*)&sq[(wm * 32 + mt * 16 + g) * 72 + off];
                    float2 hi = *(const float2*)&sq[(wm * 32 + mt * 16 + g + 8) * 72 + off];
                    a[mt][0] = __float_as_uint(lo.x); a[mt][2] = __float_as_uint(lo.y);
                    a[mt][1] = __float_as_uint(hi.x); a[mt][3] = __float_as_uint(hi.y);
                }
                #pragma unroll
                for (int nt = 0; nt < 4; nt++) {
                    float2 bb = *(const float2*)&sk[(wn * 32 + nt * 8 + g) * 72 + off];
                    b[nt][0] = __float_as_uint(bb.x); b[nt][1] = __float_as_uint(bb.y);
                }
                #pragma unroll
                for (int mt = 0; mt < 2; mt++)
                    #pragma unroll
                    for (int nt = 0; nt < 4; nt++)
                        mma8(d[mt][nt], a[mt], b[nt]);
            }
        }
        // epilogue: exp2, store raw, fused sums
        float* ob = g_att + (size_t)bh * TD * TD + (size_t)i0 * TD + j0;
        float rsum[2][2] = {};
        float cs0[4] = {}, cs1[4] = {};
        #pragma unroll
        for (int mt = 0; mt < 2; mt++) {
            int r0 = wm * 32 + mt * 16 + g;
            #pragma unroll
            for (int nt = 0; nt < 4; nt++) {
                int col = wn * 32 + nt * 8 + 2 * t;
                float e0 = ex2(d[mt][nt][0]), e1 = ex2(d[mt][nt][1]);
                float e2 = ex2(d[mt][nt][2]), e3 = ex2(d[mt][nt][3]);
                *(float2*)(ob + (size_t)r0 * TD + col)       = make_float2(e0, e1);
                *(float2*)(ob + (size_t)(r0 + 8) * TD + col) = make_float2(e2, e3);
                rsum[mt][0] += e0 + e1; rsum[mt][1] += e2 + e3;
                cs0[nt] += e0 + e2;     cs1[nt] += e1 + e3;
            }
        }
        #pragma unroll
        for (int mt = 0; mt < 2; mt++)
            #pragma unroll
            for (int h = 0; h < 2; h++) {
                rsum[mt][h] += __shfl_xor_sync(0xffffffffu, rsum[mt][h], 1);
                rsum[mt][h] += __shfl_xor_sync(0xffffffffu, rsum[mt][h], 2);
            }
        #pragma unroll
        for (int nt = 0; nt < 4; nt++) {
            cs0[nt] += __shfl_xor_sync(0xffffffffu, cs0[nt], 4);
            cs0[nt] += __shfl_xor_sync(0xffffffffu, cs0[nt], 8);
            cs0[nt] += __shfl_xor_sync(0xffffffffu, cs0[nt], 16);
            cs1[nt] += __shfl_xor_sync(0xffffffffu, cs1[nt], 4);
            cs1[nt] += __shfl_xor_sync(0xffffffffu, cs1[nt], 8);
            cs1[nt] += __shfl_xor_sync(0xffffffffu, cs1[nt], 16);
        }
        __syncthreads();                    // MMA reads of sk done before staging reuse
        float* srowp = sk;                  // [2][128]
        float* scolp = sk + 256;            // [4][64]
        if (t == 0) {
            #pragma unroll
            for (int mt = 0; mt < 2; mt++) {
                srowp[wn * 128 + wm * 32 + mt * 16 + g]     = rsum[mt][0];
                srowp[wn * 128 + wm * 32 + mt * 16 + g + 8] = rsum[mt][1];
            }
        }
        if (g == 0) {
            #pragma unroll
            for (int nt = 0; nt < 4; nt++) {
                scolp[wm * 64 + wn * 32 + nt * 8 + 2 * t]     = cs0[nt];
                scolp[wm * 64 + wn * 32 + nt * 8 + 2 * t + 1] = cs1[nt];
            }
        }
        __syncthreads();
        if (tid < 128) {
            atomicAdd(&g_srow[bh * TD + i0 + tid], srowp[tid] + srowp[128 + tid]);
        } else if (tid < 192) {
            int c = tid - 128;
            atomicAdd(&g_scol[bh * TD + j0 + c],
                      scolp[c] + scolp[64 + c] + scolp[128 + c] + scolp[192 + c]);
        }
    }
}

// ------------------------------------------- reciprocals of sums
__global__ void k_recip() {
    int i = blockIdx.x * 256 + threadIdx.x;
    g_prow[i] = 1.0f / g_srow[i];
    g_pcol[i] = 1.0f / g_scol[i];
}

// ================================================================ y = (E*(pr+pc)) @ v  (proven)
__global__ __launch_bounds__(256, 2) void k_y() {
    __shared__ __align__(16) float sS[128 * 40];
    __shared__ __align__(16) float sV[32 * 72];
    __shared__ float spr[128];
    const int tid = threadIdx.x;
    const int lane = tid & 31, warp = tid >> 5;
    const int wm = warp >> 1, wn = warp & 1;
    const int g = lane >> 2, t = lane & 3;
    const int bh = blockIdx.y;
    const int i0 = blockIdx.x * 128;
    const float* eb  = g_att + (size_t)bh * TD * TD + (size_t)i0 * TD;
    const float* pcb = g_pcol + bh * TD;
    const size_t base = (size_t)(bh >> 3) * TD * CD + (bh & 7) * DD;
    const float* vb = g_v + base;
    if (tid < 128) spr[tid] = g_prow[bh * TD + i0 + tid];
    __syncthreads();
    float d[2][4][4] = {};
    #pragma unroll 1
    for (int kc = 0; kc < 64; kc++) {
        int k0 = kc * 32;
        #pragma unroll
        for (int l = 0; l < 4; l++) {
            int idx = tid + l * 256;
            int rr = idx >> 3, c4 = (idx & 7) * 4;
            int pbase = (c4 & 24) + ((c4 & 4) ? 1 : 0);
            float4 ev = *(const float4*)(eb + (size_t)rr * TD + k0 + c4);
            float4 pv = *(const float4*)(pcb + k0 + c4);
            float p = spr[rr];
            u32* ds = (u32*)&sS[rr * 40 + pbase];
            ds[0] = tf32c(ev.x * (p + pv.x)); ds[2] = tf32c(ev.y * (p + pv.y));
            ds[4] = tf32c(ev.z * (p + pv.z)); ds[6] = tf32c(ev.w * (p + pv.w));
        }
        #pragma unroll
        for (int l = 0; l < 2; l++) {
            int idx = tid + l * 256;
            int rk = idx >> 4, n4 = (idx & 15) * 4;
            *(float4*)&sV[rk * 72 + n4] = *(const float4*)(vb + (size_t)(k0 + rk) * CD + n4);
        }
        __syncthreads();
        #pragma unroll
        for (int ks = 0; ks < 4; ks++) {
            u32 a[2][4], b[4][2];
            #pragma unroll
            for (int mt = 0; mt < 2; mt++) {
                float2 lo = *(const float2*)&sS[(wm * 32 + mt * 16 + g) * 40 + ks * 8 + 2 * t];
                float2 hi = *(const float2*)&sS[(wm * 32 + mt * 16 + g + 8) * 40 + ks * 8 + 2 * t];
                a[mt][0] = __float_as_uint(lo.x); a[mt][2] = __float_as_uint(lo.y);
                a[mt][1] = __float_as_uint(hi.x); a[mt][3] = __float_as_uint(hi.y);
            }
            #pragma unroll
            for (int nt = 0; nt < 4; nt++) {
                int n = wn * 32 + nt * 8 + g;
                b[nt][0] = __float_as_uint(sV[(ks * 8 + t) * 72 + n]);
                b[nt][1] = __float_as_uint(sV[(ks * 8 + t + 4) * 72 + n]);
            }
            #pragma unroll
            for (int mt = 0; mt < 2; mt++)
                #pragma unroll
                for (int nt = 0; nt < 4; nt++)
                    mma8(d[mt][nt], a[mt], b[nt]);
        }
        __syncthreads();
    }
    float* yb = g_y + base + (size_t)i0 * CD;
    #pragma unroll
    for (int mt = 0; mt < 2; mt++) {
        int r0 = wm * 32 + mt * 16 + g;
        #pragma unroll
        for (int nt = 0; nt < 4; nt++) {
            int col = wn * 32 + nt * 8 + 2 * t;
            *(float2*)(yb + (size_t)r0 * CD + col)       = make_float2(d[mt][nt][0], d[mt][nt][1]);
            *(float2*)(yb + (size_t)(r0 + 8) * CD + col) = make_float2(d[mt][nt][2], d[mt][nt][3]);
        }
    }
}

// ================================================================ out = y @ W (NN, tf32 MMA)
__global__ __launch_bounds__(256, 2) void k_outgemm32(float* __restrict__ out) {
    __shared__ __align__(16) float sA[128 * 40];
    __shared__ __align__(16) float sB[64 * 40];
    const int tid = threadIdx.x;
    const int lane = tid & 31, warp = tid >> 5;
    const int wm = warp >> 1, wn = warp & 1;
    const int g = lane >> 2, t = lane & 3;
    const int i0 = blockIdx.y * 128, j0 = blockIdx.x * 64;
    const float* Ab = g_y + (size_t)i0 * CD;
    float d[2][4][4] = {};
    #pragma unroll 1
    for (int kc = 0; kc < 16; kc++) {
        int k0 = kc * 32;
        #pragma unroll
        for (int l = 0; l < 4; l++) {
            int idx = tid + l * 256;
            int rr = idx >> 3, c4 = (idx & 7) * 4;
            int pbase = (c4 & 24) + ((c4 & 4) ? 1 : 0);
            float4 v = *(const float4*)(Ab + (size_t)rr * CD + k0 + c4);
            sA[rr * 40 + pbase] = tf32f(v.x); sA[rr * 40 + pbase + 2] = tf32f(v.y);
            sA[rr * 40 + pbase + 4] = tf32f(v.z); sA[rr * 40 + pbase + 6] = tf32f(v.w);
        }
        #pragma unroll
        for (int l = 0; l < 2; l++) {
            int idx = tid + l * 256;
            int kk = idx >> 4, j4 = (idx & 15) * 4;
            float4 wv = *(const float4*)(g_W + (size_t)(k0 + kk) * CD + j0 + j4);
            int pk = (kk & 24) + 2 * (kk & 3) + ((kk >> 2) & 1);
            sB[(j4 + 0) * 40 + pk] = tf32f(wv.x);
            sB[(j4 + 1) * 40 + pk] = tf32f(wv.y);
            sB[(j4 + 2) * 40 + pk] = tf32f(wv.z);
            sB[(j4 + 3) * 40 + pk] = tf32f(wv.w);
        }
        __syncthreads();
        #pragma unroll
        for (int ks = 0; ks < 4; ks++) {
            u32 a[2][4], b[4][2];
            #pragma unroll
            for (int mt = 0; mt < 2; mt++) {
                float2 lo = *(const float2*)&sA[(wm * 32 + mt * 16 + g) * 40 + ks * 8 + 2 * t];
                float2 hi = *(const float2*)&sA[(wm * 32 + mt * 16 + g + 8) * 40 + ks * 8 + 2 * t];
                a[mt][0] = __float_as_uint(lo.x); a[mt][2] = __float_as_uint(lo.y);
                a[mt][1] = __float_as_uint(hi.x); a[mt][3] = __float_as_uint(hi.y);
            }
            #pragma unroll
            for (int nt = 0; nt < 4; nt++) {
                float2 bb = *(const float2*)&sB[(wn * 32 + nt * 8 + g) * 40 + ks * 8 + 2 * t];
                b[nt][0] = __float_as_uint(bb.x); b[nt][1] = __float_as_uint(bb.y);
            }
            #pragma unroll
            for (int mt = 0; mt < 2; mt++)
                #pragma unroll
                for (int nt = 0; nt < 4; nt++)
                    mma8(d[mt][nt], a[mt], b[nt]);
        }
        __syncthreads();
    }
    float* Cb = out + (size_t)i0 * CD + j0;
    #pragma unroll
    for (int mt = 0; mt < 2; mt++) {
        int r0 = wm * 32 + mt * 16 + g;
        #pragma unroll
        for (int nt = 0; nt < 4; nt++) {
            int col = wn * 32 + nt * 8 + 2 * t;
            *(float2*)(Cb + (size_t)r0 * CD + col)       = make_float2(d[mt][nt][0], d[mt][nt][1]);
            *(float2*)(Cb + (size_t)(r0 + 8) * CD + col) = make_float2(d[mt][nt][2], d[mt][nt][3]);
        }
    }
}

extern "C" void kernel_launch(void* const* d_in, const int* in_sizes, int n_in,
                              void* d_out, int out_size) {
    (void)in_sizes; (void)n_in; (void)out_size;
    const float* x  = (const float*)d_in[0];
    const float* dw = (const float*)d_in[1];
    const float* qw = (const float*)d_in[2];
    const float* g1 = (const float*)d_in[3];
    const float* g2 = (const float*)d_in[4];
    const float* g3 = (const float*)d_in[5];
    float* out = (float*)d_out;

    static int init_done = 0;
    if (!init_done) {
        cudaFuncSetAttribute(k_att, cudaFuncAttributeMaxDynamicSharedMemorySize, ATT_SMEM);
        init_done = 1;
    }

    float *ps, *pc;
    cudaGetSymbolAddress((void**)&ps, g_srow);
    cudaGetSymbolAddress((void**)&pc, g_scol);
    cudaMemsetAsync(ps, 0, BH * TD * sizeof(float));
    cudaMemsetAsync(pc, 0, BH * TD * sizeof(float));

    k_addw<<<(CD * CD) / 256, 256>>>(dw, qw);
    k_wnorm<<<dim3(CD / 64, RWS / 128), 256>>>(x, g1, g2, g3);
    k_att<<<dim3(TD / 128, TD / 128, BH), 256, ATT_SMEM>>>();
    k_recip<<<(BH * TD) / 256, 256>>>();
    k_y<<<dim3(TD / 128, BH), 256>>>();
    k_outgemm32<<<dim3(CD / 64, RWS / 128), 256>>>(out);
}

// round 9
// speedup vs baseline: 1.5139x; 1.0599x over previous
#include <cuda_runtime.h>
#include <cuda_fp16.h>

#define TD 2048
#define CD 512
#define DD 64
#define BH 32
#define RWS 8192

typedef unsigned long long u64;
typedef unsigned int u32;

// ---------------- scratch ----------------
__device__ float g_W[CD * CD];
__device__ float g_q[RWS * CD];   // tf32-rounded, scaled by inv*0.125*log2e
__device__ float g_k[RWS * CD];   // tf32-rounded
__device__ float g_v[RWS * CD];   // tf32-rounded
__device__ __half g_att[(size_t)BH * TD * TD];  // exp(att) in fp16
__device__ float g_srow[BH * TD];
__device__ float g_scol[BH * TD];
__device__ float g_prow[BH * TD];
__device__ float g_pcol[BH * TD];
__device__ float g_y[RWS * CD];

// ---------------- helpers ----------------
__device__ __forceinline__ u32 tf32c(float f) {
    u32 r; asm("cvt.rna.tf32.f32 %0, %1;" : "=r"(r) : "f"(f)); return r;
}
__device__ __forceinline__ float tf32f(float f) { return __uint_as_float(tf32c(f)); }
__device__ __forceinline__ float ex2(float x) {
    float y; asm("ex2.approx.f32 %0, %1;" : "=f"(y) : "f"(x)); return y;
}
__device__ __forceinline__ void mma8(float* d, const u32* a, const u32* b) {
    asm("mma.sync.aligned.m16n8k8.row.col.f32.tf32.tf32.f32 "
        "{%0,%1,%2,%3},{%4,%5,%6,%7},{%8,%9},{%0,%1,%2,%3};"
        : "+f"(d[0]), "+f"(d[1]), "+f"(d[2]), "+f"(d[3])
        : "r"(a[0]), "r"(a[1]), "r"(a[2]), "r"(a[3]), "r"(b[0]), "r"(b[1]));
}

// ---------------------------------------------------------------- W = dw + qw
__global__ void k_addw(const float* __restrict__ dw, const float* __restrict__ qw) {
    int i = blockIdx.x * 256 + threadIdx.x;
    g_W[i] = dw[i] + qw[i];
}

// ================================================================ fused: w = x@W^T (one head tile)
// + RMSNorm epilogue -> q (scaled, tf32), k (tf32), v (tf32). 128x64 tile.
__global__ __launch_bounds__(256, 2) void k_wnorm(const float* __restrict__ x,
                                                  const float* __restrict__ gg1,
                                                  const float* __restrict__ gg2,
                                                  const float* __restrict__ gg3) {
    __shared__ __align__(16) float sA[128 * 40];
    __shared__ __align__(16) float sB[64 * 40];
    __shared__ float sG[192];
    const int tid = threadIdx.x;
    const int lane = tid & 31, warp = tid >> 5;
    const int wm = warp >> 1, wn = warp & 1;
    const int g = lane >> 2, t = lane & 3;
    const int i0 = blockIdx.y * 128, j0 = blockIdx.x * 64;
    if (tid < 64) sG[tid] = gg1[tid];
    else if (tid < 128) sG[tid] = gg2[tid - 64];
    else if (tid < 192) sG[tid] = gg3[tid - 128];
    const float* Ab = x + (size_t)i0 * CD;
    const float* Bb = g_W + (size_t)j0 * CD;
    float d[2][4][4] = {};
    #pragma unroll 1
    for (int kc = 0; kc < 16; kc++) {
        int k0 = kc * 32;
        #pragma unroll
        for (int l = 0; l < 4; l++) {
            int idx = tid + l * 256;
            int rr = idx >> 3, c4 = (idx & 7) * 4;
            int pbase = (c4 & 24) + ((c4 & 4) ? 1 : 0);
            float4 v = *(const float4*)(Ab + (size_t)rr * CD + k0 + c4);
            sA[rr * 40 + pbase] = tf32f(v.x); sA[rr * 40 + pbase + 2] = tf32f(v.y);
            sA[rr * 40 + pbase + 4] = tf32f(v.z); sA[rr * 40 + pbase + 6] = tf32f(v.w);
        }
        #pragma unroll
        for (int l = 0; l < 2; l++) {
            int idx = tid + l * 256;
            int rr = idx >> 3, c4 = (idx & 7) * 4;
            int pbase = (c4 & 24) + ((c4 & 4) ? 1 : 0);
            float4 w = *(const float4*)(Bb + (size_t)rr * CD + k0 + c4);
            sB[rr * 40 + pbase] = tf32f(w.x); sB[rr * 40 + pbase + 2] = tf32f(w.y);
            sB[rr * 40 + pbase + 4] = tf32f(w.z); sB[rr * 40 + pbase + 6] = tf32f(w.w);
        }
        __syncthreads();
        #pragma unroll
        for (int ks = 0; ks < 4; ks++) {
            u32 a[2][4], b[4][2];
            #pragma unroll
            for (int mt = 0; mt < 2; mt++) {
                float2 lo = *(const float2*)&sA[(wm * 32 + mt * 16 + g) * 40 + ks * 8 + 2 * t];
                float2 hi = *(const float2*)&sA[(wm * 32 + mt * 16 + g + 8) * 40 + ks * 8 + 2 * t];
                a[mt][0] = __float_as_uint(lo.x); a[mt][2] = __float_as_uint(lo.y);
                a[mt][1] = __float_as_uint(hi.x); a[mt][3] = __float_as_uint(hi.y);
            }
            #pragma unroll
            for (int nt = 0; nt < 4; nt++) {
                float2 bb = *(const float2*)&sB[(wn * 32 + nt * 8 + g) * 40 + ks * 8 + 2 * t];
                b[nt][0] = __float_as_uint(bb.x); b[nt][1] = __float_as_uint(bb.y);
            }
            #pragma unroll
            for (int mt = 0; mt < 2; mt++)
                #pragma unroll
                for (int nt = 0; nt < 4; nt++)
                    mma8(d[mt][nt], a[mt], b[nt]);
        }
        __syncthreads();
    }
    // ---- fused RMSNorm epilogue ----
    float ss0[2], ss1[2];
    #pragma unroll
    for (int mt = 0; mt < 2; mt++) {
        ss0[mt] = 0.f; ss1[mt] = 0.f;
        #pragma unroll
        for (int nt = 0; nt < 4; nt++) {
            ss0[mt] += d[mt][nt][0] * d[mt][nt][0] + d[mt][nt][1] * d[mt][nt][1];
            ss1[mt] += d[mt][nt][2] * d[mt][nt][2] + d[mt][nt][3] * d[mt][nt][3];
        }
        ss0[mt] += __shfl_xor_sync(0xffffffffu, ss0[mt], 1);
        ss0[mt] += __shfl_xor_sync(0xffffffffu, ss0[mt], 2);
        ss1[mt] += __shfl_xor_sync(0xffffffffu, ss1[mt], 1);
        ss1[mt] += __shfl_xor_sync(0xffffffffu, ss1[mt], 2);
    }
    float* ssb = sB;   // reuse: [2][128]
    if (t == 0) {
        #pragma unroll
        for (int mt = 0; mt < 2; mt++) {
            ssb[wn * 128 + wm * 32 + mt * 16 + g]     = ss0[mt];
            ssb[wn * 128 + wm * 32 + mt * 16 + g + 8] = ss1[mt];
        }
    }
    __syncthreads();
    #pragma unroll
    for (int mt = 0; mt < 2; mt++) {
        int r0 = wm * 32 + mt * 16 + g, r1 = r0 + 8;
        float inv0 = rsqrtf((ssb[r0] + ssb[128 + r0]) * (1.0f / 64.0f) + 1.1920929e-07f);
        float inv1 = rsqrtf((ssb[r1] + ssb[128 + r1]) * (1.0f / 64.0f) + 1.1920929e-07f);
        float q0 = inv0 * 0.125f * 1.44269504f;
        float q1 = inv1 * 0.125f * 1.44269504f;
        size_t a0 = (size_t)(i0 + r0) * CD + j0;
        size_t a1 = (size_t)(i0 + r1) * CD + j0;
        #pragma unroll
        for (int nt = 0; nt < 4; nt++) {
            int c = wn * 32 + nt * 8 + 2 * t;
            float G1a = sG[c], G1b = sG[c + 1];
            float G2a = sG[64 + c], G2b = sG[64 + c + 1];
            float G3a = sG[128 + c], G3b = sG[128 + c + 1];
            float v0 = d[mt][nt][0], v1 = d[mt][nt][1];
            float v2 = d[mt][nt][2], v3 = d[mt][nt][3];
            *(float2*)(g_q + a0 + c) = make_float2(tf32f(v0 * q0 * G1a), tf32f(v1 * q0 * G1b));
            *(float2*)(g_k + a0 + c) = make_float2(tf32f(v0 * inv0 * G2a), tf32f(v1 * inv0 * G2b));
            *(float2*)(g_v + a0 + c) = make_float2(tf32f(v0 * inv0 * G3a), tf32f(v1 * inv0 * G3b));
            *(float2*)(g_q + a1 + c) = make_float2(tf32f(v2 * q1 * G1a), tf32f(v3 * q1 * G1b));
            *(float2*)(g_k + a1 + c) = make_float2(tf32f(v2 * inv1 * G2a), tf32f(v3 * inv1 * G2b));
            *(float2*)(g_v + a1 + c) = make_float2(tf32f(v2 * inv1 * G3a), tf32f(v3 * inv1 * G3b));
        }
    }
}

// ================================================================ E = 2^(q@k^T) -> fp16, fused sums
// q tile (128x64) resident across 4 j-subtiles of 64; row sums accumulated in regs across subtiles.
#define ATT_SMEM ((128 * 72 + 64 * 72) * 4)
__global__ __launch_bounds__(256, 2) void k_att() {
    extern __shared__ __align__(16) float smd[];
    float* sq = smd;
    float* sk = smd + 128 * 72;
    const int tid = threadIdx.x;
    const int lane = tid & 31, warp = tid >> 5;
    const int wm = warp >> 1, wn = warp & 1;
    const int g = lane >> 2, t = lane & 3;
    const int bh = blockIdx.z;
    const int i0 = blockIdx.y * 128;
    const size_t base = (size_t)(bh >> 3) * TD * CD + (bh & 7) * DD;
    const float* qb = g_q + base + (size_t)i0 * CD;
    #pragma unroll
    for (int l = 0; l < 8; l++) {
        int idx = tid + l * 256;
        int rr = idx >> 4, cg = (idx & 15) * 4;
        int ch = cg >> 5, c4 = cg & 31;
        int pb = ch * 36 + (c4 & 24) + ((c4 & 4) ? 1 : 0);
        float4 v = *(const float4*)(qb + (size_t)rr * CD + cg);
        sq[rr * 72 + pb] = v.x; sq[rr * 72 + pb + 2] = v.y;
        sq[rr * 72 + pb + 4] = v.z; sq[rr * 72 + pb + 6] = v.w;
    }
    float rsum[2][2] = {};
    #pragma unroll 1
    for (int jj = 0; jj < 4; jj++) {
        int j0 = blockIdx.x * 256 + jj * 64;
        const float* kb = g_k + base + (size_t)j0 * CD;
        __syncthreads();
        #pragma unroll
        for (int l = 0; l < 4; l++) {
            int idx = tid + l * 256;
            int rr = idx >> 4, cg = (idx & 15) * 4;
            int ch = cg >> 5, c4 = cg & 31;
            int pb = ch * 36 + (c4 & 24) + ((c4 & 4) ? 1 : 0);
            float4 w = *(const float4*)(kb + (size_t)rr * CD + cg);
            sk[rr * 72 + pb] = w.x; sk[rr * 72 + pb + 2] = w.y;
            sk[rr * 72 + pb + 4] = w.z; sk[rr * 72 + pb + 6] = w.w;
        }
        __syncthreads();
        float d[2][4][4] = {};
        #pragma unroll
        for (int ch = 0; ch < 2; ch++) {
            #pragma unroll
            for (int ks = 0; ks < 4; ks++) {
                int off = ch * 36 + ks * 8 + 2 * t;
                u32 a[2][4], b[4][2];
                #pragma unroll
                for (int mt = 0; mt < 2; mt++) {
                    float2 lo = *(const float2*)&sq[(wm * 32 + mt * 16 + g) * 72 + off];
                    float2 hi = *(const float2*)&sq[(wm * 32 + mt * 16 + g + 8) * 72 + off];
                    a[mt][0] = __float_as_uint(lo.x); a[mt][2] = __float_as_uint(lo.y);
                    a[mt][1] = __float_as_uint(hi.x); a[mt][3] = __float_as_uint(hi.y);
                }
                #pragma unroll
                for (int nt = 0; nt < 4; nt++) {
                    float2 bb = *(const float2*)&sk[(wn * 32 + nt * 8 + g) * 72 + off];
                    b[nt][0] = __float_as_uint(bb.x); b[nt][1] = __float_as_uint(bb.y);
                }
                #pragma unroll
                for (int mt = 0; mt < 2; mt++)
                    #pragma unroll
                    for (int nt = 0; nt < 4; nt++)
                        mma8(d[mt][nt], a[mt], b[nt]);
            }
        }
        // epilogue: exp2 -> fp16, store; sums taken from the SAME fp16-rounded values
        __half* ob = g_att + (size_t)bh * TD * TD + (size_t)i0 * TD + j0;
        float cs0[4] = {}, cs1[4] = {};
        #pragma unroll
        for (int mt = 0; mt < 2; mt++) {
            int r0 = wm * 32 + mt * 16 + g;
            #pragma unroll
            for (int nt = 0; nt < 4; nt++) {
                int col = wn * 32 + nt * 8 + 2 * t;
                __half2 h01 = __floats2half2_rn(ex2(d[mt][nt][0]), ex2(d[mt][nt][1]));
                __half2 h23 = __floats2half2_rn(ex2(d[mt][nt][2]), ex2(d[mt][nt][3]));
                *(__half2*)(ob + (size_t)r0 * TD + col)       = h01;
                *(__half2*)(ob + (size_t)(r0 + 8) * TD + col) = h23;
                float2 f01 = __half22float2(h01), f23 = __half22float2(h23);
                rsum[mt][0] += f01.x + f01.y; rsum[mt][1] += f23.x + f23.y;
                cs0[nt] += f01.x + f23.x;     cs1[nt] += f01.y + f23.y;
            }
        }
        #pragma unroll
        for (int nt = 0; nt < 4; nt++) {
            cs0[nt] += __shfl_xor_sync(0xffffffffu, cs0[nt], 4);
            cs0[nt] += __shfl_xor_sync(0xffffffffu, cs0[nt], 8);
            cs0[nt] += __shfl_xor_sync(0xffffffffu, cs0[nt], 16);
            cs1[nt] += __shfl_xor_sync(0xffffffffu, cs1[nt], 4);
            cs1[nt] += __shfl_xor_sync(0xffffffffu, cs1[nt], 8);
            cs1[nt] += __shfl_xor_sync(0xffffffffu, cs1[nt], 16);
        }
        __syncthreads();               // MMA reads of sk done before staging reuse
        float* scolp = sk;             // [4][64]
        if (g == 0) {
            #pragma unroll
            for (int nt = 0; nt < 4; nt++) {
                scolp[wm * 64 + wn * 32 + nt * 8 + 2 * t]     = cs0[nt];
                scolp[wm * 64 + wn * 32 + nt * 8 + 2 * t + 1] = cs1[nt];
            }
        }
        __syncthreads();
        if (tid < 64) {
            atomicAdd(&g_scol[bh * TD + j0 + tid],
                      scolp[tid] + scolp[64 + tid] + scolp[128 + tid] + scolp[192 + tid]);
        }
    }
    // row sums: reduce over t, stage, one atomic pass
    #pragma unroll
    for (int mt = 0; mt < 2; mt++)
        #pragma unroll
        for (int h = 0; h < 2; h++) {
            rsum[mt][h] += __shfl_xor_sync(0xffffffffu, rsum[mt][h], 1);
            rsum[mt][h] += __shfl_xor_sync(0xffffffffu, rsum[mt][h], 2);
        }
    __syncthreads();
    float* srowp = sk;                 // [2][128]
    if (t == 0) {
        #pragma unroll
        for (int mt = 0; mt < 2; mt++) {
            srowp[wn * 128 + wm * 32 + mt * 16 + g]     = rsum[mt][0];
            srowp[wn * 128 + wm * 32 + mt * 16 + g + 8] = rsum[mt][1];
        }
    }
    __syncthreads();
    if (tid < 128)
        atomicAdd(&g_srow[bh * TD + i0 + tid], srowp[tid] + srowp[128 + tid]);
}

// ------------------------------------------- reciprocals of sums
__global__ void k_recip() {
    int i = blockIdx.x * 256 + threadIdx.x;
    g_prow[i] = 1.0f / g_srow[i];
    g_pcol[i] = 1.0f / g_scol[i];
}

// ================================================================ y = (E*(pr+pc)) @ v
// Proven tf32 structure; E read as fp16 (half the bytes), converted+scaled at smem fill.
__global__ __launch_bounds__(256, 2) void k_y() {
    __shared__ __align__(16) float sS[128 * 40];
    __shared__ __align__(16) float sV[32 * 72];
    __shared__ float spr[128];
    const int tid = threadIdx.x;
    const int lane = tid & 31, warp = tid >> 5;
    const int wm = warp >> 1, wn = warp & 1;
    const int g = lane >> 2, t = lane & 3;
    const int bh = blockIdx.y;
    const int i0 = blockIdx.x * 128;
    const __half* eb = g_att + (size_t)bh * TD * TD + (size_t)i0 * TD;
    const float* pcb = g_pcol + bh * TD;
    const size_t base = (size_t)(bh >> 3) * TD * CD + (bh & 7) * DD;
    const float* vb = g_v + base;
    if (tid < 128) spr[tid] = g_prow[bh * TD + i0 + tid];
    __syncthreads();
    float d[2][4][4] = {};
    #pragma unroll 1
    for (int kc = 0; kc < 64; kc++) {
        int k0 = kc * 32;
        #pragma unroll
        for (int l = 0; l < 4; l++) {
            int idx = tid + l * 256;
            int rr = idx >> 3, c4 = (idx & 7) * 4;
            int pbase = (c4 & 24) + ((c4 & 4) ? 1 : 0);
            uint2 raw = *(const uint2*)(eb + (size_t)rr * TD + k0 + c4);
            float2 e01 = __half22float2(*(__half2*)&raw.x);
            float2 e23 = __half22float2(*(__half2*)&raw.y);
            float4 pv = *(const float4*)(pcb + k0 + c4);
            float p = spr[rr];
            u32* ds = (u32*)&sS[rr * 40 + pbase];
            ds[0] = tf32c(e01.x * (p + pv.x)); ds[2] = tf32c(e01.y * (p + pv.y));
            ds[4] = tf32c(e23.x * (p + pv.z)); ds[6] = tf32c(e23.y * (p + pv.w));
        }
        #pragma unroll
        for (int l = 0; l < 2; l++) {
            int idx = tid + l * 256;
            int rk = idx >> 4, n4 = (idx & 15) * 4;
            *(float4*)&sV[rk * 72 + n4] = *(const float4*)(vb + (size_t)(k0 + rk) * CD + n4);
        }
        __syncthreads();
        #pragma unroll
        for (int ks = 0; ks < 4; ks++) {
            u32 a[2][4], b[4][2];
            #pragma unroll
            for (int mt = 0; mt < 2; mt++) {
                float2 lo = *(const float2*)&sS[(wm * 32 + mt * 16 + g) * 40 + ks * 8 + 2 * t];
                float2 hi = *(const float2*)&sS[(wm * 32 + mt * 16 + g + 8) * 40 + ks * 8 + 2 * t];
                a[mt][0] = __float_as_uint(lo.x); a[mt][2] = __float_as_uint(lo.y);
                a[mt][1] = __float_as_uint(hi.x); a[mt][3] = __float_as_uint(hi.y);
            }
            #pragma unroll
            for (int nt = 0; nt < 4; nt++) {
                int n = wn * 32 + nt * 8 + g;
                b[nt][0] = __float_as_uint(sV[(ks * 8 + t) * 72 + n]);
                b[nt][1] = __float_as_uint(sV[(ks * 8 + t + 4) * 72 + n]);
            }
            #pragma unroll
            for (int mt = 0; mt < 2; mt++)
                #pragma unroll
                for (int nt = 0; nt < 4; nt++)
                    mma8(d[mt][nt], a[mt], b[nt]);
        }
        __syncthreads();
    }
    float* yb = g_y + base + (size_t)i0 * CD;
    #pragma unroll
    for (int mt = 0; mt < 2; mt++) {
        int r0 = wm * 32 + mt * 16 + g;
        #pragma unroll
        for (int nt = 0; nt < 4; nt++) {
            int col = wn * 32 + nt * 8 + 2 * t;
            *(float2*)(yb + (size_t)r0 * CD + col)       = make_float2(d[mt][nt][0], d[mt][nt][1]);
            *(float2*)(yb + (size_t)(r0 + 8) * CD + col) = make_float2(d[mt][nt][2], d[mt][nt][3]);
        }
    }
}

// ================================================================ out = y @ W (NN, tf32 MMA)
__global__ __launch_bounds__(256, 2) void k_outgemm32(float* __restrict__ out) {
    __shared__ __align__(16) float sA[128 * 40];
    __shared__ __align__(16) float sB[64 * 40];
    const int tid = threadIdx.x;
    const int lane = tid & 31, warp = tid >> 5;
    const int wm = warp >> 1, wn = warp & 1;
    const int g = lane >> 2, t = lane & 3;
    const int i0 = blockIdx.y * 128, j0 = blockIdx.x * 64;
    const float* Ab = g_y + (size_t)i0 * CD;
    float d[2][4][4] = {};
    #pragma unroll 1
    for (int kc = 0; kc < 16; kc++) {
        int k0 = kc * 32;
        #pragma unroll
        for (int l = 0; l < 4; l++) {
            int idx = tid + l * 256;
            int rr = idx >> 3, c4 = (idx & 7) * 4;
            int pbase = (c4 & 24) + ((c4 & 4) ? 1 : 0);
            float4 v = *(const float4*)(Ab + (size_t)rr * CD + k0 + c4);
            sA[rr * 40 + pbase] = tf32f(v.x); sA[rr * 40 + pbase + 2] = tf32f(v.y);
            sA[rr * 40 + pbase + 4] = tf32f(v.z); sA[rr * 40 + pbase + 6] = tf32f(v.w);
        }
        #pragma unroll
        for (int l = 0; l < 2; l++) {
            int idx = tid + l * 256;
            int kk = idx >> 4, j4 = (idx & 15) * 4;
            float4 wv = *(const float4*)(g_W + (size_t)(k0 + kk) * CD + j0 + j4);
            int pk = (kk & 24) + 2 * (kk & 3) + ((kk >> 2) & 1);
            sB[(j4 + 0) * 40 + pk] = tf32f(wv.x);
            sB[(j4 + 1) * 40 + pk] = tf32f(wv.y);
            sB[(j4 + 2) * 40 + pk] = tf32f(wv.z);
            sB[(j4 + 3) * 40 + pk] = tf32f(wv.w);
        }
        __syncthreads();
        #pragma unroll
        for (int ks = 0; ks < 4; ks++) {
            u32 a[2][4], b[4][2];
            #pragma unroll
            for (int mt = 0; mt < 2; mt++) {
                float2 lo = *(const float2*)&sA[(wm * 32 + mt * 16 + g) * 40 + ks * 8 + 2 * t];
                float2 hi = *(const float2*)&sA[(wm * 32 + mt * 16 + g + 8) * 40 + ks * 8 + 2 * t];
                a[mt][0] = __float_as_uint(lo.x); a[mt][2] = __float_as_uint(lo.y);
                a[mt][1] = __float_as_uint(hi.x); a[mt][3] = __float_as_uint(hi.y);
            }
            #pragma unroll
            for (int nt = 0; nt < 4; nt++) {
                float2 bb = *(const float2*)&sB[(wn * 32 + nt * 8 + g) * 40 + ks * 8 + 2 * t];
                b[nt][0] = __float_as_uint(bb.x); b[nt][1] = __float_as_uint(bb.y);
            }
            #pragma unroll
            for (int mt = 0; mt < 2; mt++)
                #pragma unroll
                for (int nt = 0; nt < 4; nt++)
                    mma8(d[mt][nt], a[mt], b[nt]);
        }
        __syncthreads();
    }
    float* Cb = out + (size_t)i0 * CD + j0;
    #pragma unroll
    for (int mt = 0; mt < 2; mt++) {
        int r0 = wm * 32 + mt * 16 + g;
        #pragma unroll
        for (int nt = 0; nt < 4; nt++) {
            int col = wn * 32 + nt * 8 + 2 * t;
            *(float2*)(Cb + (size_t)r0 * CD + col)       = make_float2(d[mt][nt][0], d[mt][nt][1]);
            *(float2*)(Cb + (size_t)(r0 + 8) * CD + col) = make_float2(d[mt][nt][2], d[mt][nt][3]);
        }
    }
}

extern "C" void kernel_launch(void* const* d_in, const int* in_sizes, int n_in,
                              void* d_out, int out_size) {
    (void)in_sizes; (void)n_in; (void)out_size;
    const float* x  = (const float*)d_in[0];
    const float* dw = (const float*)d_in[1];
    const float* qw = (const float*)d_in[2];
    const float* g1 = (const float*)d_in[3];
    const float* g2 = (const float*)d_in[4];
    const float* g3 = (const float*)d_in[5];
    float* out = (float*)d_out;

    static int init_done = 0;
    if (!init_done) {
        cudaFuncSetAttribute(k_att, cudaFuncAttributeMaxDynamicSharedMemorySize, ATT_SMEM);
        init_done = 1;
    }

    float *ps, *pc;
    cudaGetSymbolAddress((void**)&ps, g_srow);
    cudaGetSymbolAddress((void**)&pc, g_scol);
    cudaMemsetAsync(ps, 0, BH * TD * sizeof(float));
    cudaMemsetAsync(pc, 0, BH * TD * sizeof(float));

    k_addw<<<(CD * CD) / 256, 256>>>(dw, qw);
    k_wnorm<<<dim3(CD / 64, RWS / 128), 256>>>(x, g1, g2, g3);
    k_att<<<dim3(TD / 256, TD / 128, BH), 256, ATT_SMEM>>>();
    k_recip<<<(BH * TD) / 256, 256>>>();
    k_y<<<dim3(TD / 128, BH), 256>>>();
    k_outgemm32<<<dim3(CD / 64, RWS / 128), 256>>>(out);
}

// round 10
// speedup vs baseline: 1.5818x; 1.0449x over previous
#include <cuda_runtime.h>
#include <cuda_fp16.h>

#define TD 2048
#define CD 512
#define DD 64
#define BH 32
#define RWS 8192

typedef unsigned long long u64;
typedef unsigned int u32;

// ---------------- scratch ----------------
__device__ float g_W[CD * CD];
__device__ float g_q[RWS * CD];   // tf32-rounded, scaled by inv*0.125*log2e
__device__ float g_k[RWS * CD];   // tf32-rounded
__device__ float g_v[RWS * CD];   // tf32-rounded
__device__ __half g_att[(size_t)BH * TD * TD];  // exp(att) in fp16
__device__ __half g_vt[(size_t)BH * DD * TD];   // v transposed [bh][d][k], fp16
__device__ __half g_pvt[(size_t)BH * DD * TD];  // 4096*pc*v transposed, fp16
__device__ float g_srow[BH * TD];
__device__ float g_scol[BH * TD];
__device__ float g_prow[BH * TD];
__device__ float g_pcol[BH * TD];
__device__ float g_y[RWS * CD];

// ---------------- helpers ----------------
__device__ __forceinline__ u32 tf32c(float f) {
    u32 r; asm("cvt.rna.tf32.f32 %0, %1;" : "=r"(r) : "f"(f)); return r;
}
__device__ __forceinline__ float tf32f(float f) { return __uint_as_float(tf32c(f)); }
__device__ __forceinline__ float ex2(float x) {
    float y; asm("ex2.approx.f32 %0, %1;" : "=f"(y) : "f"(x)); return y;
}
__device__ __forceinline__ void mma8(float* d, const u32* a, const u32* b) {
    asm("mma.sync.aligned.m16n8k8.row.col.f32.tf32.tf32.f32 "
        "{%0,%1,%2,%3},{%4,%5,%6,%7},{%8,%9},{%0,%1,%2,%3};"
        : "+f"(d[0]), "+f"(d[1]), "+f"(d[2]), "+f"(d[3])
        : "r"(a[0]), "r"(a[1]), "r"(a[2]), "r"(a[3]), "r"(b[0]), "r"(b[1]));
}
__device__ __forceinline__ void mma16(float* d, u32 a0, u32 a1, u32 a2, u32 a3,
                                      u32 b0, u32 b1) {
    asm("mma.sync.aligned.m16n8k16.row.col.f32.f16.f16.f32 "
        "{%0,%1,%2,%3},{%4,%5,%6,%7},{%8,%9},{%0,%1,%2,%3};"
        : "+f"(d[0]), "+f"(d[1]), "+f"(d[2]), "+f"(d[3])
        : "r"(a0), "r"(a1), "r"(a2), "r"(a3), "r"(b0), "r"(b1));
}

// ---------------------------------------------------------------- W = dw + qw
__global__ void k_addw(const float* __restrict__ dw, const float* __restrict__ qw) {
    int i = blockIdx.x * 256 + threadIdx.x;
    g_W[i] = dw[i] + qw[i];
}

// ================================================================ fused: w = x@W^T (one head tile)
// + RMSNorm epilogue -> q (scaled, tf32), k (tf32), v (tf32). 128x64 tile.
__global__ __launch_bounds__(256, 2) void k_wnorm(const float* __restrict__ x,
                                                  const float* __restrict__ gg1,
                                                  const float* __restrict__ gg2,
                                                  const float* __restrict__ gg3) {
    __shared__ __align__(16) float sA[128 * 40];
    __shared__ __align__(16) float sB[64 * 40];
    __shared__ float sG[192];
    const int tid = threadIdx.x;
    const int lane = tid & 31, warp = tid >> 5;
    const int wm = warp >> 1, wn = warp & 1;
    const int g = lane >> 2, t = lane & 3;
    const int i0 = blockIdx.y * 128, j0 = blockIdx.x * 64;
    if (tid < 64) sG[tid] = gg1[tid];
    else if (tid < 128) sG[tid] = gg2[tid - 64];
    else if (tid < 192) sG[tid] = gg3[tid - 128];
    const float* Ab = x + (size_t)i0 * CD;
    const float* Bb = g_W + (size_t)j0 * CD;
    float d[2][4][4] = {};
    #pragma unroll 1
    for (int kc = 0; kc < 16; kc++) {
        int k0 = kc * 32;
        #pragma unroll
        for (int l = 0; l < 4; l++) {
            int idx = tid + l * 256;
            int rr = idx >> 3, c4 = (idx & 7) * 4;
            int pbase = (c4 & 24) + ((c4 & 4) ? 1 : 0);
            float4 v = *(const float4*)(Ab + (size_t)rr * CD + k0 + c4);
            sA[rr * 40 + pbase] = tf32f(v.x); sA[rr * 40 + pbase + 2] = tf32f(v.y);
            sA[rr * 40 + pbase + 4] = tf32f(v.z); sA[rr * 40 + pbase + 6] = tf32f(v.w);
        }
        #pragma unroll
        for (int l = 0; l < 2; l++) {
            int idx = tid + l * 256;
            int rr = idx >> 3, c4 = (idx & 7) * 4;
            int pbase = (c4 & 24) + ((c4 & 4) ? 1 : 0);
            float4 w = *(const float4*)(Bb + (size_t)rr * CD + k0 + c4);
            sB[rr * 40 + pbase] = tf32f(w.x); sB[rr * 40 + pbase + 2] = tf32f(w.y);
            sB[rr * 40 + pbase + 4] = tf32f(w.z); sB[rr * 40 + pbase + 6] = tf32f(w.w);
        }
        __syncthreads();
        #pragma unroll
        for (int ks = 0; ks < 4; ks++) {
            u32 a[2][4], b[4][2];
            #pragma unroll
            for (int mt = 0; mt < 2; mt++) {
                float2 lo = *(const float2*)&sA[(wm * 32 + mt * 16 + g) * 40 + ks * 8 + 2 * t];
                float2 hi = *(const float2*)&sA[(wm * 32 + mt * 16 + g + 8) * 40 + ks * 8 + 2 * t];
                a[mt][0] = __float_as_uint(lo.x); a[mt][2] = __float_as_uint(lo.y);
                a[mt][1] = __float_as_uint(hi.x); a[mt][3] = __float_as_uint(hi.y);
            }
            #pragma unroll
            for (int nt = 0; nt < 4; nt++) {
                float2 bb = *(const float2*)&sB[(wn * 32 + nt * 8 + g) * 40 + ks * 8 + 2 * t];
                b[nt][0] = __float_as_uint(bb.x); b[nt][1] = __float_as_uint(bb.y);
            }
            #pragma unroll
            for (int mt = 0; mt < 2; mt++)
                #pragma unroll
                for (int nt = 0; nt < 4; nt++)
                    mma8(d[mt][nt], a[mt], b[nt]);
        }
        __syncthreads();
    }
    // ---- fused RMSNorm epilogue ----
    float ss0[2], ss1[2];
    #pragma unroll
    for (int mt = 0; mt < 2; mt++) {
        ss0[mt] = 0.f; ss1[mt] = 0.f;
        #pragma unroll
        for (int nt = 0; nt < 4; nt++) {
            ss0[mt] += d[mt][nt][0] * d[mt][nt][0] + d[mt][nt][1] * d[mt][nt][1];
            ss1[mt] += d[mt][nt][2] * d[mt][nt][2] + d[mt][nt][3] * d[mt][nt][3];
        }
        ss0[mt] += __shfl_xor_sync(0xffffffffu, ss0[mt], 1);
        ss0[mt] += __shfl_xor_sync(0xffffffffu, ss0[mt], 2);
        ss1[mt] += __shfl_xor_sync(0xffffffffu, ss1[mt], 1);
        ss1[mt] += __shfl_xor_sync(0xffffffffu, ss1[mt], 2);
    }
    float* ssb = sB;   // reuse: [2][128]
    if (t == 0) {
        #pragma unroll
        for (int mt = 0; mt < 2; mt++) {
            ssb[wn * 128 + wm * 32 + mt * 16 + g]     = ss0[mt];
            ssb[wn * 128 + wm * 32 + mt * 16 + g + 8] = ss1[mt];
        }
    }
    __syncthreads();
    #pragma unroll
    for (int mt = 0; mt < 2; mt++) {
        int r0 = wm * 32 + mt * 16 + g, r1 = r0 + 8;
        float inv0 = rsqrtf((ssb[r0] + ssb[128 + r0]) * (1.0f / 64.0f) + 1.1920929e-07f);
        float inv1 = rsqrtf((ssb[r1] + ssb[128 + r1]) * (1.0f / 64.0f) + 1.1920929e-07f);
        float q0 = inv0 * 0.125f * 1.44269504f;
        float q1 = inv1 * 0.125f * 1.44269504f;
        size_t a0 = (size_t)(i0 + r0) * CD + j0;
        size_t a1 = (size_t)(i0 + r1) * CD + j0;
        #pragma unroll
        for (int nt = 0; nt < 4; nt++) {
            int c = wn * 32 + nt * 8 + 2 * t;
            float G1a = sG[c], G1b = sG[c + 1];
            float G2a = sG[64 + c], G2b = sG[64 + c + 1];
            float G3a = sG[128 + c], G3b = sG[128 + c + 1];
            float v0 = d[mt][nt][0], v1 = d[mt][nt][1];
            float v2 = d[mt][nt][2], v3 = d[mt][nt][3];
            *(float2*)(g_q + a0 + c) = make_float2(tf32f(v0 * q0 * G1a), tf32f(v1 * q0 * G1b));
            *(float2*)(g_k + a0 + c) = make_float2(tf32f(v0 * inv0 * G2a), tf32f(v1 * inv0 * G2b));
            *(float2*)(g_v + a0 + c) = make_float2(tf32f(v0 * inv0 * G3a), tf32f(v1 * inv0 * G3b));
            *(float2*)(g_q + a1 + c) = make_float2(tf32f(v2 * q1 * G1a), tf32f(v3 * q1 * G1b));
            *(float2*)(g_k + a1 + c) = make_float2(tf32f(v2 * inv1 * G2a), tf32f(v3 * inv1 * G2b));
            *(float2*)(g_v + a1 + c) = make_float2(tf32f(v2 * inv1 * G3a), tf32f(v3 * inv1 * G3b));
        }
    }
}

// ================================================================ E = 2^(q@k^T) -> fp16, fused sums
#define ATT_SMEM ((128 * 72 + 64 * 72) * 4)
__global__ __launch_bounds__(256, 2) void k_att() {
    extern __shared__ __align__(16) float smd[];
    float* sq = smd;
    float* sk = smd + 128 * 72;
    const int tid = threadIdx.x;
    const int lane = tid & 31, warp = tid >> 5;
    const int wm = warp >> 1, wn = warp & 1;
    const int g = lane >> 2, t = lane & 3;
    const int bh = blockIdx.z;
    const int i0 = blockIdx.y * 128;
    const size_t base = (size_t)(bh >> 3) * TD * CD + (bh & 7) * DD;
    const float* qb = g_q + base + (size_t)i0 * CD;
    #pragma unroll
    for (int l = 0; l < 8; l++) {
        int idx = tid + l * 256;
        int rr = idx >> 4, cg = (idx & 15) * 4;
        int ch = cg >> 5, c4 = cg & 31;
        int pb = ch * 36 + (c4 & 24) + ((c4 & 4) ? 1 : 0);
        float4 v = *(const float4*)(qb + (size_t)rr * CD + cg);
        sq[rr * 72 + pb] = v.x; sq[rr * 72 + pb + 2] = v.y;
        sq[rr * 72 + pb + 4] = v.z; sq[rr * 72 + pb + 6] = v.w;
    }
    float rsum[2][2] = {};
    #pragma unroll 1
    for (int jj = 0; jj < 4; jj++) {
        int j0 = blockIdx.x * 256 + jj * 64;
        const float* kb = g_k + base + (size_t)j0 * CD;
        __syncthreads();
        #pragma unroll
        for (int l = 0; l < 4; l++) {
            int idx = tid + l * 256;
            int rr = idx >> 4, cg = (idx & 15) * 4;
            int ch = cg >> 5, c4 = cg & 31;
            int pb = ch * 36 + (c4 & 24) + ((c4 & 4) ? 1 : 0);
            float4 w = *(const float4*)(kb + (size_t)rr * CD + cg);
            sk[rr * 72 + pb] = w.x; sk[rr * 72 + pb + 2] = w.y;
            sk[rr * 72 + pb + 4] = w.z; sk[rr * 72 + pb + 6] = w.w;
        }
        __syncthreads();
        float d[2][4][4] = {};
        #pragma unroll
        for (int ch = 0; ch < 2; ch++) {
            #pragma unroll
            for (int ks = 0; ks < 4; ks++) {
                int off = ch * 36 + ks * 8 + 2 * t;
                u32 a[2][4], b[4][2];
                #pragma unroll
                for (int mt = 0; mt < 2; mt++) {
                    float2 lo = *(const float2*)&sq[(wm * 32 + mt * 16 + g) * 72 + off];
                    float2 hi = *(const float2*)&sq[(wm * 32 + mt * 16 + g + 8) * 72 + off];
                    a[mt][0] = __float_as_uint(lo.x); a[mt][2] = __float_as_uint(lo.y);
                    a[mt][1] = __float_as_uint(hi.x); a[mt][3] = __float_as_uint(hi.y);
                }
                #pragma unroll
                for (int nt = 0; nt < 4; nt++) {
                    float2 bb = *(const float2*)&sk[(wn * 32 + nt * 8 + g) * 72 + off];
                    b[nt][0] = __float_as_uint(bb.x); b[nt][1] = __float_as_uint(bb.y);
                }
                #pragma unroll
                for (int mt = 0; mt < 2; mt++)
                    #pragma unroll
                    for (int nt = 0; nt < 4; nt++)
                        mma8(d[mt][nt], a[mt], b[nt]);
            }
        }
        __half* ob = g_att + (size_t)bh * TD * TD + (size_t)i0 * TD + j0;
        float cs0[4] = {}, cs1[4] = {};
        #pragma unroll
        for (int mt = 0; mt < 2; mt++) {
            int r0 = wm * 32 + mt * 16 + g;
            #pragma unroll
            for (int nt = 0; nt < 4; nt++) {
                int col = wn * 32 + nt * 8 + 2 * t;
                __half2 h01 = __floats2half2_rn(ex2(d[mt][nt][0]), ex2(d[mt][nt][1]));
                __half2 h23 = __floats2half2_rn(ex2(d[mt][nt][2]), ex2(d[mt][nt][3]));
                *(__half2*)(ob + (size_t)r0 * TD + col)       = h01;
                *(__half2*)(ob + (size_t)(r0 + 8) * TD + col) = h23;
                float2 f01 = __half22float2(h01), f23 = __half22float2(h23);
                rsum[mt][0] += f01.x + f01.y; rsum[mt][1] += f23.x + f23.y;
                cs0[nt] += f01.x + f23.x;     cs1[nt] += f01.y + f23.y;
            }
        }
        #pragma unroll
        for (int nt = 0; nt < 4; nt++) {
            cs0[nt] += __shfl_xor_sync(0xffffffffu, cs0[nt], 4);
            cs0[nt] += __shfl_xor_sync(0xffffffffu, cs0[nt], 8);
            cs0[nt] += __shfl_xor_sync(0xffffffffu, cs0[nt], 16);
            cs1[nt] += __shfl_xor_sync(0xffffffffu, cs1[nt], 4);
            cs1[nt] += __shfl_xor_sync(0xffffffffu, cs1[nt], 8);
            cs1[nt] += __shfl_xor_sync(0xffffffffu, cs1[nt], 16);
        }
        __syncthreads();
        float* scolp = sk;
        if (g == 0) {
            #pragma unroll
            for (int nt = 0; nt < 4; nt++) {
                scolp[wm * 64 + wn * 32 + nt * 8 + 2 * t]     = cs0[nt];
                scolp[wm * 64 + wn * 32 + nt * 8 + 2 * t + 1] = cs1[nt];
            }
        }
        __syncthreads();
        if (tid < 64) {
            atomicAdd(&g_scol[bh * TD + j0 + tid],
                      scolp[tid] + scolp[64 + tid] + scolp[128 + tid] + scolp[192 + tid]);
        }
    }
    #pragma unroll
    for (int mt = 0; mt < 2; mt++)
        #pragma unroll
        for (int h = 0; h < 2; h++) {
            rsum[mt][h] += __shfl_xor_sync(0xffffffffu, rsum[mt][h], 1);
            rsum[mt][h] += __shfl_xor_sync(0xffffffffu, rsum[mt][h], 2);
        }
    __syncthreads();
    float* srowp = sk;
    if (t == 0) {
        #pragma unroll
        for (int mt = 0; mt < 2; mt++) {
            srowp[wn * 128 + wm * 32 + mt * 16 + g]     = rsum[mt][0];
            srowp[wn * 128 + wm * 32 + mt * 16 + g + 8] = rsum[mt][1];
        }
    }
    __syncthreads();
    if (tid < 128)
        atomicAdd(&g_srow[bh * TD + i0 + tid], srowp[tid] + srowp[128 + tid]);
}

// ------------------------------------------- reciprocals of sums
__global__ void k_recip() {
    int i = blockIdx.x * 256 + threadIdx.x;
    g_prow[i] = 1.0f / g_srow[i];
    g_pcol[i] = 1.0f / g_scol[i];
}

// ------------------------------------------- transpose v -> fp16 [bh][d][k]; pvt = 4096*pc*v
__global__ void k_vt() {
    int idx = blockIdx.x * 256 + threadIdx.x;   // BH*TD*16
    int kk = idx & 2047;
    int rest = idx >> 11;
    int d4 = (rest & 15) * 4;
    int bh = rest >> 4;
    size_t vbase = (size_t)(bh >> 3) * TD * CD + (bh & 7) * DD;
    float4 v = *(const float4*)(g_v + vbase + (size_t)kk * CD + d4);
    float pcs = g_pcol[bh * TD + kk] * 4096.0f;
    size_t tb = ((size_t)bh * DD + d4) * TD + kk;
    g_vt[tb]           = __float2half(v.x);
    g_vt[tb + TD]      = __float2half(v.y);
    g_vt[tb + 2 * TD]  = __float2half(v.z);
    g_vt[tb + 3 * TD]  = __float2half(v.w);
    g_pvt[tb]          = __float2half(v.x * pcs);
    g_pvt[tb + TD]     = __float2half(v.y * pcs);
    g_pvt[tb + 2 * TD] = __float2half(v.z * pcs);
    g_pvt[tb + 3 * TD] = __float2half(v.w * pcs);
}

// ================================================================ y = pr⊙(E@v) + (1/4096)·E@pcv
// fp16 m16n8k16 MMA. A = raw E fp16 (copy only); B = vt/pvt fp16 (copy only).
// k-pair perm [0,4,1,5,2,6,3,7] within 8-word blocks -> every fragment one LDS.64.
// Row stride 40 words => banks 8g+2t, conflict-free per phase.
__global__ __launch_bounds__(256, 2) void k_y() {
    __shared__ __align__(16) u32 sEw[128 * 40];
    __shared__ __align__(16) u32 sVw[64 * 40];
    __shared__ __align__(16) u32 sPw[64 * 40];
    const int tid = threadIdx.x;
    const int lane = tid & 31, warp = tid >> 5;
    const int wm = warp >> 1, wn = warp & 1;
    const int g = lane >> 2, t = lane & 3;
    const int bh = blockIdx.y;
    const int i0 = blockIdx.x * 128;
    const __half* eb  = g_att + (size_t)bh * TD * TD + (size_t)i0 * TD;
    const __half* vtb = g_vt + (size_t)bh * DD * TD;
    const __half* ptb = g_pvt + (size_t)bh * DD * TD;
    float d1[2][4][4] = {}, d2[2][4][4] = {};
    #pragma unroll 1
    for (int kc = 0; kc < 32; kc++) {
        int k0 = kc * 64;
        __syncthreads();
        // fill E tile 128x64 halves (raw copy, k-pair perm scatter)
        #pragma unroll
        for (int l = 0; l < 4; l++) {
            int idx = tid + l * 256;
            int rr = idx >> 3, c8 = (idx & 7) * 8;
            uint4 raw = *(const uint4*)(eb + (size_t)rr * TD + k0 + c8);
            u32 w[4] = {raw.x, raw.y, raw.z, raw.w};
            int p0 = (idx & 7) * 4;
            u32* dst = &sEw[rr * 40];
            #pragma unroll
            for (int j = 0; j < 4; j++) {
                int p = p0 + j;
                dst[(p & 24) + 2 * (p & 3) + ((p >> 2) & 1)] = w[j];
            }
        }
        // fill V^T and PV^T tiles 64x64 halves
        #pragma unroll
        for (int l = 0; l < 2; l++) {
            int idx = tid + l * 256;
            int rr = idx >> 3, c8 = (idx & 7) * 8;
            uint4 rv = *(const uint4*)(vtb + (size_t)rr * TD + k0 + c8);
            uint4 rp = *(const uint4*)(ptb + (size_t)rr * TD + k0 + c8);
            u32 wv[4] = {rv.x, rv.y, rv.z, rv.w};
            u32 wp[4] = {rp.x, rp.y, rp.z, rp.w};
            int p0 = (idx & 7) * 4;
            #pragma unroll
            for (int j = 0; j < 4; j++) {
                int p = p0 + j;
                int pos = (p & 24) + 2 * (p & 3) + ((p >> 2) & 1);
                sVw[rr * 40 + pos] = wv[j];
                sPw[rr * 40 + pos] = wp[j];
            }
        }
        __syncthreads();
        #pragma unroll
        for (int ks = 0; ks < 4; ks++) {
            int off = ks * 8 + 2 * t;
            uint2 alo[2], ahi[2];
            #pragma unroll
            for (int mt = 0; mt < 2; mt++) {
                int r0 = wm * 32 + mt * 16 + g;
                alo[mt] = *(const uint2*)&sEw[r0 * 40 + off];        // a0 (k 2t), a2 (k 2t+8)
                ahi[mt] = *(const uint2*)&sEw[(r0 + 8) * 40 + off];  // a1, a3
            }
            #pragma unroll
            for (int nt = 0; nt < 4; nt++) {
                int n = wn * 32 + nt * 8 + g;
                uint2 bv = *(const uint2*)&sVw[n * 40 + off];        // b0 (k 2t), b1 (k 2t+8)
                uint2 bp = *(const uint2*)&sPw[n * 40 + off];
                #pragma unroll
                for (int mt = 0; mt < 2; mt++) {
                    mma16(d1[mt][nt], alo[mt].x, ahi[mt].x, alo[mt].y, ahi[mt].y, bv.x, bv.y);
                    mma16(d2[mt][nt], alo[mt].x, ahi[mt].x, alo[mt].y, ahi[mt].y, bp.x, bp.y);
                }
            }
        }
    }
    const size_t base = (size_t)(bh >> 3) * TD * CD + (bh & 7) * DD;
    float* yb = g_y + base + (size_t)i0 * CD;
    const float isc = 1.0f / 4096.0f;
    #pragma unroll
    for (int mt = 0; mt < 2; mt++) {
        int r0 = wm * 32 + mt * 16 + g;
        float pr0 = g_prow[bh * TD + i0 + r0];
        float pr1 = g_prow[bh * TD + i0 + r0 + 8];
        #pragma unroll
        for (int nt = 0; nt < 4; nt++) {
            int col = wn * 32 + nt * 8 + 2 * t;
            *(float2*)(yb + (size_t)r0 * CD + col) =
                make_float2(pr0 * d1[mt][nt][0] + d2[mt][nt][0] * isc,
                            pr0 * d1[mt][nt][1] + d2[mt][nt][1] * isc);
            *(float2*)(yb + (size_t)(r0 + 8) * CD + col) =
                make_float2(pr1 * d1[mt][nt][2] + d2[mt][nt][2] * isc,
                            pr1 * d1[mt][nt][3] + d2[mt][nt][3] * isc);
        }
    }
}

// ================================================================ out = y @ W (NN, tf32 MMA)
__global__ __launch_bounds__(256, 2) void k_outgemm32(float* __restrict__ out) {
    __shared__ __align__(16) float sA[128 * 40];
    __shared__ __align__(16) float sB[64 * 40];
    const int tid = threadIdx.x;
    const int lane = tid & 31, warp = tid >> 5;
    const int wm = warp >> 1, wn = warp & 1;
    const int g = lane >> 2, t = lane & 3;
    const int i0 = blockIdx.y * 128, j0 = blockIdx.x * 64;
    const float* Ab = g_y + (size_t)i0 * CD;
    float d[2][4][4] = {};
    #pragma unroll 1
    for (int kc = 0; kc < 16; kc++) {
        int k0 = kc * 32;
        #pragma unroll
        for (int l = 0; l < 4; l++) {
            int idx = tid + l * 256;
            int rr = idx >> 3, c4 = (idx & 7) * 4;
            int pbase = (c4 & 24) + ((c4 & 4) ? 1 : 0);
            float4 v = *(const float4*)(Ab + (size_t)rr * CD + k0 + c4);
            sA[rr * 40 + pbase] = tf32f(v.x); sA[rr * 40 + pbase + 2] = tf32f(v.y);
            sA[rr * 40 + pbase + 4] = tf32f(v.z); sA[rr * 40 + pbase + 6] = tf32f(v.w);
        }
        #pragma unroll
        for (int l = 0; l < 2; l++) {
            int idx = tid + l * 256;
            int kk = idx >> 4, j4 = (idx & 15) * 4;
            float4 wv = *(const float4*)(g_W + (size_t)(k0 + kk) * CD + j0 + j4);
            int pk = (kk & 24) + 2 * (kk & 3) + ((kk >> 2) & 1);
            sB[(j4 + 0) * 40 + pk] = tf32f(wv.x);
            sB[(j4 + 1) * 40 + pk] = tf32f(wv.y);
            sB[(j4 + 2) * 40 + pk] = tf32f(wv.z);
            sB[(j4 + 3) * 40 + pk] = tf32f(wv.w);
        }
        __syncthreads();
        #pragma unroll
        for (int ks = 0; ks < 4; ks++) {
            u32 a[2][4], b[4][2];
            #pragma unroll
            for (int mt = 0; mt < 2; mt++) {
                float2 lo = *(const float2*)&sA[(wm * 32 + mt * 16 + g) * 40 + ks * 8 + 2 * t];
                float2 hi = *(const float2*)&sA[(wm * 32 + mt * 16 + g + 8) * 40 + ks * 8 + 2 * t];
                a[mt][0] = __float_as_uint(lo.x); a[mt][2] = __float_as_uint(lo.y);
                a[mt][1] = __float_as_uint(hi.x); a[mt][3] = __float_as_uint(hi.y);
            }
            #pragma unroll
            for (int nt = 0; nt < 4; nt++) {
                float2 bb = *(const float2*)&sB[(wn * 32 + nt * 8 + g) * 40 + ks * 8 + 2 * t];
                b[nt][0] = __float_as_uint(bb.x); b[nt][1] = __float_as_uint(bb.y);
            }
            #pragma unroll
            for (int mt = 0; mt < 2; mt++)
                #pragma unroll
                for (int nt = 0; nt < 4; nt++)
                    mma8(d[mt][nt], a[mt], b[nt]);
        }
        __syncthreads();
    }
    float* Cb = out + (size_t)i0 * CD + j0;
    #pragma unroll
    for (int mt = 0; mt < 2; mt++) {
        int r0 = wm * 32 + mt * 16 + g;
        #pragma unroll
        for (int nt = 0; nt < 4; nt++) {
            int col = wn * 32 + nt * 8 + 2 * t;
            *(float2*)(Cb + (size_t)r0 * CD + col)       = make_float2(d[mt][nt][0], d[mt][nt][1]);
            *(float2*)(Cb + (size_t)(r0 + 8) * CD + col) = make_float2(d[mt][nt][2], d[mt][nt][3]);
        }
    }
}

extern "C" void kernel_launch(void* const* d_in, const int* in_sizes, int n_in,
                              void* d_out, int out_size) {
    (void)in_sizes; (void)n_in; (void)out_size;
    const float* x  = (const float*)d_in[0];
    const float* dw = (const float*)d_in[1];
    const float* qw = (const float*)d_in[2];
    const float* g1 = (const float*)d_in[3];
    const float* g2 = (const float*)d_in[4];
    const float* g3 = (const float*)d_in[5];
    float* out = (float*)d_out;

    static int init_done = 0;
    if (!init_done) {
        cudaFuncSetAttribute(k_att, cudaFuncAttributeMaxDynamicSharedMemorySize, ATT_SMEM);
        init_done = 1;
    }

    float *ps, *pc;
    cudaGetSymbolAddress((void**)&ps, g_srow);
    cudaGetSymbolAddress((void**)&pc, g_scol);
    cudaMemsetAsync(ps, 0, BH * TD * sizeof(float));
    cudaMemsetAsync(pc, 0, BH * TD * sizeof(float));

    k_addw<<<(CD * CD) / 256, 256>>>(dw, qw);
    k_wnorm<<<dim3(CD / 64, RWS / 128), 256>>>(x, g1, g2, g3);
    k_att<<<dim3(TD / 256, TD / 128, BH), 256, ATT_SMEM>>>();
    k_recip<<<(BH * TD) / 256, 256>>>();
    k_vt<<<(BH * TD * 16) / 256, 256>>>();
    k_y<<<dim3(TD / 128, BH), 256>>>();
    k_outgemm32<<<dim3(CD / 64, RWS / 128), 256>>>(out);
}

// round 11
// speedup vs baseline: 1.7046x; 1.0776x over previous
#include <cuda_runtime.h>
#include <cuda_fp16.h>

#define TD 2048
#define CD 512
#define DD 64
#define BH 32
#define RWS 8192

typedef unsigned long long u64;
typedef unsigned int u32;

// ---------------- scratch ----------------
__device__ float g_W[CD * CD];
__device__ __half g_qh[RWS * CD];  // fp16, scaled by inv*0.125*log2e
__device__ __half g_kh[RWS * CD];  // fp16
__device__ float g_v[RWS * CD];    // tf32-rounded fp32 (for k_vt)
__device__ __half g_att[(size_t)BH * TD * TD];  // exp(att) fp16
__device__ __half g_vt[(size_t)BH * DD * TD];   // v transposed [bh][d][k], fp16
__device__ __half g_pvt[(size_t)BH * DD * TD];  // 4096*pc*v transposed, fp16
__device__ float g_srow[BH * TD];
__device__ float g_scol[BH * TD];
__device__ float g_prow[BH * TD];
__device__ float g_pcol[BH * TD];
__device__ float g_y[RWS * CD];

// ---------------- helpers ----------------
__device__ __forceinline__ u32 tf32c(float f) {
    u32 r; asm("cvt.rna.tf32.f32 %0, %1;" : "=r"(r) : "f"(f)); return r;
}
__device__ __forceinline__ float tf32f(float f) { return __uint_as_float(tf32c(f)); }
__device__ __forceinline__ float ex2(float x) {
    float y; asm("ex2.approx.f32 %0, %1;" : "=f"(y) : "f"(x)); return y;
}
__device__ __forceinline__ void mma8(float* d, const u32* a, const u32* b) {
    asm("mma.sync.aligned.m16n8k8.row.col.f32.tf32.tf32.f32 "
        "{%0,%1,%2,%3},{%4,%5,%6,%7},{%8,%9},{%0,%1,%2,%3};"
        : "+f"(d[0]), "+f"(d[1]), "+f"(d[2]), "+f"(d[3])
        : "r"(a[0]), "r"(a[1]), "r"(a[2]), "r"(a[3]), "r"(b[0]), "r"(b[1]));
}
__device__ __forceinline__ void mma16(float* d, u32 a0, u32 a1, u32 a2, u32 a3,
                                      u32 b0, u32 b1) {
    asm("mma.sync.aligned.m16n8k16.row.col.f32.f16.f16.f32 "
        "{%0,%1,%2,%3},{%4,%5,%6,%7},{%8,%9},{%0,%1,%2,%3};"
        : "+f"(d[0]), "+f"(d[1]), "+f"(d[2]), "+f"(d[3])
        : "r"(a0), "r"(a1), "r"(a2), "r"(a3), "r"(b0), "r"(b1));
}

// ---------------------------------------------------------------- W = dw + qw
__global__ void k_addw(const float* __restrict__ dw, const float* __restrict__ qw) {
    int i = blockIdx.x * 256 + threadIdx.x;
    g_W[i] = dw[i] + qw[i];
}

// ================================================================ fused: w = x@W^T (one head tile)
// + RMSNorm epilogue -> q (fp16, scaled), k (fp16), v (tf32 fp32). 128x64 tile.
__global__ __launch_bounds__(256, 2) void k_wnorm(const float* __restrict__ x,
                                                  const float* __restrict__ gg1,
                                                  const float* __restrict__ gg2,
                                                  const float* __restrict__ gg3) {
    __shared__ __align__(16) float sA[128 * 40];
    __shared__ __align__(16) float sB[64 * 40];
    __shared__ float sG[192];
    const int tid = threadIdx.x;
    const int lane = tid & 31, warp = tid >> 5;
    const int wm = warp >> 1, wn = warp & 1;
    const int g = lane >> 2, t = lane & 3;
    const int i0 = blockIdx.y * 128, j0 = blockIdx.x * 64;
    if (tid < 64) sG[tid] = gg1[tid];
    else if (tid < 128) sG[tid] = gg2[tid - 64];
    else if (tid < 192) sG[tid] = gg3[tid - 128];
    const float* Ab = x + (size_t)i0 * CD;
    const float* Bb = g_W + (size_t)j0 * CD;
    float d[2][4][4] = {};
    #pragma unroll 1
    for (int kc = 0; kc < 16; kc++) {
        int k0 = kc * 32;
        #pragma unroll
        for (int l = 0; l < 4; l++) {
            int idx = tid + l * 256;
            int rr = idx >> 3, c4 = (idx & 7) * 4;
            int pbase = (c4 & 24) + ((c4 & 4) ? 1 : 0);
            float4 v = *(const float4*)(Ab + (size_t)rr * CD + k0 + c4);
            sA[rr * 40 + pbase] = tf32f(v.x); sA[rr * 40 + pbase + 2] = tf32f(v.y);
            sA[rr * 40 + pbase + 4] = tf32f(v.z); sA[rr * 40 + pbase + 6] = tf32f(v.w);
        }
        #pragma unroll
        for (int l = 0; l < 2; l++) {
            int idx = tid + l * 256;
            int rr = idx >> 3, c4 = (idx & 7) * 4;
            int pbase = (c4 & 24) + ((c4 & 4) ? 1 : 0);
            float4 w = *(const float4*)(Bb + (size_t)rr * CD + k0 + c4);
            sB[rr * 40 + pbase] = tf32f(w.x); sB[rr * 40 + pbase + 2] = tf32f(w.y);
            sB[rr * 40 + pbase + 4] = tf32f(w.z); sB[rr * 40 + pbase + 6] = tf32f(w.w);
        }
        __syncthreads();
        #pragma unroll
        for (int ks = 0; ks < 4; ks++) {
            u32 a[2][4], b[4][2];
            #pragma unroll
            for (int mt = 0; mt < 2; mt++) {
                float2 lo = *(const float2*)&sA[(wm * 32 + mt * 16 + g) * 40 + ks * 8 + 2 * t];
                float2 hi = *(const float2*)&sA[(wm * 32 + mt * 16 + g + 8) * 40 + ks * 8 + 2 * t];
                a[mt][0] = __float_as_uint(lo.x); a[mt][2] = __float_as_uint(lo.y);
                a[mt][1] = __float_as_uint(hi.x); a[mt][3] = __float_as_uint(hi.y);
            }
            #pragma unroll
            for (int nt = 0; nt < 4; nt++) {
                float2 bb = *(const float2*)&sB[(wn * 32 + nt * 8 + g) * 40 + ks * 8 + 2 * t];
                b[nt][0] = __float_as_uint(bb.x); b[nt][1] = __float_as_uint(bb.y);
            }
            #pragma unroll
            for (int mt = 0; mt < 2; mt++)
                #pragma unroll
                for (int nt = 0; nt < 4; nt++)
                    mma8(d[mt][nt], a[mt], b[nt]);
        }
        __syncthreads();
    }
    // ---- fused RMSNorm epilogue ----
    float ss0[2], ss1[2];
    #pragma unroll
    for (int mt = 0; mt < 2; mt++) {
        ss0[mt] = 0.f; ss1[mt] = 0.f;
        #pragma unroll
        for (int nt = 0; nt < 4; nt++) {
            ss0[mt] += d[mt][nt][0] * d[mt][nt][0] + d[mt][nt][1] * d[mt][nt][1];
            ss1[mt] += d[mt][nt][2] * d[mt][nt][2] + d[mt][nt][3] * d[mt][nt][3];
        }
        ss0[mt] += __shfl_xor_sync(0xffffffffu, ss0[mt], 1);
        ss0[mt] += __shfl_xor_sync(0xffffffffu, ss0[mt], 2);
        ss1[mt] += __shfl_xor_sync(0xffffffffu, ss1[mt], 1);
        ss1[mt] += __shfl_xor_sync(0xffffffffu, ss1[mt], 2);
    }
    float* ssb = sB;   // reuse: [2][128]
    if (t == 0) {
        #pragma unroll
        for (int mt = 0; mt < 2; mt++) {
            ssb[wn * 128 + wm * 32 + mt * 16 + g]     = ss0[mt];
            ssb[wn * 128 + wm * 32 + mt * 16 + g + 8] = ss1[mt];
        }
    }
    __syncthreads();
    #pragma unroll
    for (int mt = 0; mt < 2; mt++) {
        int r0 = wm * 32 + mt * 16 + g, r1 = r0 + 8;
        float inv0 = rsqrtf((ssb[r0] + ssb[128 + r0]) * (1.0f / 64.0f) + 1.1920929e-07f);
        float inv1 = rsqrtf((ssb[r1] + ssb[128 + r1]) * (1.0f / 64.0f) + 1.1920929e-07f);
        float q0 = inv0 * 0.125f * 1.44269504f;
        float q1 = inv1 * 0.125f * 1.44269504f;
        size_t a0 = (size_t)(i0 + r0) * CD + j0;
        size_t a1 = (size_t)(i0 + r1) * CD + j0;
        #pragma unroll
        for (int nt = 0; nt < 4; nt++) {
            int c = wn * 32 + nt * 8 + 2 * t;
            float G1a = sG[c], G1b = sG[c + 1];
            float G2a = sG[64 + c], G2b = sG[64 + c + 1];
            float G3a = sG[128 + c], G3b = sG[128 + c + 1];
            float v0 = d[mt][nt][0], v1 = d[mt][nt][1];
            float v2 = d[mt][nt][2], v3 = d[mt][nt][3];
            *(__half2*)(g_qh + a0 + c) = __floats2half2_rn(v0 * q0 * G1a, v1 * q0 * G1b);
            *(__half2*)(g_kh + a0 + c) = __floats2half2_rn(v0 * inv0 * G2a, v1 * inv0 * G2b);
            *(float2*)(g_v + a0 + c) = make_float2(tf32f(v0 * inv0 * G3a), tf32f(v1 * inv0 * G3b));
            *(__half2*)(g_qh + a1 + c) = __floats2half2_rn(v2 * q1 * G1a, v3 * q1 * G1b);
            *(__half2*)(g_kh + a1 + c) = __floats2half2_rn(v2 * inv1 * G2a, v3 * inv1 * G2b);
            *(float2*)(g_v + a1 + c) = make_float2(tf32f(v2 * inv1 * G3a), tf32f(v3 * inv1 * G3b));
        }
    }
}

// ================================================================ E = 2^(q@k^T) -> fp16, fused sums
// fp16 m16n8k16 MMA; q tile resident across 4 j-subtiles. k-pair perm, stride 40 u32.
__global__ __launch_bounds__(256, 2) void k_att() {
    __shared__ __align__(16) u32 sq[128 * 40];
    __shared__ __align__(16) u32 sk[64 * 40];
    const int tid = threadIdx.x;
    const int lane = tid & 31, warp = tid >> 5;
    const int wm = warp >> 1, wn = warp & 1;
    const int g = lane >> 2, t = lane & 3;
    const int bh = blockIdx.z;
    const int i0 = blockIdx.y * 128;
    const size_t base = (size_t)(bh >> 3) * TD * CD + (bh & 7) * DD;
    const __half* qb = g_qh + base + (size_t)i0 * CD;
    // fill q tile 128x64 halves (raw copy, k-pair perm scatter)
    #pragma unroll
    for (int l = 0; l < 4; l++) {
        int idx = tid + l * 256;
        int rr = idx >> 3, c8 = (idx & 7) * 8;
        uint4 raw = *(const uint4*)(qb + (size_t)rr * CD + c8);
        u32 w[4] = {raw.x, raw.y, raw.z, raw.w};
        int p0 = (idx & 7) * 4;
        u32* dst = &sq[rr * 40];
        #pragma unroll
        for (int j = 0; j < 4; j++) {
            int p = p0 + j;
            dst[(p & 24) + 2 * (p & 3) + ((p >> 2) & 1)] = w[j];
        }
    }
    float rsum[2][2] = {};
    #pragma unroll 1
    for (int jj = 0; jj < 4; jj++) {
        int j0 = blockIdx.x * 256 + jj * 64;
        const __half* kb = g_kh + base + (size_t)j0 * CD;
        __syncthreads();
        #pragma unroll
        for (int l = 0; l < 2; l++) {
            int idx = tid + l * 256;
            int rr = idx >> 3, c8 = (idx & 7) * 8;
            uint4 raw = *(const uint4*)(kb + (size_t)rr * CD + c8);
            u32 w[4] = {raw.x, raw.y, raw.z, raw.w};
            int p0 = (idx & 7) * 4;
            u32* dst = &sk[rr * 40];
            #pragma unroll
            for (int j = 0; j < 4; j++) {
                int p = p0 + j;
                dst[(p & 24) + 2 * (p & 3) + ((p >> 2) & 1)] = w[j];
            }
        }
        __syncthreads();
        float d[2][4][4] = {};
        #pragma unroll
        for (int ks = 0; ks < 4; ks++) {
            int off = ks * 8 + 2 * t;
            uint2 alo[2], ahi[2];
            #pragma unroll
            for (int mt = 0; mt < 2; mt++) {
                int r0 = wm * 32 + mt * 16 + g;
                alo[mt] = *(const uint2*)&sq[r0 * 40 + off];
                ahi[mt] = *(const uint2*)&sq[(r0 + 8) * 40 + off];
            }
            #pragma unroll
            for (int nt = 0; nt < 4; nt++) {
                int n = wn * 32 + nt * 8 + g;
                uint2 bb = *(const uint2*)&sk[n * 40 + off];
                #pragma unroll
                for (int mt = 0; mt < 2; mt++)
                    mma16(d[mt][nt], alo[mt].x, ahi[mt].x, alo[mt].y, ahi[mt].y, bb.x, bb.y);
            }
        }
        // epilogue: exp2 -> fp16, store; sums of the SAME fp16-rounded values
        __half* ob = g_att + (size_t)bh * TD * TD + (size_t)i0 * TD + j0;
        float cs0[4] = {}, cs1[4] = {};
        #pragma unroll
        for (int mt = 0; mt < 2; mt++) {
            int r0 = wm * 32 + mt * 16 + g;
            #pragma unroll
            for (int nt = 0; nt < 4; nt++) {
                int col = wn * 32 + nt * 8 + 2 * t;
                __half2 h01 = __floats2half2_rn(ex2(d[mt][nt][0]), ex2(d[mt][nt][1]));
                __half2 h23 = __floats2half2_rn(ex2(d[mt][nt][2]), ex2(d[mt][nt][3]));
                *(__half2*)(ob + (size_t)r0 * TD + col)       = h01;
                *(__half2*)(ob + (size_t)(r0 + 8) * TD + col) = h23;
                float2 f01 = __half22float2(h01), f23 = __half22float2(h23);
                rsum[mt][0] += f01.x + f01.y; rsum[mt][1] += f23.x + f23.y;
                cs0[nt] += f01.x + f23.x;     cs1[nt] += f01.y + f23.y;
            }
        }
        #pragma unroll
        for (int nt = 0; nt < 4; nt++) {
            cs0[nt] += __shfl_xor_sync(0xffffffffu, cs0[nt], 4);
            cs0[nt] += __shfl_xor_sync(0xffffffffu, cs0[nt], 8);
            cs0[nt] += __shfl_xor_sync(0xffffffffu, cs0[nt], 16);
            cs1[nt] += __shfl_xor_sync(0xffffffffu, cs1[nt], 4);
            cs1[nt] += __shfl_xor_sync(0xffffffffu, cs1[nt], 8);
            cs1[nt] += __shfl_xor_sync(0xffffffffu, cs1[nt], 16);
        }
        __syncthreads();
        float* scolp = (float*)sk;   // [4][64]
        if (g == 0) {
            #pragma unroll
            for (int nt = 0; nt < 4; nt++) {
                scolp[wm * 64 + wn * 32 + nt * 8 + 2 * t]     = cs0[nt];
                scolp[wm * 64 + wn * 32 + nt * 8 + 2 * t + 1] = cs1[nt];
            }
        }
        __syncthreads();
        if (tid < 64) {
            atomicAdd(&g_scol[bh * TD + j0 + tid],
                      scolp[tid] + scolp[64 + tid] + scolp[128 + tid] + scolp[192 + tid]);
        }
    }
    #pragma unroll
    for (int mt = 0; mt < 2; mt++)
        #pragma unroll
        for (int h = 0; h < 2; h++) {
            rsum[mt][h] += __shfl_xor_sync(0xffffffffu, rsum[mt][h], 1);
            rsum[mt][h] += __shfl_xor_sync(0xffffffffu, rsum[mt][h], 2);
        }
    __syncthreads();
    float* srowp = (float*)sk;       // [2][128]
    if (t == 0) {
        #pragma unroll
        for (int mt = 0; mt < 2; mt++) {
            srowp[wn * 128 + wm * 32 + mt * 16 + g]     = rsum[mt][0];
            srowp[wn * 128 + wm * 32 + mt * 16 + g + 8] = rsum[mt][1];
        }
    }
    __syncthreads();
    if (tid < 128)
        atomicAdd(&g_srow[bh * TD + i0 + tid], srowp[tid] + srowp[128 + tid]);
}

// ------------------------------------------- reciprocals of sums
__global__ void k_recip() {
    int i = blockIdx.x * 256 + threadIdx.x;
    g_prow[i] = 1.0f / g_srow[i];
    g_pcol[i] = 1.0f / g_scol[i];
}

// ------------------------------------------- transpose v -> fp16 [bh][d][k]; pvt = 4096*pc*v
__global__ void k_vt() {
    int idx = blockIdx.x * 256 + threadIdx.x;   // BH*TD*16
    int kk = idx & 2047;
    int rest = idx >> 11;
    int d4 = (rest & 15) * 4;
    int bh = rest >> 4;
    size_t vbase = (size_t)(bh >> 3) * TD * CD + (bh & 7) * DD;
    float4 v = *(const float4*)(g_v + vbase + (size_t)kk * CD + d4);
    float pcs = g_pcol[bh * TD + kk] * 4096.0f;
    size_t tb = ((size_t)bh * DD + d4) * TD + kk;
    g_vt[tb]           = __float2half(v.x);
    g_vt[tb + TD]      = __float2half(v.y);
    g_vt[tb + 2 * TD]  = __float2half(v.z);
    g_vt[tb + 3 * TD]  = __float2half(v.w);
    g_pvt[tb]          = __float2half(v.x * pcs);
    g_pvt[tb + TD]     = __float2half(v.y * pcs);
    g_pvt[tb + 2 * TD] = __float2half(v.z * pcs);
    g_pvt[tb + 3 * TD] = __float2half(v.w * pcs);
}

// ================================================================ y = pr⊙(E@v) + (1/4096)·E@pcv
__global__ __launch_bounds__(256, 2) void k_y() {
    __shared__ __align__(16) u32 sEw[128 * 40];
    __shared__ __align__(16) u32 sVw[64 * 40];
    __shared__ __align__(16) u32 sPw[64 * 40];
    const int tid = threadIdx.x;
    const int lane = tid & 31, warp = tid >> 5;
    const int wm = warp >> 1, wn = warp & 1;
    const int g = lane >> 2, t = lane & 3;
    const int bh = blockIdx.y;
    const int i0 = blockIdx.x * 128;
    const __half* eb  = g_att + (size_t)bh * TD * TD + (size_t)i0 * TD;
    const __half* vtb = g_vt + (size_t)bh * DD * TD;
    const __half* ptb = g_pvt + (size_t)bh * DD * TD;
    float d1[2][4][4] = {}, d2[2][4][4] = {};
    #pragma unroll 1
    for (int kc = 0; kc < 32; kc++) {
        int k0 = kc * 64;
        __syncthreads();
        #pragma unroll
        for (int l = 0; l < 4; l++) {
            int idx = tid + l * 256;
            int rr = idx >> 3, c8 = (idx & 7) * 8;
            uint4 raw = *(const uint4*)(eb + (size_t)rr * TD + k0 + c8);
            u32 w[4] = {raw.x, raw.y, raw.z, raw.w};
            int p0 = (idx & 7) * 4;
            u32* dst = &sEw[rr * 40];
            #pragma unroll
            for (int j = 0; j < 4; j++) {
                int p = p0 + j;
                dst[(p & 24) + 2 * (p & 3) + ((p >> 2) & 1)] = w[j];
            }
        }
        #pragma unroll
        for (int l = 0; l < 2; l++) {
            int idx = tid + l * 256;
            int rr = idx >> 3, c8 = (idx & 7) * 8;
            uint4 rv = *(const uint4*)(vtb + (size_t)rr * TD + k0 + c8);
            uint4 rp = *(const uint4*)(ptb + (size_t)rr * TD + k0 + c8);
            u32 wv[4] = {rv.x, rv.y, rv.z, rv.w};
            u32 wp[4] = {rp.x, rp.y, rp.z, rp.w};
            int p0 = (idx & 7) * 4;
            #pragma unroll
            for (int j = 0; j < 4; j++) {
                int p = p0 + j;
                int pos = (p & 24) + 2 * (p & 3) + ((p >> 2) & 1);
                sVw[rr * 40 + pos] = wv[j];
                sPw[rr * 40 + pos] = wp[j];
            }
        }
        __syncthreads();
        #pragma unroll
        for (int ks = 0; ks < 4; ks++) {
            int off = ks * 8 + 2 * t;
            uint2 alo[2], ahi[2];
            #pragma unroll
            for (int mt = 0; mt < 2; mt++) {
                int r0 = wm * 32 + mt * 16 + g;
                alo[mt] = *(const uint2*)&sEw[r0 * 40 + off];
                ahi[mt] = *(const uint2*)&sEw[(r0 + 8) * 40 + off];
            }
            #pragma unroll
            for (int nt = 0; nt < 4; nt++) {
                int n = wn * 32 + nt * 8 + g;
                uint2 bv = *(const uint2*)&sVw[n * 40 + off];
                uint2 bp = *(const uint2*)&sPw[n * 40 + off];
                #pragma unroll
                for (int mt = 0; mt < 2; mt++) {
                    mma16(d1[mt][nt], alo[mt].x, ahi[mt].x, alo[mt].y, ahi[mt].y, bv.x, bv.y);
                    mma16(d2[mt][nt], alo[mt].x, ahi[mt].x, alo[mt].y, ahi[mt].y, bp.x, bp.y);
                }
            }
        }
    }
    const size_t base = (size_t)(bh >> 3) * TD * CD + (bh & 7) * DD;
    float* yb = g_y + base + (size_t)i0 * CD;
    const float isc = 1.0f / 4096.0f;
    #pragma unroll
    for (int mt = 0; mt < 2; mt++) {
        int r0 = wm * 32 + mt * 16 + g;
        float pr0 = g_prow[bh * TD + i0 + r0];
        float pr1 = g_prow[bh * TD + i0 + r0 + 8];
        #pragma unroll
        for (int nt = 0; nt < 4; nt++) {
            int col = wn * 32 + nt * 8 + 2 * t;
            *(float2*)(yb + (size_t)r0 * CD + col) =
                make_float2(pr0 * d1[mt][nt][0] + d2[mt][nt][0] * isc,
                            pr0 * d1[mt][nt][1] + d2[mt][nt][1] * isc);
            *(float2*)(yb + (size_t)(r0 + 8) * CD + col) =
                make_float2(pr1 * d1[mt][nt][2] + d2[mt][nt][2] * isc,
                            pr1 * d1[mt][nt][3] + d2[mt][nt][3] * isc);
        }
    }
}

// ================================================================ out = y @ W (NN, tf32 MMA)
__global__ __launch_bounds__(256, 2) void k_outgemm32(float* __restrict__ out) {
    __shared__ __align__(16) float sA[128 * 40];
    __shared__ __align__(16) float sB[64 * 40];
    const int tid = threadIdx.x;
    const int lane = tid & 31, warp = tid >> 5;
    const int wm = warp >> 1, wn = warp & 1;
    const int g = lane >> 2, t = lane & 3;
    const int i0 = blockIdx.y * 128, j0 = blockIdx.x * 64;
    const float* Ab = g_y + (size_t)i0 * CD;
    float d[2][4][4] = {};
    #pragma unroll 1
    for (int kc = 0; kc < 16; kc++) {
        int k0 = kc * 32;
        #pragma unroll
        for (int l = 0; l < 4; l++) {
            int idx = tid + l * 256;
            int rr = idx >> 3, c4 = (idx & 7) * 4;
            int pbase = (c4 & 24) + ((c4 & 4) ? 1 : 0);
            float4 v = *(const float4*)(Ab + (size_t)rr * CD + k0 + c4);
            sA[rr * 40 + pbase] = tf32f(v.x); sA[rr * 40 + pbase + 2] = tf32f(v.y);
            sA[rr * 40 + pbase + 4] = tf32f(v.z); sA[rr * 40 + pbase + 6] = tf32f(v.w);
        }
        #pragma unroll
        for (int l = 0; l < 2; l++) {
            int idx = tid + l * 256;
            int kk = idx >> 4, j4 = (idx & 15) * 4;
            float4 wv = *(const float4*)(g_W + (size_t)(k0 + kk) * CD + j0 + j4);
            int pk = (kk & 24) + 2 * (kk & 3) + ((kk >> 2) & 1);
            sB[(j4 + 0) * 40 + pk] = tf32f(wv.x);
            sB[(j4 + 1) * 40 + pk] = tf32f(wv.y);
            sB[(j4 + 2) * 40 + pk] = tf32f(wv.z);
            sB[(j4 + 3) * 40 + pk] = tf32f(wv.w);
        }
        __syncthreads();
        #pragma unroll
        for (int ks = 0; ks < 4; ks++) {
            u32 a[2][4], b[4][2];
            #pragma unroll
            for (int mt = 0; mt < 2; mt++) {
                float2 lo = *(const float2*)&sA[(wm * 32 + mt * 16 + g) * 40 + ks * 8 + 2 * t];
                float2 hi = *(const float2*)&sA[(wm * 32 + mt * 16 + g + 8) * 40 + ks * 8 + 2 * t];
                a[mt][0] = __float_as_uint(lo.x); a[mt][2] = __float_as_uint(lo.y);
                a[mt][1] = __float_as_uint(hi.x); a[mt][3] = __float_as_uint(hi.y);
            }
            #pragma unroll
            for (int nt = 0; nt < 4; nt++) {
                float2 bb = *(const float2*)&sB[(wn * 32 + nt * 8 + g) * 40 + ks * 8 + 2 * t];
                b[nt][0] = __float_as_uint(bb.x); b[nt][1] = __float_as_uint(bb.y);
            }
            #pragma unroll
            for (int mt = 0; mt < 2; mt++)
                #pragma unroll
                for (int nt = 0; nt < 4; nt++)
                    mma8(d[mt][nt], a[mt], b[nt]);
        }
        __syncthreads();
    }
    float* Cb = out + (size_t)i0 * CD + j0;
    #pragma unroll
    for (int mt = 0; mt < 2; mt++) {
        int r0 = wm * 32 + mt * 16 + g;
        #pragma unroll
        for (int nt = 0; nt < 4; nt++) {
            int col = wn * 32 + nt * 8 + 2 * t;
            *(float2*)(Cb + (size_t)r0 * CD + col)       = make_float2(d[mt][nt][0], d[mt][nt][1]);
            *(float2*)(Cb + (size_t)(r0 + 8) * CD + col) = make_float2(d[mt][nt][2], d[mt][nt][3]);
        }
    }
}

extern "C" void kernel_launch(void* const* d_in, const int* in_sizes, int n_in,
                              void* d_out, int out_size) {
    (void)in_sizes; (void)n_in; (void)out_size;
    const float* x  = (const float*)d_in[0];
    const float* dw = (const float*)d_in[1];
    const float* qw = (const float*)d_in[2];
    const float* g1 = (const float*)d_in[3];
    const float* g2 = (const float*)d_in[4];
    const float* g3 = (const float*)d_in[5];
    float* out = (float*)d_out;

    float *ps, *pc;
    cudaGetSymbolAddress((void**)&ps, g_srow);
    cudaGetSymbolAddress((void**)&pc, g_scol);
    cudaMemsetAsync(ps, 0, BH * TD * sizeof(float));
    cudaMemsetAsync(pc, 0, BH * TD * sizeof(float));

    k_addw<<<(CD * CD) / 256, 256>>>(dw, qw);
    k_wnorm<<<dim3(CD / 64, RWS / 128), 256>>>(x, g1, g2, g3);
    k_att<<<dim3(TD / 256, TD / 128, BH), 256>>>();
    k_recip<<<(BH * TD) / 256, 256>>>();
    k_vt<<<(BH * TD * 16) / 256, 256>>>();
    k_y<<<dim3(TD / 128, BH), 256>>>();
    k_outgemm32<<<dim3(CD / 64, RWS / 128), 256>>>(out);
}

// round 13
// speedup vs baseline: 2.0174x; 1.1835x over previous
#include <cuda_runtime.h>
#include <cuda_fp16.h>

#define TD 2048
#define CD 512
#define DD 64
#define BH 32
#define RWS 8192

typedef unsigned int u32;

// ---------------- scratch ----------------
__device__ __half g_Wh[CD * CD];   // W fp16, [j][k] native (for wgemm B)
__device__ __half g_Wt[CD * CD];   // W^T fp16, [j][k] (for outgemm B)
__device__ __half g_qh[RWS * CD];  // fp16, scaled by inv*0.125*log2e
__device__ __half g_kh[RWS * CD];  // fp16
__device__ __half g_vh[RWS * CD];  // fp16
__device__ __half g_att[(size_t)BH * TD * TD];  // exp(att) fp16
__device__ __half g_vt[(size_t)BH * DD * TD];   // v transposed [bh][d][k], fp16
__device__ __half g_pvt[(size_t)BH * DD * TD];  // 4096*pc*v transposed, fp16
__device__ __half g_yh[RWS * CD];  // y fp16
__device__ float g_srow[BH * TD];
__device__ float g_scol[BH * TD];
__device__ float g_prow[BH * TD];
__device__ float g_pcol[BH * TD];

// ---------------- helpers ----------------
__device__ __forceinline__ float ex2(float x) {
    float y; asm("ex2.approx.f32 %0, %1;" : "=f"(y) : "f"(x)); return y;
}
__device__ __forceinline__ u32 h2u(__half2 h) {
    u32 r; memcpy(&r, &h, 4); return r;
}
__device__ __forceinline__ void mma16(float* d, u32 a0, u32 a1, u32 a2, u32 a3,
                                      u32 b0, u32 b1) {
    asm("mma.sync.aligned.m16n8k16.row.col.f32.f16.f16.f32 "
        "{%0,%1,%2,%3},{%4,%5,%6,%7},{%8,%9},{%0,%1,%2,%3};"
        : "+f"(d[0]), "+f"(d[1]), "+f"(d[2]), "+f"(d[3])
        : "r"(a0), "r"(a1), "r"(a2), "r"(a3), "r"(b0), "r"(b1));
}
// k-pair perm position within 8-word block: [0,4,1,5,2,6,3,7]
__device__ __forceinline__ int pperm(int p) {
    return (p & 24) + 2 * (p & 3) + ((p >> 2) & 1);
}

// ---------------------------------------------------------------- W -> fp16 native + transposed
__global__ void k_addw(const float* __restrict__ dw, const float* __restrict__ qw) {
    int i = blockIdx.x * 256 + threadIdx.x;
    float val = dw[i] + qw[i];
    __half h = __float2half(val);
    g_Wh[i] = h;                              // [r][c] native
    g_Wt[(i & 511) * CD + (i >> 9)] = h;      // transposed
}

// ================================================================ fused: w = x@W^T (fp16 MMA)
// + RMSNorm epilogue -> q (fp16 scaled), k (fp16), v (fp16). 128x64 tile, K-chunks of 64.
__global__ __launch_bounds__(256, 2) void k_wnorm(const float* __restrict__ x,
                                                  const float* __restrict__ gg1,
                                                  const float* __restrict__ gg2,
                                                  const float* __restrict__ gg3) {
    __shared__ __align__(16) u32 sA[128 * 40];
    __shared__ __align__(16) u32 sB[64 * 40];
    __shared__ float sG[192];
    const int tid = threadIdx.x;
    const int lane = tid & 31, warp = tid >> 5;
    const int wm = warp >> 1, wn = warp & 1;
    const int g = lane >> 2, t = lane & 3;
    const int i0 = blockIdx.y * 128, j0 = blockIdx.x * 64;
    if (tid < 64) sG[tid] = gg1[tid];
    else if (tid < 128) sG[tid] = gg2[tid - 64];
    else if (tid < 192) sG[tid] = gg3[tid - 128];
    const float* Ab = x + (size_t)i0 * CD;
    float d[2][4][4] = {};
    #pragma unroll 1
    for (int kc = 0; kc < 8; kc++) {
        int k0 = kc * 64;
        __syncthreads();
        // A: x fp32 -> fp16 half2 words, k-pair perm
        #pragma unroll
        for (int l = 0; l < 8; l++) {
            int idx = tid + l * 256;
            int rr = idx >> 4, c4 = (idx & 15) * 4;
            float4 v = *(const float4*)(Ab + (size_t)rr * CD + k0 + c4);
            int p = c4 >> 1;
            u32* dst = &sA[rr * 40];
            dst[pperm(p)]     = h2u(__floats2half2_rn(v.x, v.y));
            dst[pperm(p + 1)] = h2u(__floats2half2_rn(v.z, v.w));
        }
        // B: Wh fp16 raw copy, perm scatter
        #pragma unroll
        for (int l = 0; l < 2; l++) {
            int idx = tid + l * 256;
            int rr = idx >> 3, c8 = (idx & 7) * 8;
            uint4 raw = *(const uint4*)(g_Wh + (size_t)(j0 + rr) * CD + k0 + c8);
            u32 w[4] = {raw.x, raw.y, raw.z, raw.w};
            int p0 = (idx & 7) * 4;
            u32* dst = &sB[rr * 40];
            #pragma unroll
            for (int j = 0; j < 4; j++) dst[pperm(p0 + j)] = w[j];
        }
        __syncthreads();
        #pragma unroll
        for (int ks = 0; ks < 4; ks++) {
            int off = ks * 8 + 2 * t;
            uint2 alo[2], ahi[2];
            #pragma unroll
            for (int mt = 0; mt < 2; mt++) {
                int r0 = wm * 32 + mt * 16 + g;
                alo[mt] = *(const uint2*)&sA[r0 * 40 + off];
                ahi[mt] = *(const uint2*)&sA[(r0 + 8) * 40 + off];
            }
            #pragma unroll
            for (int nt = 0; nt < 4; nt++) {
                int n = wn * 32 + nt * 8 + g;
                uint2 bb = *(const uint2*)&sB[n * 40 + off];
                #pragma unroll
                for (int mt = 0; mt < 2; mt++)
                    mma16(d[mt][nt], alo[mt].x, ahi[mt].x, alo[mt].y, ahi[mt].y, bb.x, bb.y);
            }
        }
    }
    // ---- fused RMSNorm epilogue (accumulator layout identical to prior rounds) ----
    float ss0[2], ss1[2];
    #pragma unroll
    for (int mt = 0; mt < 2; mt++) {
        ss0[mt] = 0.f; ss1[mt] = 0.f;
        #pragma unroll
        for (int nt = 0; nt < 4; nt++) {
            ss0[mt] += d[mt][nt][0] * d[mt][nt][0] + d[mt][nt][1] * d[mt][nt][1];
            ss1[mt] += d[mt][nt][2] * d[mt][nt][2] + d[mt][nt][3] * d[mt][nt][3];
        }
        ss0[mt] += __shfl_xor_sync(0xffffffffu, ss0[mt], 1);
        ss0[mt] += __shfl_xor_sync(0xffffffffu, ss0[mt], 2);
        ss1[mt] += __shfl_xor_sync(0xffffffffu, ss1[mt], 1);
        ss1[mt] += __shfl_xor_sync(0xffffffffu, ss1[mt], 2);
    }
    __syncthreads();
    float* ssb = (float*)sB;   // reuse: [2][128]
    if (t == 0) {
        #pragma unroll
        for (int mt = 0; mt < 2; mt++) {
            ssb[wn * 128 + wm * 32 + mt * 16 + g]     = ss0[mt];
            ssb[wn * 128 + wm * 32 + mt * 16 + g + 8] = ss1[mt];
        }
    }
    __syncthreads();
    #pragma unroll
    for (int mt = 0; mt < 2; mt++) {
        int r0 = wm * 32 + mt * 16 + g, r1 = r0 + 8;
        float inv0 = rsqrtf((ssb[r0] + ssb[128 + r0]) * (1.0f / 64.0f) + 1.1920929e-07f);
        float inv1 = rsqrtf((ssb[r1] + ssb[128 + r1]) * (1.0f / 64.0f) + 1.1920929e-07f);
        float q0 = inv0 * 0.125f * 1.44269504f;
        float q1 = inv1 * 0.125f * 1.44269504f;
        size_t a0 = (size_t)(i0 + r0) * CD + j0;
        size_t a1 = (size_t)(i0 + r1) * CD + j0;
        #pragma unroll
        for (int nt = 0; nt < 4; nt++) {
            int c = wn * 32 + nt * 8 + 2 * t;
            float G1a = sG[c], G1b = sG[c + 1];
            float G2a = sG[64 + c], G2b = sG[64 + c + 1];
            float G3a = sG[128 + c], G3b = sG[128 + c + 1];
            float v0 = d[mt][nt][0], v1 = d[mt][nt][1];
            float v2 = d[mt][nt][2], v3 = d[mt][nt][3];
            *(__half2*)(g_qh + a0 + c) = __floats2half2_rn(v0 * q0 * G1a, v1 * q0 * G1b);
            *(__half2*)(g_kh + a0 + c) = __floats2half2_rn(v0 * inv0 * G2a, v1 * inv0 * G2b);
            *(__half2*)(g_vh + a0 + c) = __floats2half2_rn(v0 * inv0 * G3a, v1 * inv0 * G3b);
            *(__half2*)(g_qh + a1 + c) = __floats2half2_rn(v2 * q1 * G1a, v3 * q1 * G1b);
            *(__half2*)(g_kh + a1 + c) = __floats2half2_rn(v2 * inv1 * G2a, v3 * inv1 * G2b);
            *(__half2*)(g_vh + a1 + c) = __floats2half2_rn(v2 * inv1 * G3a, v3 * inv1 * G3b);
        }
    }
}

// ================================================================ E = 2^(q@k^T) -> fp16, fused sums
__global__ __launch_bounds__(256, 2) void k_att() {
    __shared__ __align__(16) u32 sq[128 * 40];
    __shared__ __align__(16) u32 sk[64 * 40];
    const int tid = threadIdx.x;
    const int lane = tid & 31, warp = tid >> 5;
    const int wm = warp >> 1, wn = warp & 1;
    const int g = lane >> 2, t = lane & 3;
    const int bh = blockIdx.z;
    const int i0 = blockIdx.y * 128;
    const size_t base = (size_t)(bh >> 3) * TD * CD + (bh & 7) * DD;
    const __half* qb = g_qh + base + (size_t)i0 * CD;
    #pragma unroll
    for (int l = 0; l < 4; l++) {
        int idx = tid + l * 256;
        int rr = idx >> 3, c8 = (idx & 7) * 8;
        uint4 raw = *(const uint4*)(qb + (size_t)rr * CD + c8);
        u32 w[4] = {raw.x, raw.y, raw.z, raw.w};
        int p0 = (idx & 7) * 4;
        u32* dst = &sq[rr * 40];
        #pragma unroll
        for (int j = 0; j < 4; j++) dst[pperm(p0 + j)] = w[j];
    }
    float rsum[2][2] = {};
    #pragma unroll 1
    for (int jj = 0; jj < 4; jj++) {
        int j0 = blockIdx.x * 256 + jj * 64;
        const __half* kb = g_kh + base + (size_t)j0 * CD;
        __syncthreads();
        #pragma unroll
        for (int l = 0; l < 2; l++) {
            int idx = tid + l * 256;
            int rr = idx >> 3, c8 = (idx & 7) * 8;
            uint4 raw = *(const uint4*)(kb + (size_t)rr * CD + c8);
            u32 w[4] = {raw.x, raw.y, raw.z, raw.w};
            int p0 = (idx & 7) * 4;
            u32* dst = &sk[rr * 40];
            #pragma unroll
            for (int j = 0; j < 4; j++) dst[pperm(p0 + j)] = w[j];
        }
        __syncthreads();
        float d[2][4][4] = {};
        #pragma unroll
        for (int ks = 0; ks < 4; ks++) {
            int off = ks * 8 + 2 * t;
            uint2 alo[2], ahi[2];
            #pragma unroll
            for (int mt = 0; mt < 2; mt++) {
                int r0 = wm * 32 + mt * 16 + g;
                alo[mt] = *(const uint2*)&sq[r0 * 40 + off];
                ahi[mt] = *(const uint2*)&sq[(r0 + 8) * 40 + off];
            }
            #pragma unroll
            for (int nt = 0; nt < 4; nt++) {
                int n = wn * 32 + nt * 8 + g;
                uint2 bb = *(const uint2*)&sk[n * 40 + off];
                #pragma unroll
                for (int mt = 0; mt < 2; mt++)
                    mma16(d[mt][nt], alo[mt].x, ahi[mt].x, alo[mt].y, ahi[mt].y, bb.x, bb.y);
            }
        }
        __half* ob = g_att + (size_t)bh * TD * TD + (size_t)i0 * TD + j0;
        float cs0[4] = {}, cs1[4] = {};
        #pragma unroll
        for (int mt = 0; mt < 2; mt++) {
            int r0 = wm * 32 + mt * 16 + g;
            #pragma unroll
            for (int nt = 0; nt < 4; nt++) {
                int col = wn * 32 + nt * 8 + 2 * t;
                __half2 h01 = __floats2half2_rn(ex2(d[mt][nt][0]), ex2(d[mt][nt][1]));
                __half2 h23 = __floats2half2_rn(ex2(d[mt][nt][2]), ex2(d[mt][nt][3]));
                *(__half2*)(ob + (size_t)r0 * TD + col)       = h01;
                *(__half2*)(ob + (size_t)(r0 + 8) * TD + col) = h23;
                float2 f01 = __half22float2(h01), f23 = __half22float2(h23);
                rsum[mt][0] += f01.x + f01.y; rsum[mt][1] += f23.x + f23.y;
                cs0[nt] += f01.x + f23.x;     cs1[nt] += f01.y + f23.y;
            }
        }
        #pragma unroll
        for (int nt = 0; nt < 4; nt++) {
            cs0[nt] += __shfl_xor_sync(0xffffffffu, cs0[nt], 4);
            cs0[nt] += __shfl_xor_sync(0xffffffffu, cs0[nt], 8);
            cs0[nt] += __shfl_xor_sync(0xffffffffu, cs0[nt], 16);
            cs1[nt] += __shfl_xor_sync(0xffffffffu, cs1[nt], 4);
            cs1[nt] += __shfl_xor_sync(0xffffffffu, cs1[nt], 8);
            cs1[nt] += __shfl_xor_sync(0xffffffffu, cs1[nt], 16);
        }
        __syncthreads();
        float* scolp = (float*)sk;   // [4][64]
        if (g == 0) {
            #pragma unroll
            for (int nt = 0; nt < 4; nt++) {
                scolp[wm * 64 + wn * 32 + nt * 8 + 2 * t]     = cs0[nt];
                scolp[wm * 64 + wn * 32 + nt * 8 + 2 * t + 1] = cs1[nt];
            }
        }
        __syncthreads();
        if (tid < 64) {
            atomicAdd(&g_scol[bh * TD + j0 + tid],
                      scolp[tid] + scolp[64 + tid] + scolp[128 + tid] + scolp[192 + tid]);
        }
    }
    #pragma unroll
    for (int mt = 0; mt < 2; mt++)
        #pragma unroll
        for (int h = 0; h < 2; h++) {
            rsum[mt][h] += __shfl_xor_sync(0xffffffffu, rsum[mt][h], 1);
            rsum[mt][h] += __shfl_xor_sync(0xffffffffu, rsum[mt][h], 2);
        }
    __syncthreads();
    float* srowp = (float*)sk;       // [2][128]
    if (t == 0) {
        #pragma unroll
        for (int mt = 0; mt < 2; mt++) {
            srowp[wn * 128 + wm * 32 + mt * 16 + g]     = rsum[mt][0];
            srowp[wn * 128 + wm * 32 + mt * 16 + g + 8] = rsum[mt][1];
        }
    }
    __syncthreads();
    if (tid < 128)
        atomicAdd(&g_srow[bh * TD + i0 + tid], srowp[tid] + srowp[128 + tid]);
}

// ------------------------------------------- reciprocals of sums
__global__ void k_recip() {
    int i = blockIdx.x * 256 + threadIdx.x;
    g_prow[i] = 1.0f / g_srow[i];
    g_pcol[i] = 1.0f / g_scol[i];
}

// ------------------------------------------- vt = v^T (raw fp16 copy); pvt = 4096*pc*v^T
__global__ void k_vt() {
    int idx = blockIdx.x * 256 + threadIdx.x;   // BH*TD*16
    int kk = idx & 2047;
    int rest = idx >> 11;
    int d4 = (rest & 15) * 4;
    int bh = rest >> 4;
    size_t vbase = (size_t)(bh >> 3) * TD * CD + (bh & 7) * DD;
    uint2 raw = *(const uint2*)(g_vh + vbase + (size_t)kk * CD + d4);
    __half hv[4]; memcpy(hv, &raw, 8);
    float pcs = g_pcol[bh * TD + kk] * 4096.0f;
    size_t tb = ((size_t)bh * DD + d4) * TD + kk;
    #pragma unroll
    for (int j = 0; j < 4; j++) {
        g_vt[tb + (size_t)j * TD]  = hv[j];
        g_pvt[tb + (size_t)j * TD] = __float2half(__half2float(hv[j]) * pcs);
    }
}

// ================================================================ y = pr⊙(E@v) + (1/4096)·E@pcv -> fp16
__global__ __launch_bounds__(256, 2) void k_y() {
    __shared__ __align__(16) u32 sEw[128 * 40];
    __shared__ __align__(16) u32 sVw[64 * 40];
    __shared__ __align__(16) u32 sPw[64 * 40];
    const int tid = threadIdx.x;
    const int lane = tid & 31, warp = tid >> 5;
    const int wm = warp >> 1, wn = warp & 1;
    const int g = lane >> 2, t = lane & 3;
    const int bh = blockIdx.y;
    const int i0 = blockIdx.x * 128;
    const __half* eb  = g_att + (size_t)bh * TD * TD + (size_t)i0 * TD;
    const __half* vtb = g_vt + (size_t)bh * DD * TD;
    const __half* ptb = g_pvt + (size_t)bh * DD * TD;
    float d1[2][4][4] = {}, d2[2][4][4] = {};
    #pragma unroll 1
    for (int kc = 0; kc < 32; kc++) {
        int k0 = kc * 64;
        __syncthreads();
        #pragma unroll
        for (int l = 0; l < 4; l++) {
            int idx = tid + l * 256;
            int rr = idx >> 3, c8 = (idx & 7) * 8;
            uint4 raw = *(const uint4*)(eb + (size_t)rr * TD + k0 + c8);
            u32 w[4] = {raw.x, raw.y, raw.z, raw.w};
            int p0 = (idx & 7) * 4;
            u32* dst = &sEw[rr * 40];
            #pragma unroll
            for (int j = 0; j < 4; j++) dst[pperm(p0 + j)] = w[j];
        }
        #pragma unroll
        for (int l = 0; l < 2; l++) {
            int idx = tid + l * 256;
            int rr = idx >> 3, c8 = (idx & 7) * 8;
            uint4 rv = *(const uint4*)(vtb + (size_t)rr * TD + k0 + c8);
            uint4 rp = *(const uint4*)(ptb + (size_t)rr * TD + k0 + c8);
            u32 wv[4] = {rv.x, rv.y, rv.z, rv.w};
            u32 wp[4] = {rp.x, rp.y, rp.z, rp.w};
            int p0 = (idx & 7) * 4;
            #pragma unroll
            for (int j = 0; j < 4; j++) {
                int pos = pperm(p0 + j);
                sVw[rr * 40 + pos] = wv[j];
                sPw[rr * 40 + pos] = wp[j];
            }
        }
        __syncthreads();
        #pragma unroll
        for (int ks = 0; ks < 4; ks++) {
            int off = ks * 8 + 2 * t;
            uint2 alo[2], ahi[2];
            #pragma unroll
            for (int mt = 0; mt < 2; mt++) {
                int r0 = wm * 32 + mt * 16 + g;
                alo[mt] = *(const uint2*)&sEw[r0 * 40 + off];
                ahi[mt] = *(const uint2*)&sEw[(r0 + 8) * 40 + off];
            }
            #pragma unroll
            for (int nt = 0; nt < 4; nt++) {
                int n = wn * 32 + nt * 8 + g;
                uint2 bv = *(const uint2*)&sVw[n * 40 + off];
                uint2 bp = *(const uint2*)&sPw[n * 40 + off];
                #pragma unroll
                for (int mt = 0; mt < 2; mt++) {
                    mma16(d1[mt][nt], alo[mt].x, ahi[mt].x, alo[mt].y, ahi[mt].y, bv.x, bv.y);
                    mma16(d2[mt][nt], alo[mt].x, ahi[mt].x, alo[mt].y, ahi[mt].y, bp.x, bp.y);
                }
            }
        }
    }
    const size_t base = (size_t)(bh >> 3) * TD * CD + (bh & 7) * DD;
    __half* yb = g_yh + base + (size_t)i0 * CD;
    const float isc = 1.0f / 4096.0f;
    #pragma unroll
    for (int mt = 0; mt < 2; mt++) {
        int r0 = wm * 32 + mt * 16 + g;
        float pr0 = g_prow[bh * TD + i0 + r0];
        float pr1 = g_prow[bh * TD + i0 + r0 + 8];
        #pragma unroll
        for (int nt = 0; nt < 4; nt++) {
            int col = wn * 32 + nt * 8 + 2 * t;
            *(__half2*)(yb + (size_t)r0 * CD + col) =
                __floats2half2_rn(pr0 * d1[mt][nt][0] + d2[mt][nt][0] * isc,
                                  pr0 * d1[mt][nt][1] + d2[mt][nt][1] * isc);
            *(__half2*)(yb + (size_t)(r0 + 8) * CD + col) =
                __floats2half2_rn(pr1 * d1[mt][nt][2] + d2[mt][nt][2] * isc,
                                  pr1 * d1[mt][nt][3] + d2[mt][nt][3] * isc);
        }
    }
}

// ================================================================ out = y @ W (fp16 MMA, zero cvts)
__global__ __launch_bounds__(256, 2) void k_outgemm(float* __restrict__ out) {
    __shared__ __align__(16) u32 sA[128 * 40];
    __shared__ __align__(16) u32 sB[64 * 40];
    const int tid = threadIdx.x;
    const int lane = tid & 31, warp = tid >> 5;
    const int wm = warp >> 1, wn = warp & 1;
    const int g = lane >> 2, t = lane & 3;
    const int i0 = blockIdx.y * 128, j0 = blockIdx.x * 64;
    const __half* Ab = g_yh + (size_t)i0 * CD;
    float d[2][4][4] = {};
    #pragma unroll 1
    for (int kc = 0; kc < 8; kc++) {
        int k0 = kc * 64;
        __syncthreads();
        #pragma unroll
        for (int l = 0; l < 4; l++) {
            int idx = tid + l * 256;
            int rr = idx >> 3, c8 = (idx & 7) * 8;
            uint4 raw = *(const uint4*)(Ab + (size_t)rr * CD + k0 + c8);
            u32 w[4] = {raw.x, raw.y, raw.z, raw.w};
            int p0 = (idx & 7) * 4;
            u32* dst = &sA[rr * 40];
            #pragma unroll
            for (int j = 0; j < 4; j++) dst[pperm(p0 + j)] = w[j];
        }
        #pragma unroll
        for (int l = 0; l < 2; l++) {
            int idx = tid + l * 256;
            int rr = idx >> 3, c8 = (idx & 7) * 8;
            uint4 raw = *(const uint4*)(g_Wt + (size_t)(j0 + rr) * CD + k0 + c8);
            u32 w[4] = {raw.x, raw.y, raw.z, raw.w};
            int p0 = (idx & 7) * 4;
            u32* dst = &sB[rr * 40];
            #pragma unroll
            for (int j = 0; j < 4; j++) dst[pperm(p0 + j)] = w[j];
        }
        __syncthreads();
        #pragma unroll
        for (int ks = 0; ks < 4; ks++) {
            int off = ks * 8 + 2 * t;
            uint2 alo[2], ahi[2];
            #pragma unroll
            for (int mt = 0; mt < 2; mt++) {
                int r0 = wm * 32 + mt * 16 + g;
                alo[mt] = *(const uint2*)&sA[r0 * 40 + off];
                ahi[mt] = *(const uint2*)&sA[(r0 + 8) * 40 + off];
            }
            #pragma unroll
            for (int nt = 0; nt < 4; nt++) {
                int n = wn * 32 + nt * 8 + g;
                uint2 bb = *(const uint2*)&sB[n * 40 + off];
                #pragma unroll
                for (int mt = 0; mt < 2; mt++)
                    mma16(d[mt][nt], alo[mt].x, ahi[mt].x, alo[mt].y, ahi[mt].y, bb.x, bb.y);
            }
        }
    }
    float* Cb = out + (size_t)i0 * CD + j0;
    #pragma unroll
    for (int mt = 0; mt < 2; mt++) {
        int r0 = wm * 32 + mt * 16 + g;
        #pragma unroll
        for (int nt = 0; nt < 4; nt++) {
            int col = wn * 32 + nt * 8 + 2 * t;
            *(float2*)(Cb + (size_t)r0 * CD + col)       = make_float2(d[mt][nt][0], d[mt][nt][1]);
            *(float2*)(Cb + (size_t)(r0 + 8) * CD + col) = make_float2(d[mt][nt][2], d[mt][nt][3]);
        }
    }
}

extern "C" void kernel_launch(void* const* d_in, const int* in_sizes, int n_in,
                              void* d_out, int out_size) {
    (void)in_sizes; (void)n_in; (void)out_size;
    const float* x  = (const float*)d_in[0];
    const float* dw = (const float*)d_in[1];
    const float* qw = (const float*)d_in[2];
    const float* g1 = (const float*)d_in[3];
    const float* g2 = (const float*)d_in[4];
    const float* g3 = (const float*)d_in[5];
    float* out = (float*)d_out;

    float *ps, *pc;
    cudaGetSymbolAddress((void**)&ps, g_srow);
    cudaGetSymbolAddress((void**)&pc, g_scol);
    cudaMemsetAsync(ps, 0, BH * TD * sizeof(float));
    cudaMemsetAsync(pc, 0, BH * TD * sizeof(float));

    k_addw<<<(CD * CD) / 256, 256>>>(dw, qw);
    k_wnorm<<<dim3(CD / 64, RWS / 128), 256>>>(x, g1, g2, g3);
    k_att<<<dim3(TD / 256, TD / 128, BH), 256>>>();
    k_recip<<<(BH * TD) / 256, 256>>>();
    k_vt<<<(BH * TD * 16) / 256, 256>>>();
    k_y<<<dim3(TD / 128, BH), 256>>>();
    k_outgemm<<<dim3(CD / 64, RWS / 128), 256>>>(out);
}

// round 15
// speedup vs baseline: 2.1175x; 1.0496x over previous
#include <cuda_runtime.h>
#include <cuda_fp16.h>

#define TD 2048
#define CD 512
#define DD 64
#define BH 32
#define RWS 8192

typedef unsigned int u32;

// ---------------- scratch ----------------
__device__ __half g_Wh[CD * CD];   // W fp16, [j][k] native (for wgemm B)
__device__ __half g_Wt[CD * CD];   // W^T fp16, [j][k] (for outgemm B)
__device__ __half g_qh[RWS * CD];  // fp16, scaled by inv*0.125*log2e
__device__ __half g_kh[RWS * CD];  // fp16
__device__ __half g_vh[RWS * CD];  // fp16
__device__ __half g_att[(size_t)BH * TD * TD];  // exp(att) fp16
__device__ __half g_vt[(size_t)BH * DD * TD];   // v transposed [bh][d][k], fp16
__device__ __half g_pvt[(size_t)BH * DD * TD];  // 4096*pc*v transposed, fp16
__device__ __half g_yh[RWS * CD];  // y fp16
__device__ float g_srow[BH * TD];
__device__ float g_scol[BH * TD];
__device__ float g_prow[BH * TD];
__device__ float g_pcol[BH * TD];

// ---------------- helpers ----------------
__device__ __forceinline__ float ex2(float x) {
    float y; asm("ex2.approx.f32 %0, %1;" : "=f"(y) : "f"(x)); return y;
}
__device__ __forceinline__ u32 h2u(__half2 h) {
    u32 r; memcpy(&r, &h, 4); return r;
}
__device__ __forceinline__ void mma16(float* d, u32 a0, u32 a1, u32 a2, u32 a3,
                                      u32 b0, u32 b1) {
    asm("mma.sync.aligned.m16n8k16.row.col.f32.f16.f16.f32 "
        "{%0,%1,%2,%3},{%4,%5,%6,%7},{%8,%9},{%0,%1,%2,%3};"
        : "+f"(d[0]), "+f"(d[1]), "+f"(d[2]), "+f"(d[3])
        : "r"(a0), "r"(a1), "r"(a2), "r"(a3), "r"(b0), "r"(b1));
}
// k-pair perm position within 8-word block: [0,4,1,5,2,6,3,7]
__device__ __forceinline__ int pperm(int p) {
    return (p & 24) + 2 * (p & 3) + ((p >> 2) & 1);
}

// ---------------------------------------------------------------- W -> fp16 native + transposed
__global__ void k_addw(const float* __restrict__ dw, const float* __restrict__ qw) {
    int i = blockIdx.x * 256 + threadIdx.x;
    float val = dw[i] + qw[i];
    __half h = __float2half(val);
    g_Wh[i] = h;                              // [r][c] native
    g_Wt[(i & 511) * CD + (i >> 9)] = h;      // transposed
}

// ================================================================ fused: w = x@W^T (fp16 MMA)
// + RMSNorm epilogue -> q (fp16 scaled), k (fp16), v (fp16). 128x64 tile, K-chunks of 64.
__global__ __launch_bounds__(256, 2) void k_wnorm(const float* __restrict__ x,
                                                  const float* __restrict__ gg1,
                                                  const float* __restrict__ gg2,
                                                  const float* __restrict__ gg3) {
    __shared__ __align__(16) u32 sA[128 * 40];
    __shared__ __align__(16) u32 sB[64 * 40];
    __shared__ float sG[192];
    const int tid = threadIdx.x;
    const int lane = tid & 31, warp = tid >> 5;
    const int wm = warp >> 1, wn = warp & 1;
    const int g = lane >> 2, t = lane & 3;
    const int i0 = blockIdx.y * 128, j0 = blockIdx.x * 64;
    if (tid < 64) sG[tid] = gg1[tid];
    else if (tid < 128) sG[tid] = gg2[tid - 64];
    else if (tid < 192) sG[tid] = gg3[tid - 128];
    const float* Ab = x + (size_t)i0 * CD;
    float d[2][4][4] = {};
    #pragma unroll 1
    for (int kc = 0; kc < 8; kc++) {
        int k0 = kc * 64;
        __syncthreads();
        // A: x fp32 -> fp16 half2 words, k-pair perm
        #pragma unroll
        for (int l = 0; l < 8; l++) {
            int idx = tid + l * 256;
            int rr = idx >> 4, c4 = (idx & 15) * 4;
            float4 v = *(const float4*)(Ab + (size_t)rr * CD + k0 + c4);
            int p = c4 >> 1;
            u32* dst = &sA[rr * 40];
            dst[pperm(p)]     = h2u(__floats2half2_rn(v.x, v.y));
            dst[pperm(p + 1)] = h2u(__floats2half2_rn(v.z, v.w));
        }
        // B: Wh fp16 raw copy, perm scatter
        #pragma unroll
        for (int l = 0; l < 2; l++) {
            int idx = tid + l * 256;
            int rr = idx >> 3, c8 = (idx & 7) * 8;
            uint4 raw = *(const uint4*)(g_Wh + (size_t)(j0 + rr) * CD + k0 + c8);
            u32 w[4] = {raw.x, raw.y, raw.z, raw.w};
            int p0 = (idx & 7) * 4;
            u32* dst = &sB[rr * 40];
            #pragma unroll
            for (int j = 0; j < 4; j++) dst[pperm(p0 + j)] = w[j];
        }
        __syncthreads();
        #pragma unroll
        for (int ks = 0; ks < 4; ks++) {
            int off = ks * 8 + 2 * t;
            uint2 alo[2], ahi[2];
            #pragma unroll
            for (int mt = 0; mt < 2; mt++) {
                int r0 = wm * 32 + mt * 16 + g;
                alo[mt] = *(const uint2*)&sA[r0 * 40 + off];
                ahi[mt] = *(const uint2*)&sA[(r0 + 8) * 40 + off];
            }
            #pragma unroll
            for (int nt = 0; nt < 4; nt++) {
                int n = wn * 32 + nt * 8 + g;
                uint2 bb = *(const uint2*)&sB[n * 40 + off];
                #pragma unroll
                for (int mt = 0; mt < 2; mt++)
                    mma16(d[mt][nt], alo[mt].x, ahi[mt].x, alo[mt].y, ahi[mt].y, bb.x, bb.y);
            }
        }
    }
    // ---- fused RMSNorm epilogue ----
    float ss0[2], ss1[2];
    #pragma unroll
    for (int mt = 0; mt < 2; mt++) {
        ss0[mt] = 0.f; ss1[mt] = 0.f;
        #pragma unroll
        for (int nt = 0; nt < 4; nt++) {
            ss0[mt] += d[mt][nt][0] * d[mt][nt][0] + d[mt][nt][1] * d[mt][nt][1];
            ss1[mt] += d[mt][nt][2] * d[mt][nt][2] + d[mt][nt][3] * d[mt][nt][3];
        }
        ss0[mt] += __shfl_xor_sync(0xffffffffu, ss0[mt], 1);
        ss0[mt] += __shfl_xor_sync(0xffffffffu, ss0[mt], 2);
        ss1[mt] += __shfl_xor_sync(0xffffffffu, ss1[mt], 1);
        ss1[mt] += __shfl_xor_sync(0xffffffffu, ss1[mt], 2);
    }
    __syncthreads();
    float* ssb = (float*)sB;   // reuse: [2][128]
    if (t == 0) {
        #pragma unroll
        for (int mt = 0; mt < 2; mt++) {
            ssb[wn * 128 + wm * 32 + mt * 16 + g]     = ss0[mt];
            ssb[wn * 128 + wm * 32 + mt * 16 + g + 8] = ss1[mt];
        }
    }
    __syncthreads();
    #pragma unroll
    for (int mt = 0; mt < 2; mt++) {
        int r0 = wm * 32 + mt * 16 + g, r1 = r0 + 8;
        float inv0 = rsqrtf((ssb[r0] + ssb[128 + r0]) * (1.0f / 64.0f) + 1.1920929e-07f);
        float inv1 = rsqrtf((ssb[r1] + ssb[128 + r1]) * (1.0f / 64.0f) + 1.1920929e-07f);
        float q0 = inv0 * 0.125f * 1.44269504f;
        float q1 = inv1 * 0.125f * 1.44269504f;
        size_t a0 = (size_t)(i0 + r0) * CD + j0;
        size_t a1 = (size_t)(i0 + r1) * CD + j0;
        #pragma unroll
        for (int nt = 0; nt < 4; nt++) {
            int c = wn * 32 + nt * 8 + 2 * t;
            float G1a = sG[c], G1b = sG[c + 1];
            float G2a = sG[64 + c], G2b = sG[64 + c + 1];
            float G3a = sG[128 + c], G3b = sG[128 + c + 1];
            float v0 = d[mt][nt][0], v1 = d[mt][nt][1];
            float v2 = d[mt][nt][2], v3 = d[mt][nt][3];
            *(__half2*)(g_qh + a0 + c) = __floats2half2_rn(v0 * q0 * G1a, v1 * q0 * G1b);
            *(__half2*)(g_kh + a0 + c) = __floats2half2_rn(v0 * inv0 * G2a, v1 * inv0 * G2b);
            *(__half2*)(g_vh + a0 + c) = __floats2half2_rn(v0 * inv0 * G3a, v1 * inv0 * G3b);
            *(__half2*)(g_qh + a1 + c) = __floats2half2_rn(v2 * q1 * G1a, v3 * q1 * G1b);
            *(__half2*)(g_kh + a1 + c) = __floats2half2_rn(v2 * inv1 * G2a, v3 * inv1 * G2b);
            *(__half2*)(g_vh + a1 + c) = __floats2half2_rn(v2 * inv1 * G3a, v3 * inv1 * G3b);
        }
    }
}

// ================================================================ E = 2^(q@k^T) -> fp16, fused sums
// Epilogue stages the exp'd tile in smem (stride 36 words, bank 4g+t conflict-free),
// then stores coalesced uint4 rows (full 128B lines).
__global__ __launch_bounds__(256, 2) void k_att() {
    __shared__ __align__(16) u32 sq[128 * 40];
    __shared__ __align__(16) u32 sk[64 * 40];
    __shared__ __align__(16) u32 sstg[128 * 36];
    const int tid = threadIdx.x;
    const int lane = tid & 31, warp = tid >> 5;
    const int wm = warp >> 1, wn = warp & 1;
    const int g = lane >> 2, t = lane & 3;
    const int bh = blockIdx.z;
    const int i0 = blockIdx.y * 128;
    const size_t base = (size_t)(bh >> 3) * TD * CD + (bh & 7) * DD;
    const __half* qb = g_qh + base + (size_t)i0 * CD;
    #pragma unroll
    for (int l = 0; l < 4; l++) {
        int idx = tid + l * 256;
        int rr = idx >> 3, c8 = (idx & 7) * 8;
        uint4 raw = *(const uint4*)(qb + (size_t)rr * CD + c8);
        u32 w[4] = {raw.x, raw.y, raw.z, raw.w};
        int p0 = (idx & 7) * 4;
        u32* dst = &sq[rr * 40];
        #pragma unroll
        for (int j = 0; j < 4; j++) dst[pperm(p0 + j)] = w[j];
    }
    float rsum[2][2] = {};
    #pragma unroll 1
    for (int jj = 0; jj < 4; jj++) {
        int j0 = blockIdx.x * 256 + jj * 64;
        const __half* kb = g_kh + base + (size_t)j0 * CD;
        __syncthreads();
        #pragma unroll
        for (int l = 0; l < 2; l++) {
            int idx = tid + l * 256;
            int rr = idx >> 3, c8 = (idx & 7) * 8;
            uint4 raw = *(const uint4*)(kb + (size_t)rr * CD + c8);
            u32 w[4] = {raw.x, raw.y, raw.z, raw.w};
            int p0 = (idx & 7) * 4;
            u32* dst = &sk[rr * 40];
            #pragma unroll
            for (int j = 0; j < 4; j++) dst[pperm(p0 + j)] = w[j];
        }
        __syncthreads();
        float d[2][4][4] = {};
        #pragma unroll
        for (int ks = 0; ks < 4; ks++) {
            int off = ks * 8 + 2 * t;
            uint2 alo[2], ahi[2];
            #pragma unroll
            for (int mt = 0; mt < 2; mt++) {
                int r0 = wm * 32 + mt * 16 + g;
                alo[mt] = *(const uint2*)&sq[r0 * 40 + off];
                ahi[mt] = *(const uint2*)&sq[(r0 + 8) * 40 + off];
            }
            #pragma unroll
            for (int nt = 0; nt < 4; nt++) {
                int n = wn * 32 + nt * 8 + g;
                uint2 bb = *(const uint2*)&sk[n * 40 + off];
                #pragma unroll
                for (int mt = 0; mt < 2; mt++)
                    mma16(d[mt][nt], alo[mt].x, ahi[mt].x, alo[mt].y, ahi[mt].y, bb.x, bb.y);
            }
        }
        // epilogue: exp2 -> fp16 into stage; sums of the SAME fp16-rounded values
        float cs0[4] = {}, cs1[4] = {};
        #pragma unroll
        for (int mt = 0; mt < 2; mt++) {
            int r0 = wm * 32 + mt * 16 + g;
            #pragma unroll
            for (int nt = 0; nt < 4; nt++) {
                int cw = wn * 16 + nt * 4 + t;   // half2-word column index
                __half2 h01 = __floats2half2_rn(ex2(d[mt][nt][0]), ex2(d[mt][nt][1]));
                __half2 h23 = __floats2half2_rn(ex2(d[mt][nt][2]), ex2(d[mt][nt][3]));
                sstg[r0 * 36 + cw]       = h2u(h01);
                sstg[(r0 + 8) * 36 + cw] = h2u(h23);
                float2 f01 = __half22float2(h01), f23 = __half22float2(h23);
                rsum[mt][0] += f01.x + f01.y; rsum[mt][1] += f23.x + f23.y;
                cs0[nt] += f01.x + f23.x;     cs1[nt] += f01.y + f23.y;
            }
        }
        #pragma unroll
        for (int nt = 0; nt < 4; nt++) {
            cs0[nt] += __shfl_xor_sync(0xffffffffu, cs0[nt], 4);
            cs0[nt] += __shfl_xor_sync(0xffffffffu, cs0[nt], 8);
            cs0[nt] += __shfl_xor_sync(0xffffffffu, cs0[nt], 16);
            cs1[nt] += __shfl_xor_sync(0xffffffffu, cs1[nt], 4);
            cs1[nt] += __shfl_xor_sync(0xffffffffu, cs1[nt], 8);
            cs1[nt] += __shfl_xor_sync(0xffffffffu, cs1[nt], 16);
        }
        __syncthreads();   // stage written + MMA reads of sk done
        // coalesced store pass: 4x uint4 per thread (full 128B lines)
        __half* ob = g_att + (size_t)bh * TD * TD + (size_t)i0 * TD + j0;
        #pragma unroll
        for (int l = 0; l < 4; l++) {
            int idx = tid + l * 256;
            int rr = idx >> 3, q = idx & 7;
            uint4 vv = *(const uint4*)&sstg[rr * 36 + q * 4];
            *(uint4*)(ob + (size_t)rr * TD + q * 8) = vv;
        }
        float* scolp = (float*)sk;   // [4][64]
        if (g == 0) {
            #pragma unroll
            for (int nt = 0; nt < 4; nt++) {
                scolp[wm * 64 + wn * 32 + nt * 8 + 2 * t]     = cs0[nt];
                scolp[wm * 64 + wn * 32 + nt * 8 + 2 * t + 1] = cs1[nt];
            }
        }
        __syncthreads();
        if (tid < 64) {
            atomicAdd(&g_scol[bh * TD + j0 + tid],
                      scolp[tid] + scolp[64 + tid] + scolp[128 + tid] + scolp[192 + tid]);
        }
    }
    #pragma unroll
    for (int mt = 0; mt < 2; mt++)
        #pragma unroll
        for (int h = 0; h < 2; h++) {
            rsum[mt][h] += __shfl_xor_sync(0xffffffffu, rsum[mt][h], 1);
            rsum[mt][h] += __shfl_xor_sync(0xffffffffu, rsum[mt][h], 2);
        }
    __syncthreads();
    float* srowp = (float*)sk;       // [2][128]
    if (t == 0) {
        #pragma unroll
        for (int mt = 0; mt < 2; mt++) {
            srowp[wn * 128 + wm * 32 + mt * 16 + g]     = rsum[mt][0];
            srowp[wn * 128 + wm * 32 + mt * 16 + g + 8] = rsum[mt][1];
        }
    }
    __syncthreads();
    if (tid < 128)
        atomicAdd(&g_srow[bh * TD + i0 + tid], srowp[tid] + srowp[128 + tid]);
}

// ------------------------------------------- reciprocals of sums
__global__ void k_recip() {
    int i = blockIdx.x * 256 + threadIdx.x;
    g_prow[i] = 1.0f / g_srow[i];
    g_pcol[i] = 1.0f / g_scol[i];
}

// ------------------------------------------- vt = v^T (raw fp16 copy); pvt = 4096*pc*v^T
__global__ void k_vt() {
    int idx = blockIdx.x * 256 + threadIdx.x;   // BH*TD*16
    int kk = idx & 2047;
    int rest = idx >> 11;
    int d4 = (rest & 15) * 4;
    int bh = rest >> 4;
    size_t vbase = (size_t)(bh >> 3) * TD * CD + (bh & 7) * DD;
    uint2 raw = *(const uint2*)(g_vh + vbase + (size_t)kk * CD + d4);
    __half hv[4]; memcpy(hv, &raw, 8);
    float pcs = g_pcol[bh * TD + kk] * 4096.0f;
    size_t tb = ((size_t)bh * DD + d4) * TD + kk;
    #pragma unroll
    for (int j = 0; j < 4; j++) {
        g_vt[tb + (size_t)j * TD]  = hv[j];
        g_pvt[tb + (size_t)j * TD] = __float2half(__half2float(hv[j]) * pcs);
    }
}

// ================================================================ y = pr⊙(E@v) + (1/4096)·E@pcv -> fp16
__global__ __launch_bounds__(256, 2) void k_y() {
    __shared__ __align__(16) u32 sEw[128 * 40];
    __shared__ __align__(16) u32 sVw[64 * 40];
    __shared__ __align__(16) u32 sPw[64 * 40];
    const int tid = threadIdx.x;
    const int lane = tid & 31, warp = tid >> 5;
    const int wm = warp >> 1, wn = warp & 1;
    const int g = lane >> 2, t = lane & 3;
    const int bh = blockIdx.y;
    const int i0 = blockIdx.x * 128;
    const __half* eb  = g_att + (size_t)bh * TD * TD + (size_t)i0 * TD;
    const __half* vtb = g_vt + (size_t)bh * DD * TD;
    const __half* ptb = g_pvt + (size_t)bh * DD * TD;
    float d1[2][4][4] = {}, d2[2][4][4] = {};
    #pragma unroll 1
    for (int kc = 0; kc < 32; kc++) {
        int k0 = kc * 64;
        __syncthreads();
        #pragma unroll
        for (int l = 0; l < 4; l++) {
            int idx = tid + l * 256;
            int rr = idx >> 3, c8 = (idx & 7) * 8;
            uint4 raw = *(const uint4*)(eb + (size_t)rr * TD + k0 + c8);
            u32 w[4] = {raw.x, raw.y, raw.z, raw.w};
            int p0 = (idx & 7) * 4;
            u32* dst = &sEw[rr * 40];
            #pragma unroll
            for (int j = 0; j < 4; j++) dst[pperm(p0 + j)] = w[j];
        }
        #pragma unroll
        for (int l = 0; l < 2; l++) {
            int idx = tid + l * 256;
            int rr = idx >> 3, c8 = (idx & 7) * 8;
            uint4 rv = *(const uint4*)(vtb + (size_t)rr * TD + k0 + c8);
            uint4 rp = *(const uint4*)(ptb + (size_t)rr * TD + k0 + c8);
            u32 wv[4] = {rv.x, rv.y, rv.z, rv.w};
            u32 wp[4] = {rp.x, rp.y, rp.z, rp.w};
            int p0 = (idx & 7) * 4;
            #pragma unroll
            for (int j = 0; j < 4; j++) {
                int pos = pperm(p0 + j);
                sVw[rr * 40 + pos] = wv[j];
                sPw[rr * 40 + pos] = wp[j];
            }
        }
        __syncthreads();
        #pragma unroll
        for (int ks = 0; ks < 4; ks++) {
            int off = ks * 8 + 2 * t;
            uint2 alo[2], ahi[2];
            #pragma unroll
            for (int mt = 0; mt < 2; mt++) {
                int r0 = wm * 32 + mt * 16 + g;
                alo[mt] = *(const uint2*)&sEw[r0 * 40 + off];
                ahi[mt] = *(const uint2*)&sEw[(r0 + 8) * 40 + off];
            }
            #pragma unroll
            for (int nt = 0; nt < 4; nt++) {
                int n = wn * 32 + nt * 8 + g;
                uint2 bv = *(const uint2*)&sVw[n * 40 + off];
                uint2 bp = *(const uint2*)&sPw[n * 40 + off];
                #pragma unroll
                for (int mt = 0; mt < 2; mt++) {
                    mma16(d1[mt][nt], alo[mt].x, ahi[mt].x, alo[mt].y, ahi[mt].y, bv.x, bv.y);
                    mma16(d2[mt][nt], alo[mt].x, ahi[mt].x, alo[mt].y, ahi[mt].y, bp.x, bp.y);
                }
            }
        }
    }
    const size_t base = (size_t)(bh >> 3) * TD * CD + (bh & 7) * DD;
    __half* yb = g_yh + base + (size_t)i0 * CD;
    const float isc = 1.0f / 4096.0f;
    #pragma unroll
    for (int mt = 0; mt < 2; mt++) {
        int r0 = wm * 32 + mt * 16 + g;
        float pr0 = g_prow[bh * TD + i0 + r0];
        float pr1 = g_prow[bh * TD + i0 + r0 + 8];
        #pragma unroll
        for (int nt = 0; nt < 4; nt++) {
            int col = wn * 32 + nt * 8 + 2 * t;
            *(__half2*)(yb + (size_t)r0 * CD + col) =
                __floats2half2_rn(pr0 * d1[mt][nt][0] + d2[mt][nt][0] * isc,
                                  pr0 * d1[mt][nt][1] + d2[mt][nt][1] * isc);
            *(__half2*)(yb + (size_t)(r0 + 8) * CD + col) =
                __floats2half2_rn(pr1 * d1[mt][nt][2] + d2[mt][nt][2] * isc,
                                  pr1 * d1[mt][nt][3] + d2[mt][nt][3] * isc);
        }
    }
}

// ================================================================ out = y @ W (fp16 MMA, zero cvts)
__global__ __launch_bounds__(256, 2) void k_outgemm(float* __restrict__ out) {
    __shared__ __align__(16) u32 sA[128 * 40];
    __shared__ __align__(16) u32 sB[64 * 40];
    const int tid = threadIdx.x;
    const int lane = tid & 31, warp = tid >> 5;
    const int wm = warp >> 1, wn = warp & 1;
    const int g = lane >> 2, t = lane & 3;
    const int i0 = blockIdx.y * 128, j0 = blockIdx.x * 64;
    const __half* Ab = g_yh + (size_t)i0 * CD;
    float d[2][4][4] = {};
    #pragma unroll 1
    for (int kc = 0; kc < 8; kc++) {
        int k0 = kc * 64;
        __syncthreads();
        #pragma unroll
        for (int l = 0; l < 4; l++) {
            int idx = tid + l * 256;
            int rr = idx >> 3, c8 = (idx & 7) * 8;
            uint4 raw = *(const uint4*)(Ab + (size_t)rr * CD + k0 + c8);
            u32 w[4] = {raw.x, raw.y, raw.z, raw.w};
            int p0 = (idx & 7) * 4;
            u32* dst = &sA[rr * 40];
            #pragma unroll
            for (int j = 0; j < 4; j++) dst[pperm(p0 + j)] = w[j];
        }
        #pragma unroll
        for (int l = 0; l < 2; l++) {
            int idx = tid + l * 256;
            int rr = idx >> 3, c8 = (idx & 7) * 8;
            uint4 raw = *(const uint4*)(g_Wt + (size_t)(j0 + rr) * CD + k0 + c8);
            u32 w[4] = {raw.x, raw.y, raw.z, raw.w};
            int p0 = (idx & 7) * 4;
            u32* dst = &sB[rr * 40];
            #pragma unroll
            for (int j = 0; j < 4; j++) dst[pperm(p0 + j)] = w[j];
        }
        __syncthreads();
        #pragma unroll
        for (int ks = 0; ks < 4; ks++) {
            int off = ks * 8 + 2 * t;
            uint2 alo[2], ahi[2];
            #pragma unroll
            for (int mt = 0; mt < 2; mt++) {
                int r0 = wm * 32 + mt * 16 + g;
                alo[mt] = *(const uint2*)&sA[r0 * 40 + off];
                ahi[mt] = *(const uint2*)&sA[(r0 + 8) * 40 + off];
            }
            #pragma unroll
            for (int nt = 0; nt < 4; nt++) {
                int n = wn * 32 + nt * 8 + g;
                uint2 bb = *(const uint2*)&sB[n * 40 + off];
                #pragma unroll
                for (int mt = 0; mt < 2; mt++)
                    mma16(d[mt][nt], alo[mt].x, ahi[mt].x, alo[mt].y, ahi[mt].y, bb.x, bb.y);
            }
        }
    }
    float* Cb = out + (size_t)i0 * CD + j0;
    #pragma unroll
    for (int mt = 0; mt < 2; mt++) {
        int r0 = wm * 32 + mt * 16 + g;
        #pragma unroll
        for (int nt = 0; nt < 4; nt++) {
            int col = wn * 32 + nt * 8 + 2 * t;
            *(float2*)(Cb + (size_t)r0 * CD + col)       = make_float2(d[mt][nt][0], d[mt][nt][1]);
            *(float2*)(Cb + (size_t)(r0 + 8) * CD + col) = make_float2(d[mt][nt][2], d[mt][nt][3]);
        }
    }
}

extern "C" void kernel_launch(void* const* d_in, const int* in_sizes, int n_in,
                              void* d_out, int out_size) {
    (void)in_sizes; (void)n_in; (void)out_size;
    const float* x  = (const float*)d_in[0];
    const float* dw = (const float*)d_in[1];
    const float* qw = (const float*)d_in[2];
    const float* g1 = (const float*)d_in[3];
    const float* g2 = (const float*)d_in[4];
    const float* g3 = (const float*)d_in[5];
    float* out = (float*)d_out;

    float *ps, *pc;
    cudaGetSymbolAddress((void**)&ps, g_srow);
    cudaGetSymbolAddress((void**)&pc, g_scol);
    cudaMemsetAsync(ps, 0, BH * TD * sizeof(float));
    cudaMemsetAsync(pc, 0, BH * TD * sizeof(float));

    k_addw<<<(CD * CD) / 256, 256>>>(dw, qw);
    k_wnorm<<<dim3(CD / 64, RWS / 128), 256>>>(x, g1, g2, g3);
    k_att<<<dim3(TD / 256, TD / 128, BH), 256>>>();
    k_recip<<<(BH * TD) / 256, 256>>>();
    k_vt<<<(BH * TD * 16) / 256, 256>>>();
    k_y<<<dim3(TD / 128, BH), 256>>>();
    k_outgemm<<<dim3(CD / 64, RWS / 128), 256>>>(out);
}

// round 16
// speedup vs baseline: 2.1266x; 1.0043x over previous
#include <cuda_runtime.h>
#include <cuda_fp16.h>

#define TD 2048
#define CD 512
#define DD 64
#define BH 32
#define RWS 8192

typedef unsigned int u32;

// ---------------- scratch ----------------
__device__ __half g_Wh[CD * CD];   // W fp16, [j][k] native (for wgemm B)
__device__ __half g_Wt[CD * CD];   // W^T fp16, [j][k] (for outgemm B)
__device__ __half g_qh[RWS * CD];  // fp16, scaled by inv*0.125*log2e
__device__ __half g_kh[RWS * CD];  // fp16
__device__ __half g_vh[RWS * CD];  // fp16
__device__ __half g_att[(size_t)BH * TD * TD];  // exp(att) fp16
__device__ __half g_vt[(size_t)BH * DD * TD];   // v transposed [bh][d][k], fp16
__device__ __half g_pvt[(size_t)BH * DD * TD];  // 4096*pc*v transposed, fp16
__device__ __half g_yh[RWS * CD];  // y fp16
__device__ float g_srow[BH * TD];
__device__ float g_scol[BH * TD];
__device__ float g_prow[BH * TD];
__device__ float g_pcol[BH * TD];

// ---------------- helpers ----------------
__device__ __forceinline__ float ex2(float x) {
    float y; asm("ex2.approx.f32 %0, %1;" : "=f"(y) : "f"(x)); return y;
}
__device__ __forceinline__ u32 h2u(__half2 h) {
    u32 r; memcpy(&r, &h, 4); return r;
}
__device__ __forceinline__ void mma16(float* d, u32 a0, u32 a1, u32 a2, u32 a3,
                                      u32 b0, u32 b1) {
    asm("mma.sync.aligned.m16n8k16.row.col.f32.f16.f16.f32 "
        "{%0,%1,%2,%3},{%4,%5,%6,%7},{%8,%9},{%0,%1,%2,%3};"
        : "+f"(d[0]), "+f"(d[1]), "+f"(d[2]), "+f"(d[3])
        : "r"(a0), "r"(a1), "r"(a2), "r"(a3), "r"(b0), "r"(b1));
}
// k-pair perm position within 8-word block: [0,4,1,5,2,6,3,7]
__device__ __forceinline__ int pperm(int p) {
    return (p & 24) + 2 * (p & 3) + ((p >> 2) & 1);
}

// ---------------------------------------------------------------- W -> fp16 native + transposed
__global__ void k_addw(const float* __restrict__ dw, const float* __restrict__ qw) {
    int i = blockIdx.x * 256 + threadIdx.x;
    float val = dw[i] + qw[i];
    __half h = __float2half(val);
    g_Wh[i] = h;                              // [r][c] native
    g_Wt[(i & 511) * CD + (i >> 9)] = h;      // transposed
}

// ================================================================ fused: w = x@W^T (fp16 MMA)
// + RMSNorm epilogue -> q (fp16 scaled), k (fp16), v (fp16). 128x64 tile, K-chunks of 64.
__global__ __launch_bounds__(256, 2) void k_wnorm(const float* __restrict__ x,
                                                  const float* __restrict__ gg1,
                                                  const float* __restrict__ gg2,
                                                  const float* __restrict__ gg3) {
    __shared__ __align__(16) u32 sA[128 * 40];
    __shared__ __align__(16) u32 sB[64 * 40];
    __shared__ float sG[192];
    const int tid = threadIdx.x;
    const int lane = tid & 31, warp = tid >> 5;
    const int wm = warp >> 1, wn = warp & 1;
    const int g = lane >> 2, t = lane & 3;
    const int i0 = blockIdx.y * 128, j0 = blockIdx.x * 64;
    if (tid < 64) sG[tid] = gg1[tid];
    else if (tid < 128) sG[tid] = gg2[tid - 64];
    else if (tid < 192) sG[tid] = gg3[tid - 128];
    const float* Ab = x + (size_t)i0 * CD;
    float d[2][4][4] = {};
    #pragma unroll 1
    for (int kc = 0; kc < 8; kc++) {
        int k0 = kc * 64;
        __syncthreads();
        // A: x fp32 -> fp16 half2 words, k-pair perm
        #pragma unroll
        for (int l = 0; l < 8; l++) {
            int idx = tid + l * 256;
            int rr = idx >> 4, c4 = (idx & 15) * 4;
            float4 v = *(const float4*)(Ab + (size_t)rr * CD + k0 + c4);
            int p = c4 >> 1;
            u32* dst = &sA[rr * 40];
            dst[pperm(p)]     = h2u(__floats2half2_rn(v.x, v.y));
            dst[pperm(p + 1)] = h2u(__floats2half2_rn(v.z, v.w));
        }
        // B: Wh fp16 raw copy, perm scatter
        #pragma unroll
        for (int l = 0; l < 2; l++) {
            int idx = tid + l * 256;
            int rr = idx >> 3, c8 = (idx & 7) * 8;
            uint4 raw = *(const uint4*)(g_Wh + (size_t)(j0 + rr) * CD + k0 + c8);
            u32 w[4] = {raw.x, raw.y, raw.z, raw.w};
            int p0 = (idx & 7) * 4;
            u32* dst = &sB[rr * 40];
            #pragma unroll
            for (int j = 0; j < 4; j++) dst[pperm(p0 + j)] = w[j];
        }
        __syncthreads();
        #pragma unroll
        for (int ks = 0; ks < 4; ks++) {
            int off = ks * 8 + 2 * t;
            uint2 alo[2], ahi[2];
            #pragma unroll
            for (int mt = 0; mt < 2; mt++) {
                int r0 = wm * 32 + mt * 16 + g;
                alo[mt] = *(const uint2*)&sA[r0 * 40 + off];
                ahi[mt] = *(const uint2*)&sA[(r0 + 8) * 40 + off];
            }
            #pragma unroll
            for (int nt = 0; nt < 4; nt++) {
                int n = wn * 32 + nt * 8 + g;
                uint2 bb = *(const uint2*)&sB[n * 40 + off];
                #pragma unroll
                for (int mt = 0; mt < 2; mt++)
                    mma16(d[mt][nt], alo[mt].x, ahi[mt].x, alo[mt].y, ahi[mt].y, bb.x, bb.y);
            }
        }
    }
    // ---- fused RMSNorm epilogue ----
    float ss0[2], ss1[2];
    #pragma unroll
    for (int mt = 0; mt < 2; mt++) {
        ss0[mt] = 0.f; ss1[mt] = 0.f;
        #pragma unroll
        for (int nt = 0; nt < 4; nt++) {
            ss0[mt] += d[mt][nt][0] * d[mt][nt][0] + d[mt][nt][1] * d[mt][nt][1];
            ss1[mt] += d[mt][nt][2] * d[mt][nt][2] + d[mt][nt][3] * d[mt][nt][3];
        }
        ss0[mt] += __shfl_xor_sync(0xffffffffu, ss0[mt], 1);
        ss0[mt] += __shfl_xor_sync(0xffffffffu, ss0[mt], 2);
        ss1[mt] += __shfl_xor_sync(0xffffffffu, ss1[mt], 1);
        ss1[mt] += __shfl_xor_sync(0xffffffffu, ss1[mt], 2);
    }
    __syncthreads();
    float* ssb = (float*)sB;   // reuse: [2][128]
    if (t == 0) {
        #pragma unroll
        for (int mt = 0; mt < 2; mt++) {
            ssb[wn * 128 + wm * 32 + mt * 16 + g]     = ss0[mt];
            ssb[wn * 128 + wm * 32 + mt * 16 + g + 8] = ss1[mt];
        }
    }
    __syncthreads();
    #pragma unroll
    for (int mt = 0; mt < 2; mt++) {
        int r0 = wm * 32 + mt * 16 + g, r1 = r0 + 8;
        float inv0 = rsqrtf((ssb[r0] + ssb[128 + r0]) * (1.0f / 64.0f) + 1.1920929e-07f);
        float inv1 = rsqrtf((ssb[r1] + ssb[128 + r1]) * (1.0f / 64.0f) + 1.1920929e-07f);
        float q0 = inv0 * 0.125f * 1.44269504f;
        float q1 = inv1 * 0.125f * 1.44269504f;
        size_t a0 = (size_t)(i0 + r0) * CD + j0;
        size_t a1 = (size_t)(i0 + r1) * CD + j0;
        #pragma unroll
        for (int nt = 0; nt < 4; nt++) {
            int c = wn * 32 + nt * 8 + 2 * t;
            float G1a = sG[c], G1b = sG[c + 1];
            float G2a = sG[64 + c], G2b = sG[64 + c + 1];
            float G3a = sG[128 + c], G3b = sG[128 + c + 1];
            float v0 = d[mt][nt][0], v1 = d[mt][nt][1];
            float v2 = d[mt][nt][2], v3 = d[mt][nt][3];
            *(__half2*)(g_qh + a0 + c) = __floats2half2_rn(v0 * q0 * G1a, v1 * q0 * G1b);
            *(__half2*)(g_kh + a0 + c) = __floats2half2_rn(v0 * inv0 * G2a, v1 * inv0 * G2b);
            *(__half2*)(g_vh + a0 + c) = __floats2half2_rn(v0 * inv0 * G3a, v1 * inv0 * G3b);
            *(__half2*)(g_qh + a1 + c) = __floats2half2_rn(v2 * q1 * G1a, v3 * q1 * G1b);
            *(__half2*)(g_kh + a1 + c) = __floats2half2_rn(v2 * inv1 * G2a, v3 * inv1 * G2b);
            *(__half2*)(g_vh + a1 + c) = __floats2half2_rn(v2 * inv1 * G3a, v3 * inv1 * G3b);
        }
    }
}

// ================================================================ E = 2^(q@k^T) -> fp16, fused sums
// Epilogue stages the exp'd tile in smem (stride 36 words, bank 4g+t conflict-free),
// then stores coalesced uint4 rows (full 128B lines).
__global__ __launch_bounds__(256, 2) void k_att() {
    __shared__ __align__(16) u32 sq[128 * 40];
    __shared__ __align__(16) u32 sk[64 * 40];
    __shared__ __align__(16) u32 sstg[128 * 36];
    const int tid = threadIdx.x;
    const int lane = tid & 31, warp = tid >> 5;
    const int wm = warp >> 1, wn = warp & 1;
    const int g = lane >> 2, t = lane & 3;
    const int bh = blockIdx.z;
    const int i0 = blockIdx.y * 128;
    const size_t base = (size_t)(bh >> 3) * TD * CD + (bh & 7) * DD;
    const __half* qb = g_qh + base + (size_t)i0 * CD;
    #pragma unroll
    for (int l = 0; l < 4; l++) {
        int idx = tid + l * 256;
        int rr = idx >> 3, c8 = (idx & 7) * 8;
        uint4 raw = *(const uint4*)(qb + (size_t)rr * CD + c8);
        u32 w[4] = {raw.x, raw.y, raw.z, raw.w};
        int p0 = (idx & 7) * 4;
        u32* dst = &sq[rr * 40];
        #pragma unroll
        for (int j = 0; j < 4; j++) dst[pperm(p0 + j)] = w[j];
    }
    float rsum[2][2] = {};
    #pragma unroll 1
    for (int jj = 0; jj < 4; jj++) {
        int j0 = blockIdx.x * 256 + jj * 64;
        const __half* kb = g_kh + base + (size_t)j0 * CD;
        __syncthreads();
        #pragma unroll
        for (int l = 0; l < 2; l++) {
            int idx = tid + l * 256;
            int rr = idx >> 3, c8 = (idx & 7) * 8;
            uint4 raw = *(const uint4*)(kb + (size_t)rr * CD + c8);
            u32 w[4] = {raw.x, raw.y, raw.z, raw.w};
            int p0 = (idx & 7) * 4;
            u32* dst = &sk[rr * 40];
            #pragma unroll
            for (int j = 0; j < 4; j++) dst[pperm(p0 + j)] = w[j];
        }
        __syncthreads();
        float d[2][4][4] = {};
        #pragma unroll
        for (int ks = 0; ks < 4; ks++) {
            int off = ks * 8 + 2 * t;
            uint2 alo[2], ahi[2];
            #pragma unroll
            for (int mt = 0; mt < 2; mt++) {
                int r0 = wm * 32 + mt * 16 + g;
                alo[mt] = *(const uint2*)&sq[r0 * 40 + off];
                ahi[mt] = *(const uint2*)&sq[(r0 + 8) * 40 + off];
            }
            #pragma unroll
            for (int nt = 0; nt < 4; nt++) {
                int n = wn * 32 + nt * 8 + g;
                uint2 bb = *(const uint2*)&sk[n * 40 + off];
                #pragma unroll
                for (int mt = 0; mt < 2; mt++)
                    mma16(d[mt][nt], alo[mt].x, ahi[mt].x, alo[mt].y, ahi[mt].y, bb.x, bb.y);
            }
        }
        // epilogue: exp2 -> fp16 into stage; sums of the SAME fp16-rounded values
        float cs0[4] = {}, cs1[4] = {};
        #pragma unroll
        for (int mt = 0; mt < 2; mt++) {
            int r0 = wm * 32 + mt * 16 + g;
            #pragma unroll
            for (int nt = 0; nt < 4; nt++) {
                int cw = wn * 16 + nt * 4 + t;   // half2-word column index
                __half2 h01 = __floats2half2_rn(ex2(d[mt][nt][0]), ex2(d[mt][nt][1]));
                __half2 h23 = __floats2half2_rn(ex2(d[mt][nt][2]), ex2(d[mt][nt][3]));
                sstg[r0 * 36 + cw]       = h2u(h01);
                sstg[(r0 + 8) * 36 + cw] = h2u(h23);
                float2 f01 = __half22float2(h01), f23 = __half22float2(h23);
                rsum[mt][0] += f01.x + f01.y; rsum[mt][1] += f23.x + f23.y;
                cs0[nt] += f01.x + f23.x;     cs1[nt] += f01.y + f23.y;
            }
        }
        #pragma unroll
        for (int nt = 0; nt < 4; nt++) {
            cs0[nt] += __shfl_xor_sync(0xffffffffu, cs0[nt], 4);
            cs0[nt] += __shfl_xor_sync(0xffffffffu, cs0[nt], 8);
            cs0[nt] += __shfl_xor_sync(0xffffffffu, cs0[nt], 16);
            cs1[nt] += __shfl_xor_sync(0xffffffffu, cs1[nt], 4);
            cs1[nt] += __shfl_xor_sync(0xffffffffu, cs1[nt], 8);
            cs1[nt] += __shfl_xor_sync(0xffffffffu, cs1[nt], 16);
        }
        __syncthreads();   // stage written + MMA reads of sk done
        // coalesced store pass: 4x uint4 per thread (full 128B lines)
        __half* ob = g_att + (size_t)bh * TD * TD + (size_t)i0 * TD + j0;
        #pragma unroll
        for (int l = 0; l < 4; l++) {
            int idx = tid + l * 256;
            int rr = idx >> 3, q = idx & 7;
            uint4 vv = *(const uint4*)&sstg[rr * 36 + q * 4];
            *(uint4*)(ob + (size_t)rr * TD + q * 8) = vv;
        }
        float* scolp = (float*)sk;   // [4][64]
        if (g == 0) {
            #pragma unroll
            for (int nt = 0; nt < 4; nt++) {
                scolp[wm * 64 + wn * 32 + nt * 8 + 2 * t]     = cs0[nt];
                scolp[wm * 64 + wn * 32 + nt * 8 + 2 * t + 1] = cs1[nt];
            }
        }
        __syncthreads();
        if (tid < 64) {
            atomicAdd(&g_scol[bh * TD + j0 + tid],
                      scolp[tid] + scolp[64 + tid] + scolp[128 + tid] + scolp[192 + tid]);
        }
    }
    #pragma unroll
    for (int mt = 0; mt < 2; mt++)
        #pragma unroll
        for (int h = 0; h < 2; h++) {
            rsum[mt][h] += __shfl_xor_sync(0xffffffffu, rsum[mt][h], 1);
            rsum[mt][h] += __shfl_xor_sync(0xffffffffu, rsum[mt][h], 2);
        }
    __syncthreads();
    float* srowp = (float*)sk;       // [2][128]
    if (t == 0) {
        #pragma unroll
        for (int mt = 0; mt < 2; mt++) {
            srowp[wn * 128 + wm * 32 + mt * 16 + g]     = rsum[mt][0];
            srowp[wn * 128 + wm * 32 + mt * 16 + g + 8] = rsum[mt][1];
        }
    }
    __syncthreads();
    if (tid < 128)
        atomicAdd(&g_srow[bh * TD + i0 + tid], srowp[tid] + srowp[128 + tid]);
}

// ------------------------------------------- reciprocals of sums
__global__ void k_recip() {
    int i = blockIdx.x * 256 + threadIdx.x;
    g_prow[i] = 1.0f / g_srow[i];
    g_pcol[i] = 1.0f / g_scol[i];
}

// ------------------------------------------- vt = v^T (raw fp16 copy); pvt = 4096*pc*v^T
__global__ void k_vt() {
    int idx = blockIdx.x * 256 + threadIdx.x;   // BH*TD*16
    int kk = idx & 2047;
    int rest = idx >> 11;
    int d4 = (rest & 15) * 4;
    int bh = rest >> 4;
    size_t vbase = (size_t)(bh >> 3) * TD * CD + (bh & 7) * DD;
    uint2 raw = *(const uint2*)(g_vh + vbase + (size_t)kk * CD + d4);
    __half hv[4]; memcpy(hv, &raw, 8);
    float pcs = g_pcol[bh * TD + kk] * 4096.0f;
    size_t tb = ((size_t)bh * DD + d4) * TD + kk;
    #pragma unroll
    for (int j = 0; j < 4; j++) {
        g_vt[tb + (size_t)j * TD]  = hv[j];
        g_pvt[tb + (size_t)j * TD] = __float2half(__half2float(hv[j]) * pcs);
    }
}

// ================================================================ y = pr⊙(E@v) + (1/4096)·E@pcv -> fp16
__global__ __launch_bounds__(256, 2) void k_y() {
    __shared__ __align__(16) u32 sEw[128 * 40];
    __shared__ __align__(16) u32 sVw[64 * 40];
    __shared__ __align__(16) u32 sPw[64 * 40];
    const int tid = threadIdx.x;
    const int lane = tid & 31, warp = tid >> 5;
    const int wm = warp >> 1, wn = warp & 1;
    const int g = lane >> 2, t = lane & 3;
    const int bh = blockIdx.y;
    const int i0 = blockIdx.x * 128;
    const __half* eb  = g_att + (size_t)bh * TD * TD + (size_t)i0 * TD;
    const __half* vtb = g_vt + (size_t)bh * DD * TD;
    const __half* ptb = g_pvt + (size_t)bh * DD * TD;
    float d1[2][4][4] = {}, d2[2][4][4] = {};
    #pragma unroll 1
    for (int kc = 0; kc < 32; kc++) {
        int k0 = kc * 64;
        __syncthreads();
        #pragma unroll
        for (int l = 0; l < 4; l++) {
            int idx = tid + l * 256;
            int rr = idx >> 3, c8 = (idx & 7) * 8;
            uint4 raw = *(const uint4*)(eb + (size_t)rr * TD + k0 + c8);
            u32 w[4] = {raw.x, raw.y, raw.z, raw.w};
            int p0 = (idx & 7) * 4;
            u32* dst = &sEw[rr * 40];
            #pragma unroll
            for (int j = 0; j < 4; j++) dst[pperm(p0 + j)] = w[j];
        }
        #pragma unroll
        for (int l = 0; l < 2; l++) {
            int idx = tid + l * 256;
            int rr = idx >> 3, c8 = (idx & 7) * 8;
            uint4 rv = *(const uint4*)(vtb + (size_t)rr * TD + k0 + c8);
            uint4 rp = *(const uint4*)(ptb + (size_t)rr * TD + k0 + c8);
            u32 wv[4] = {rv.x, rv.y, rv.z, rv.w};
            u32 wp[4] = {rp.x, rp.y, rp.z, rp.w};
            int p0 = (idx & 7) * 4;
            #pragma unroll
            for (int j = 0; j < 4; j++) {
                int pos = pperm(p0 + j);
                sVw[rr * 40 + pos] = wv[j];
                sPw[rr * 40 + pos] = wp[j];
            }
        }
        __syncthreads();
        #pragma unroll
        for (int ks = 0; ks < 4; ks++) {
            int off = ks * 8 + 2 * t;
            uint2 alo[2], ahi[2];
            #pragma unroll
            for (int mt = 0; mt < 2; mt++) {
                int r0 = wm * 32 + mt * 16 + g;
                alo[mt] = *(const uint2*)&sEw[r0 * 40 + off];
                ahi[mt] = *(const uint2*)&sEw[(r0 + 8) * 40 + off];
            }
            #pragma unroll
            for (int nt = 0; nt < 4; nt++) {
                int n = wn * 32 + nt * 8 + g;
                uint2 bv = *(const uint2*)&sVw[n * 40 + off];
                uint2 bp = *(const uint2*)&sPw[n * 40 + off];
                #pragma unroll
                for (int mt = 0; mt < 2; mt++) {
                    mma16(d1[mt][nt], alo[mt].x, ahi[mt].x, alo[mt].y, ahi[mt].y, bv.x, bv.y);
                    mma16(d2[mt][nt], alo[mt].x, ahi[mt].x, alo[mt].y, ahi[mt].y, bp.x, bp.y);
                }
            }
        }
    }
    const size_t base = (size_t)(bh >> 3) * TD * CD + (bh & 7) * DD;
    __half* yb = g_yh + base + (size_t)i0 * CD;
    const float isc = 1.0f / 4096.0f;
    #pragma unroll
    for (int mt = 0; mt < 2; mt++) {
        int r0 = wm * 32 + mt * 16 + g;
        float pr0 = g_prow[bh * TD + i0 + r0];
        float pr1 = g_prow[bh * TD + i0 + r0 + 8];
        #pragma unroll
        for (int nt = 0; nt < 4; nt++) {
            int col = wn * 32 + nt * 8 + 2 * t;
            *(__half2*)(yb + (size_t)r0 * CD + col) =
                __floats2half2_rn(pr0 * d1[mt][nt][0] + d2[mt][nt][0] * isc,
                                  pr0 * d1[mt][nt][1] + d2[mt][nt][1] * isc);
            *(__half2*)(yb + (size_t)(r0 + 8) * CD + col) =
                __floats2half2_rn(pr1 * d1[mt][nt][2] + d2[mt][nt][2] * isc,
                                  pr1 * d1[mt][nt][3] + d2[mt][nt][3] * isc);
        }
    }
}

// ================================================================ out = y @ W (fp16 MMA, zero cvts)
__global__ __launch_bounds__(256, 2) void k_outgemm(float* __restrict__ out) {
    __shared__ __align__(16) u32 sA[128 * 40];
    __shared__ __align__(16) u32 sB[64 * 40];
    const int tid = threadIdx.x;
    const int lane = tid & 31, warp = tid >> 5;
    const int wm = warp >> 1, wn = warp & 1;
    const int g = lane >> 2, t = lane & 3;
    const int i0 = blockIdx.y * 128, j0 = blockIdx.x * 64;
    const __half* Ab = g_yh + (size_t)i0 * CD;
    float d[2][4][4] = {};
    #pragma unroll 1
    for (int kc = 0; kc < 8; kc++) {
        int k0 = kc * 64;
        __syncthreads();
        #pragma unroll
        for (int l = 0; l < 4; l++) {
            int idx = tid + l * 256;
            int rr = idx >> 3, c8 = (idx & 7) * 8;
            uint4 raw = *(const uint4*)(Ab + (size_t)rr * CD + k0 + c8);
            u32 w[4] = {raw.x, raw.y, raw.z, raw.w};
            int p0 = (idx & 7) * 4;
            u32* dst = &sA[rr * 40];
            #pragma unroll
            for (int j = 0; j < 4; j++) dst[pperm(p0 + j)] = w[j];
        }
        #pragma unroll
        for (int l = 0; l < 2; l++) {
            int idx = tid + l * 256;
            int rr = idx >> 3, c8 = (idx & 7) * 8;
            uint4 raw = *(const uint4*)(g_Wt + (size_t)(j0 + rr) * CD + k0 + c8);
            u32 w[4] = {raw.x, raw.y, raw.z, raw.w};
            int p0 = (idx & 7) * 4;
            u32* dst = &sB[rr * 40];
            #pragma unroll
            for (int j = 0; j < 4; j++) dst[pperm(p0 + j)] = w[j];
        }
        __syncthreads();
        #pragma unroll
        for (int ks = 0; ks < 4; ks++) {
            int off = ks * 8 + 2 * t;
            uint2 alo[2], ahi[2];
            #pragma unroll
            for (int mt = 0; mt < 2; mt++) {
                int r0 = wm * 32 + mt * 16 + g;
                alo[mt] = *(const uint2*)&sA[r0 * 40 + off];
                ahi[mt] = *(const uint2*)&sA[(r0 + 8) * 40 + off];
            }
            #pragma unroll
            for (int nt = 0; nt < 4; nt++) {
                int n = wn * 32 + nt * 8 + g;
                uint2 bb = *(const uint2*)&sB[n * 40 + off];
                #pragma unroll
                for (int mt = 0; mt < 2; mt++)
                    mma16(d[mt][nt], alo[mt].x, ahi[mt].x, alo[mt].y, ahi[mt].y, bb.x, bb.y);
            }
        }
    }
    float* Cb = out + (size_t)i0 * CD + j0;
    #pragma unroll
    for (int mt = 0; mt < 2; mt++) {
        int r0 = wm * 32 + mt * 16 + g;
        #pragma unroll
        for (int nt = 0; nt < 4; nt++) {
            int col = wn * 32 + nt * 8 + 2 * t;
            *(float2*)(Cb + (size_t)r0 * CD + col)       = make_float2(d[mt][nt][0], d[mt][nt][1]);
            *(float2*)(Cb + (size_t)(r0 + 8) * CD + col) = make_float2(d[mt][nt][2], d[mt][nt][3]);
        }
    }
}

extern "C" void kernel_launch(void* const* d_in, const int* in_sizes, int n_in,
                              void* d_out, int out_size) {
    (void)in_sizes; (void)n_in; (void)out_size;
    const float* x  = (const float*)d_in[0];
    const float* dw = (const float*)d_in[1];
    const float* qw = (const float*)d_in[2];
    const float* g1 = (const float*)d_in[3];
    const float* g2 = (const float*)d_in[4];
    const float* g3 = (const float*)d_in[5];
    float* out = (float*)d_out;

    float *ps, *pc;
    cudaGetSymbolAddress((void**)&ps, g_srow);
    cudaGetSymbolAddress((void**)&pc, g_scol);
    cudaMemsetAsync(ps, 0, BH * TD * sizeof(float));
    cudaMemsetAsync(pc, 0, BH * TD * sizeof(float));

    k_addw<<<(CD * CD) / 256, 256>>>(dw, qw);
    k_wnorm<<<dim3(CD / 64, RWS / 128), 256>>>(x, g1, g2, g3);
    k_att<<<dim3(TD / 256, TD / 128, BH), 256>>>();
    k_recip<<<(BH * TD) / 256, 256>>>();
    k_vt<<<(BH * TD * 16) / 256, 256>>>();
    k_y<<<dim3(TD / 128, BH), 256>>>();
    k_outgemm<<<dim3(CD / 64, RWS / 128), 256>>>(out);
}